// round 3
// baseline (speedup 1.0000x reference)
#include <cuda_runtime.h>

#define NL 4
#define BATCH 16384
#define THREADS 512
#define EPB 32                    // batch elements per block
#define ROWS 64                   // job rows per block (elem x branch)
#define NBLK (BATCH / EPB)        // 512 blocks
#define XS_S 68                   // xs stride (pad, 16B aligned)
#define XC_S 132                  // xc/sz stride (pad, 16B aligned)
#define XPW_S 129                 // B/C weight rows (scalar conflict-free)
#define EPSV 1e-5f

typedef unsigned long long ull;

// ---------------- f32x2 helpers ----------------
__device__ __forceinline__ ull pk2(float lo, float hi) {
    ull r; asm("mov.b64 %0,{%1,%2};" : "=l"(r) : "f"(lo), "f"(hi)); return r;
}
__device__ __forceinline__ void upk2(ull v, float& lo, float& hi) {
    asm("mov.b64 {%0,%1},%2;" : "=f"(lo), "=f"(hi) : "l"(v));
}
__device__ __forceinline__ ull ffma2(ull a, ull b, ull c) {
    ull d; asm("fma.rn.f32x2 %0,%1,%2,%3;" : "=l"(d) : "l"(a), "l"(b), "l"(c)); return d;
}
__device__ __forceinline__ float warp_sum(float v) {
    v += __shfl_xor_sync(0xffffffffu, v, 16);
    v += __shfl_xor_sync(0xffffffffu, v, 8);
    v += __shfl_xor_sync(0xffffffffu, v, 4);
    v += __shfl_xor_sync(0xffffffffu, v, 2);
    v += __shfl_xor_sync(0xffffffffu, v, 1);
    return v;
}
__device__ __forceinline__ float half_sum(float v) {
    v += __shfl_xor_sync(0xffffffffu, v, 8);
    v += __shfl_xor_sync(0xffffffffu, v, 4);
    v += __shfl_xor_sync(0xffffffffu, v, 2);
    v += __shfl_xor_sync(0xffffffffu, v, 1);
    return v;
}
__device__ __forceinline__ float siluf(float v) {
    return __fdividef(v, 1.0f + __expf(-v));
}
__device__ __forceinline__ float softplusf(float v) {
    return fmaxf(v, 0.0f) + __logf(1.0f + __expf(-fabsf(v)));
}
__device__ __forceinline__ float fcomp(const float4& v, int k) {
    return k == 0 ? v.x : k == 1 ? v.y : k == 2 ? v.z : v.w;
}

// ------------- folded input-projection weights -------------
__device__ float g_Wnr[12 * 64];
__device__ float g_bnr[64];
__device__ float g_Wr[4 * 64];
__device__ float g_br[64];

__global__ void __launch_bounds__(256)
prep_kernel(const float* __restrict__ w_nr, const float* __restrict__ b_nr,
            const float* __restrict__ w_r,  const float* __restrict__ b_r,
            const float* __restrict__ w_in_nr, const float* __restrict__ b_in_nr,
            const float* __restrict__ w_in_r,  const float* __restrict__ b_in_r) {
    int W = blockIdx.x * 8 + (threadIdx.x >> 5);   // 0..1151
    int lane = threadIdx.x & 31;
    const float* vec; const float* mat; int o;
    if (W < 768)        { vec = w_nr + (W >> 6) * 1000;        mat = w_in_nr; o = W & 63; }
    else if (W < 832)   { vec = b_nr;                          mat = w_in_nr; o = W - 768; }
    else if (W < 1088)  { vec = w_r + ((W - 832) >> 6) * 1000; mat = w_in_r;  o = (W - 832) & 63; }
    else                { vec = b_r;                           mat = w_in_r;  o = W - 1088; }
    float a = 0.0f;
    for (int c = lane; c < 1000; c += 32)
        a = fmaf(vec[c], mat[c * 64 + o], a);
    a = warp_sum(a);
    if (lane == 0) {
        if (W < 768)       g_Wnr[W] = a;
        else if (W < 832)  g_bnr[W - 768] = a + b_in_nr[W - 768];
        else if (W < 1088) g_Wr[W - 832] = a;
        else               g_br[W - 1088] = a + b_in_r[W - 1088];
    }
}

// ---------------- shared memory (214,480 B; 1 block/SM) ----------------
struct __align__(16) Smem {
    float ipw[64 * 256];      // 65536 B
    float opw[128 * 64];      // 32768 B
    float xpwT[36 * XPW_S];   // B/C rows (4..35 used), stride 129
    float xpj[4 * 132];       // dt-proj rows 0..3, stride 132 (float4-safe)
    float dtw[4 * 128];
    float cw3[128];
    float cb[128];
    float dtb[128];
    float dskip[128];
    float lng[64];
    float lnb[64];
    float Wnr[12 * 64];
    float Wr[4 * 64];
    float bnr[64];
    float br[64];
    float xs[ROWS * XS_S];    // residual stream [row][64]
    float xc[ROWS * XC_S];    // xc, then y (in place); head reuses as hw1[128][33]
    float sz[ROWS * XC_S];    // silu(z), then o (stride 68 view)
    float proj4[ROWS * 4];
    float BC[ROWS];
};

__global__ void __launch_bounds__(THREADS, 1)
mamba_main(const float* __restrict__ xin,
           const float* __restrict__ ipw_g, const float* __restrict__ cw_g,
           const float* __restrict__ cb_g,  const float* __restrict__ xpw_g,
           const float* __restrict__ dtw_g, const float* __restrict__ dtb_g,
           const float* __restrict__ dskip_g, const float* __restrict__ opw_g,
           const float* __restrict__ lng_g, const float* __restrict__ lnb_g,
           const float* __restrict__ hw1, const float* __restrict__ hb1,
           const float* __restrict__ hw2, const float* __restrict__ hb2,
           float* __restrict__ out) {
    extern __shared__ __align__(16) char smem_raw[];
    Smem& s = *reinterpret_cast<Smem*>(smem_raw);

    const int t = threadIdx.x;
    const int w = t >> 5;
    const int lane = t & 31;

    // ---- stage folded input-proj weights ----
    for (int i = t; i < 768; i += THREADS) s.Wnr[i] = g_Wnr[i];
    if (t < 256)      s.Wr[t] = g_Wr[t];
    else if (t < 320) s.bnr[t - 256] = g_bnr[t - 256];
    else if (t < 384) s.br[t - 320] = g_br[t - 320];
    __syncthreads();

    // ---- x0 = feat @ W_eff + b_eff : warp w -> rows 4w..4w+3 ----
    {
        const int e0 = blockIdx.x * EPB + 2 * w;
        float fe[2][16];
#pragma unroll
        for (int e = 0; e < 2; e++) {
            const float4* xp = (const float4*)(xin + (size_t)(e0 + e) * 16);
#pragma unroll
            for (int q = 0; q < 4; q++) {
                float4 v = xp[q];
                fe[e][4 * q + 0] = v.x; fe[e][4 * q + 1] = v.y;
                fe[e][4 * q + 2] = v.z; fe[e][4 * q + 3] = v.w;
            }
        }
        float2 bn = *(const float2*)&s.bnr[2 * lane];
        float2 bb = *(const float2*)&s.br[2 * lane];
        ull a0 = pk2(bn.x, bn.y), a2 = a0;
        ull a1 = pk2(bb.x, bb.y), a3 = a1;
#pragma unroll
        for (int f = 0; f < 12; f++) {
            ull wp = *(const ull*)&s.Wnr[f * 64 + 2 * lane];
            a0 = ffma2(wp, pk2(fe[0][f], fe[0][f]), a0);
            a2 = ffma2(wp, pk2(fe[1][f], fe[1][f]), a2);
        }
#pragma unroll
        for (int f = 0; f < 4; f++) {
            ull wp = *(const ull*)&s.Wr[f * 64 + 2 * lane];
            a1 = ffma2(wp, pk2(fe[0][12 + f], fe[0][12 + f]), a1);
            a3 = ffma2(wp, pk2(fe[1][12 + f], fe[1][12 + f]), a3);
        }
        float v0, v1;
        upk2(a0, v0, v1); *(float2*)&s.xs[(4 * w + 0) * XS_S + 2 * lane] = make_float2(v0, v1);
        upk2(a1, v0, v1); *(float2*)&s.xs[(4 * w + 1) * XS_S + 2 * lane] = make_float2(v0, v1);
        upk2(a2, v0, v1); *(float2*)&s.xs[(4 * w + 2) * XS_S + 2 * lane] = make_float2(v0, v1);
        upk2(a3, v0, v1); *(float2*)&s.xs[(4 * w + 3) * XS_S + 2 * lane] = make_float2(v0, v1);
    }

    // ================= layer loop =================
#pragma unroll 1
    for (int l = 0; l < NL; l++) {
        __syncthreads();   // previous stages done before weight overwrite
        {
            const float4* srcI = (const float4*)(ipw_g + l * 16384);
            float4* dI = (float4*)s.ipw;
            for (int i = t; i < 4096; i += THREADS) dI[i] = srcI[i];
            const float4* srcO = (const float4*)(opw_g + l * 8192);
            float4* dO = (float4*)s.opw;
            for (int i = t; i < 2048; i += THREADS) dO[i] = srcO[i];
            for (int i = t; i < 4608; i += THREADS) {   // xpw[l][d][j]
                int d = i / 36, j = i - d * 36;
                float v = xpw_g[l * 4608 + i];
                if (j < 4) s.xpj[j * 132 + d] = v;
                else       s.xpwT[j * XPW_S + d] = v;
            }
            s.dtw[t] = dtw_g[l * 512 + t];
            if (t < 128)      s.cw3[t] = cw_g[(l * 128 + t) * 4 + 3];
            else if (t < 256) s.cb[t - 128] = cb_g[l * 128 + (t - 128)];
            else if (t < 384) s.dtb[t - 256] = dtb_g[l * 128 + (t - 256)];
            else              s.dskip[t - 384] = dskip_g[l * 128 + (t - 384)];
            if (t < 64)       s.lng[t] = lng_g[l * 64 + t];
            else if (t < 128) s.lnb[t - 64] = lnb_g[l * 64 + (t - 64)];
        }
        __syncthreads();

        // ---- xz GEMM: XZ[64][256] = xs[64][64] @ ipw ; warp tile 32x32 ----
        {
            const int tr = (w & 1) * 32;
            const int tc = (w >> 1) * 32;
            const int ly = lane >> 2, lx = lane & 3;
            ull acc[4][4];
#pragma unroll
            for (int i = 0; i < 4; i++)
#pragma unroll
                for (int q = 0; q < 4; q++) acc[i][q] = 0ULL;
            const float* x0p = &s.xs[(tr + ly) * XS_S];
            const float* wbase = &s.ipw[tc + lx * 8];
#pragma unroll 2
            for (int k = 0; k < 64; k += 4) {
                float4 xv[4];
#pragma unroll
                for (int i = 0; i < 4; i++)
                    xv[i] = *(const float4*)(x0p + i * 8 * XS_S + k);
#pragma unroll
                for (int kk = 0; kk < 4; kk++) {
                    const float* wr = wbase + (k + kk) * 256;
                    ulonglong2 w01 = *(const ulonglong2*)wr;        // col pairs 0,1
                    ulonglong2 w23 = *(const ulonglong2*)(wr + 4);  // col pairs 2,3
#pragma unroll
                    for (int i = 0; i < 4; i++) {
                        float xf = fcomp(xv[i], kk);
                        ull xp = pk2(xf, xf);
                        acc[i][0] = ffma2(w01.x, xp, acc[i][0]);
                        acc[i][1] = ffma2(w01.y, xp, acc[i][1]);
                        acc[i][2] = ffma2(w23.x, xp, acc[i][2]);
                        acc[i][3] = ffma2(w23.y, xp, acc[i][3]);
                    }
                }
            }
            if (tc < 128) {   // xc: conv tap + silu
#pragma unroll
                for (int i = 0; i < 4; i++) {
                    int row = tr + ly + 8 * i;
#pragma unroll
                    for (int q = 0; q < 4; q++) {
                        int c = tc + lx * 8 + 2 * q;
                        float a0, a1; upk2(acc[i][q], a0, a1);
                        float2 cwv = *(const float2*)&s.cw3[c];
                        float2 cbv = *(const float2*)&s.cb[c];
                        *(float2*)&s.xc[row * XC_S + c] =
                            make_float2(siluf(fmaf(a0, cwv.x, cbv.x)),
                                        siluf(fmaf(a1, cwv.y, cbv.y)));
                    }
                }
            } else {          // z: silu
#pragma unroll
                for (int i = 0; i < 4; i++) {
                    int row = tr + ly + 8 * i;
#pragma unroll
                    for (int q = 0; q < 4; q++) {
                        int c = tc - 128 + lx * 8 + 2 * q;
                        float a0, a1; upk2(acc[i][q], a0, a1);
                        *(float2*)&s.sz[row * XC_S + c] =
                            make_float2(siluf(a0), siluf(a1));
                    }
                }
            }
        }
        __syncthreads();

        // ---- B/C + dt projection: warp owns rows 4w..4w+3 ----
        {
            const int rb = 4 * w;
            float xcv[4][4];
#pragma unroll
            for (int j = 0; j < 4; j++) {
                float4 v = *(const float4*)&s.xc[(rb + j) * XC_S + 4 * lane];
                xcv[j][0] = v.x; xcv[j][1] = v.y; xcv[j][2] = v.z; xcv[j][3] = v.w;
            }
            float pr[4][4];
#pragma unroll
            for (int r = 0; r < 4; r++) {
                float4 wv = *(const float4*)&s.xpj[r * 132 + 4 * lane];
#pragma unroll
                for (int j = 0; j < 4; j++) {
                    float p = xcv[j][0] * wv.x + xcv[j][1] * wv.y
                            + xcv[j][2] * wv.z + xcv[j][3] * wv.w;
                    pr[r][j] = warp_sum(p);
                }
            }
            if (lane == 0) {
#pragma unroll
                for (int j = 0; j < 4; j++)
                    *(float4*)&s.proj4[(rb + j) * 4] =
                        make_float4(pr[0][j], pr[1][j], pr[2][j], pr[3][j]);
            }
            // BC: lane computes xpwT row 4+lane over 128 dims, 4 jobs
            const float* wrow = &s.xpwT[(4 + lane) * XPW_S];
            ull a01 = 0ULL, a23 = 0ULL;
#pragma unroll 4
            for (int d0 = 0; d0 < 128; d0 += 4) {
                float4 c0 = *(const float4*)&s.xc[(rb + 0) * XC_S + d0];
                float4 c1 = *(const float4*)&s.xc[(rb + 1) * XC_S + d0];
                float4 c2 = *(const float4*)&s.xc[(rb + 2) * XC_S + d0];
                float4 c3 = *(const float4*)&s.xc[(rb + 3) * XC_S + d0];
                float w0 = wrow[d0], w1 = wrow[d0 + 1], w2 = wrow[d0 + 2], w3 = wrow[d0 + 3];
                a01 = ffma2(pk2(c0.x, c1.x), pk2(w0, w0), a01);
                a23 = ffma2(pk2(c2.x, c3.x), pk2(w0, w0), a23);
                a01 = ffma2(pk2(c0.y, c1.y), pk2(w1, w1), a01);
                a23 = ffma2(pk2(c2.y, c3.y), pk2(w1, w1), a23);
                a01 = ffma2(pk2(c0.z, c1.z), pk2(w2, w2), a01);
                a23 = ffma2(pk2(c2.z, c3.z), pk2(w2, w2), a23);
                a01 = ffma2(pk2(c0.w, c1.w), pk2(w3, w3), a01);
                a23 = ffma2(pk2(c2.w, c3.w), pk2(w3, w3), a23);
            }
            float bc[4];
            upk2(a01, bc[0], bc[1]); upk2(a23, bc[2], bc[3]);
#pragma unroll
            for (int j = 0; j < 4; j++) {
                float other = __shfl_xor_sync(0xffffffffu, bc[j], 16);
                bc[j] = half_sum(bc[j] * other);
            }
            if (lane == 0) {
                s.BC[rb + 0] = bc[0]; s.BC[rb + 1] = bc[1];
                s.BC[rb + 2] = bc[2]; s.BC[rb + 3] = bc[3];
            }
        }
        __syncthreads();

        // ---- y = xc*(softplus(proj4@dtw+dtb)*BC + dskip)*sz, in-place into xc ----
        {
            const int r = t >> 3;
            const int c0 = (t & 7) * 16;
            float4 pj = *(const float4*)&s.proj4[r * 4];
            float bcr = s.BC[r];
#pragma unroll
            for (int cc = 0; cc < 16; cc += 4) {
                int c = c0 + cc;
                float4 xcv = *(const float4*)&s.xc[r * XC_S + c];
                float4 szv = *(const float4*)&s.sz[r * XC_S + c];
                float4 d0v = *(const float4*)&s.dtw[c];
                float4 d1v = *(const float4*)&s.dtw[128 + c];
                float4 d2v = *(const float4*)&s.dtw[256 + c];
                float4 d3v = *(const float4*)&s.dtw[384 + c];
                float4 dtbv = *(const float4*)&s.dtb[c];
                float4 dskv = *(const float4*)&s.dskip[c];
                float4 yv;
                float dt;
                dt = softplusf(pj.x*d0v.x + pj.y*d1v.x + pj.z*d2v.x + pj.w*d3v.x + dtbv.x);
                yv.x = xcv.x * fmaf(dt, bcr, dskv.x) * szv.x;
                dt = softplusf(pj.x*d0v.y + pj.y*d1v.y + pj.z*d2v.y + pj.w*d3v.y + dtbv.y);
                yv.y = xcv.y * fmaf(dt, bcr, dskv.y) * szv.y;
                dt = softplusf(pj.x*d0v.z + pj.y*d1v.z + pj.z*d2v.z + pj.w*d3v.z + dtbv.z);
                yv.z = xcv.z * fmaf(dt, bcr, dskv.z) * szv.z;
                dt = softplusf(pj.x*d0v.w + pj.y*d1v.w + pj.z*d2v.w + pj.w*d3v.w + dtbv.w);
                yv.w = xcv.w * fmaf(dt, bcr, dskv.w) * szv.w;
                *(float4*)&s.xc[r * XC_S + c] = yv;
            }
        }
        __syncthreads();

        // ---- out-proj GEMM: O[64][64] = Y[64][128] @ opw ; warp tile 16x16 ----
        {
            const int tr = (w >> 2) * 16, tc = (w & 3) * 16;
            const int ly = lane >> 2, lx = lane & 3;
            ull acc[2][2] = {{0ULL, 0ULL}, {0ULL, 0ULL}};
            const float* y0p = &s.xc[(tr + ly) * XC_S];
            const float* y1p = &s.xc[(tr + ly + 8) * XC_S];
            const float* wbase = &s.opw[tc + lx * 4];
#pragma unroll 2
            for (int k = 0; k < 128; k += 4) {
                float4 ya = *(const float4*)(y0p + k);
                float4 yb = *(const float4*)(y1p + k);
#pragma unroll
                for (int kk = 0; kk < 4; kk++) {
                    ulonglong2 wv = *(const ulonglong2*)(wbase + (k + kk) * 64);
                    float fa = fcomp(ya, kk), fb = fcomp(yb, kk);
                    ull pa = pk2(fa, fa), pb = pk2(fb, fb);
                    acc[0][0] = ffma2(wv.x, pa, acc[0][0]);
                    acc[0][1] = ffma2(wv.y, pa, acc[0][1]);
                    acc[1][0] = ffma2(wv.x, pb, acc[1][0]);
                    acc[1][1] = ffma2(wv.y, pb, acc[1][1]);
                }
            }
#pragma unroll
            for (int i = 0; i < 2; i++) {
                int row = tr + ly + 8 * i;
#pragma unroll
                for (int q = 0; q < 2; q++) {
                    float a0, a1; upk2(acc[i][q], a0, a1);
                    *(float2*)&s.sz[row * 68 + tc + lx * 4 + 2 * q] = make_float2(a0, a1);
                }
            }
        }
        __syncthreads();

        // ---- layernorm(64) + residual into xs; 8 threads per row ----
        {
            const int r = t >> 3, part = t & 7;
            const int c = part * 8;
            float4 v0 = *(const float4*)&s.sz[r * 68 + c];
            float4 v1 = *(const float4*)&s.sz[r * 68 + c + 4];
            float sm = (v0.x + v0.y) + (v0.z + v0.w) + (v1.x + v1.y) + (v1.z + v1.w);
            float sq = v0.x*v0.x + v0.y*v0.y + v0.z*v0.z + v0.w*v0.w
                     + v1.x*v1.x + v1.y*v1.y + v1.z*v1.z + v1.w*v1.w;
            sm += __shfl_xor_sync(0xffffffffu, sm, 4);
            sq += __shfl_xor_sync(0xffffffffu, sq, 4);
            sm += __shfl_xor_sync(0xffffffffu, sm, 2);
            sq += __shfl_xor_sync(0xffffffffu, sq, 2);
            sm += __shfl_xor_sync(0xffffffffu, sm, 1);
            sq += __shfl_xor_sync(0xffffffffu, sq, 1);
            float m = sm * (1.0f / 64.0f);
            float m2 = sq * (1.0f / 64.0f);
            float rs = rsqrtf(m2 - m * m + EPSV);
            float4 g0 = *(const float4*)&s.lng[c];
            float4 g1 = *(const float4*)&s.lng[c + 4];
            float4 b0 = *(const float4*)&s.lnb[c];
            float4 b1 = *(const float4*)&s.lnb[c + 4];
            float4 x0v = *(const float4*)&s.xs[r * XS_S + c];
            float4 x1v = *(const float4*)&s.xs[r * XS_S + c + 4];
            x0v.x += (v0.x - m) * rs * g0.x + b0.x;
            x0v.y += (v0.y - m) * rs * g0.y + b0.y;
            x0v.z += (v0.z - m) * rs * g0.z + b0.z;
            x0v.w += (v0.w - m) * rs * g0.w + b0.w;
            x1v.x += (v1.x - m) * rs * g1.x + b1.x;
            x1v.y += (v1.y - m) * rs * g1.y + b1.y;
            x1v.z += (v1.z - m) * rs * g1.z + b1.z;
            x1v.w += (v1.w - m) * rs * g1.w + b1.w;
            *(float4*)&s.xs[r * XS_S + c] = x0v;
            *(float4*)&s.xs[r * XS_S + c + 4] = x1v;
        }
    }

    // ================= head =================
    {
        float* hs = s.xc;   // reuse as hw1[128][33]
        for (int i = t; i < 4096; i += THREADS) {
            int k = i >> 5, c = i & 31;
            hs[k * 33 + c] = hw1[i];
        }
        if (t < 32) { s.cw3[t] = hb1[t]; s.cb[t] = hw2[t]; }
        __syncthreads();

        float b2v = hb2[0];
#pragma unroll
        for (int j = 0; j < 2; j++) {
            int ra = 4 * w + 2 * j;              // nr row; r row = ra+1
            float h = s.cw3[lane];
            const float* xa = &s.xs[ra * XS_S];
            const float* xb = &s.xs[(ra + 1) * XS_S];
#pragma unroll 8
            for (int k = 0; k < 64; k++) h = fmaf(xa[k], hs[k * 33 + lane], h);
#pragma unroll 8
            for (int k = 0; k < 64; k++) h = fmaf(xb[k], hs[(64 + k) * 33 + lane], h);
            h = fmaxf(h, 0.0f);
            float v = warp_sum(h * s.cb[lane]);
            if (lane == 0) out[blockIdx.x * EPB + 2 * w + j] = v + b2v;
        }
    }
}

extern "C" void kernel_launch(void* const* d_in, const int* in_sizes, int n_in,
                              void* d_out, int out_size) {
    const float* x        = (const float*)d_in[0];
    const float* w_nr     = (const float*)d_in[1];
    const float* b_nr     = (const float*)d_in[2];
    const float* w_r      = (const float*)d_in[3];
    const float* b_r      = (const float*)d_in[4];
    const float* w_in_nr  = (const float*)d_in[5];
    const float* b_in_nr  = (const float*)d_in[6];
    const float* w_in_r   = (const float*)d_in[7];
    const float* b_in_r   = (const float*)d_in[8];
    const float* ipw      = (const float*)d_in[9];
    const float* cw       = (const float*)d_in[10];
    const float* cb       = (const float*)d_in[11];
    const float* xpw      = (const float*)d_in[12];
    const float* dtw      = (const float*)d_in[13];
    const float* dtb      = (const float*)d_in[14];
    /* alog d_in[15] dead at L=1 (scan h0=0) */
    const float* dskip    = (const float*)d_in[16];
    const float* opw      = (const float*)d_in[17];
    const float* lng      = (const float*)d_in[18];
    const float* lnb      = (const float*)d_in[19];
    const float* hw1      = (const float*)d_in[20];
    const float* hb1      = (const float*)d_in[21];
    const float* hw2      = (const float*)d_in[22];
    const float* hb2      = (const float*)d_in[23];

    size_t smem = sizeof(Smem);
    cudaFuncSetAttribute((const void*)mamba_main,
                         cudaFuncAttributeMaxDynamicSharedMemorySize, (int)smem);

    prep_kernel<<<144, 256>>>(w_nr, b_nr, w_r, b_r, w_in_nr, b_in_nr, w_in_r, b_in_r);
    mamba_main<<<NBLK, THREADS, smem>>>(x, ipw, cw, cb, xpw, dtw, dtb, dskip, opw,
                                        lng, lnb, hw1, hb1, hw2, hb2, (float*)d_out);
}

// round 4
// speedup vs baseline: 1.2561x; 1.2561x over previous
#include <cuda_runtime.h>

#define NL 4
#define BATCH 16384
#define THREADS 512
#define EPB 32                    // batch elements per block
#define NBLK (BATCH / EPB)        // 512 blocks
#define XS_S 68                   // residual stride (floats)
#define XC_S 132                  // xc/sz stride (floats)
#define XPW_S 129                 // B/C weight row stride (scalar conflict-free)
#define EPSV 1e-5f

typedef unsigned long long ull;

__device__ __forceinline__ ull pk2(float lo, float hi) {
    ull r; asm("mov.b64 %0,{%1,%2};" : "=l"(r) : "f"(lo), "f"(hi)); return r;
}
__device__ __forceinline__ void upk2(ull v, float& lo, float& hi) {
    asm("mov.b64 {%0,%1},%2;" : "=f"(lo), "=f"(hi) : "l"(v));
}
__device__ __forceinline__ ull ffma2(ull a, ull b, ull c) {
    ull d; asm("fma.rn.f32x2 %0,%1,%2,%3;" : "=l"(d) : "l"(a), "l"(b), "l"(c)); return d;
}
__device__ __forceinline__ float warp_sum(float v) {
    v += __shfl_xor_sync(0xffffffffu, v, 16);
    v += __shfl_xor_sync(0xffffffffu, v, 8);
    v += __shfl_xor_sync(0xffffffffu, v, 4);
    v += __shfl_xor_sync(0xffffffffu, v, 2);
    v += __shfl_xor_sync(0xffffffffu, v, 1);
    return v;
}
__device__ __forceinline__ float half_sum(float v) {
    v += __shfl_xor_sync(0xffffffffu, v, 8);
    v += __shfl_xor_sync(0xffffffffu, v, 4);
    v += __shfl_xor_sync(0xffffffffu, v, 2);
    v += __shfl_xor_sync(0xffffffffu, v, 1);
    return v;
}
__device__ __forceinline__ float siluf(float v) {
    return __fdividef(v, 1.0f + __expf(-v));
}
__device__ __forceinline__ float softplusf(float v) {
    return fmaxf(v, 0.0f) + __logf(1.0f + __expf(-fabsf(v)));
}
__device__ __forceinline__ float fcomp(const float4& v, int k) {
    return k == 0 ? v.x : k == 1 ? v.y : k == 2 ? v.z : v.w;
}

// ------------- folded input-projection weights -------------
__device__ float g_Wnr[12 * 64];
__device__ float g_bnr[64];
__device__ float g_Wr[4 * 64];
__device__ float g_br[64];

__global__ void __launch_bounds__(256)
prep_kernel(const float* __restrict__ w_nr, const float* __restrict__ b_nr,
            const float* __restrict__ w_r,  const float* __restrict__ b_r,
            const float* __restrict__ w_in_nr, const float* __restrict__ b_in_nr,
            const float* __restrict__ w_in_r,  const float* __restrict__ b_in_r) {
    int W = blockIdx.x * 8 + (threadIdx.x >> 5);   // 0..1151
    int lane = threadIdx.x & 31;
    const float* vec; const float* mat; int o;
    if (W < 768)        { vec = w_nr + (W >> 6) * 1000;        mat = w_in_nr; o = W & 63; }
    else if (W < 832)   { vec = b_nr;                          mat = w_in_nr; o = W - 768; }
    else if (W < 1088)  { vec = w_r + ((W - 832) >> 6) * 1000; mat = w_in_r;  o = (W - 832) & 63; }
    else                { vec = b_r;                           mat = w_in_r;  o = W - 1088; }
    float a = 0.0f;
    for (int c = lane; c < 1000; c += 32)
        a = fmaf(vec[c], mat[c * 64 + o], a);
    a = warp_sum(a);
    if (lane == 0) {
        if (W < 768)       g_Wnr[W] = a;
        else if (W < 832)  g_bnr[W - 768] = a + b_in_nr[W - 768];
        else if (W < 1088) g_Wr[W - 832] = a;
        else               g_br[W - 1088] = a + b_in_r[W - 1088];
    }
}

// ---------------- shared memory (~208 KB; 1 block/SM) ----------------
struct __align__(16) Smem {
    float ipw[64 * 256];
    float opw[128 * 64];
    float xpwT[36 * XPW_S];   // B/C rows 4..35, stride 129
    float xpj[4 * 132];       // dt-proj rows 0..3
    float dtw[4 * 128];
    float cw3[128];
    float cb[128];
    float dtb[128];
    float dskip[128];
    float lng[64];
    float lnb[64];
    float Wnr[12 * 64];
    float Wr[4 * 64];
    float bnr[64];
    float br[64];
    float xs[64 * XS_S];      // residual stream [row][64]
    float xc[64 * XC_S];      // xc, then y (in place); head reuses as hw1[128][33]
    float sz[64 * XC_S];      // silu(z)
};

__global__ void __launch_bounds__(THREADS, 1)
mamba_main(const float* __restrict__ xin,
           const float* __restrict__ ipw_g, const float* __restrict__ cw_g,
           const float* __restrict__ cb_g,  const float* __restrict__ xpw_g,
           const float* __restrict__ dtw_g, const float* __restrict__ dtb_g,
           const float* __restrict__ dskip_g, const float* __restrict__ opw_g,
           const float* __restrict__ lng_g, const float* __restrict__ lnb_g,
           const float* __restrict__ hw1, const float* __restrict__ hb1,
           const float* __restrict__ hw2, const float* __restrict__ hb2,
           float* __restrict__ out) {
    extern __shared__ __align__(16) char smem_raw[];
    Smem& s = *reinterpret_cast<Smem*>(smem_raw);

    const int t = threadIdx.x;
    const int w = t >> 5;
    const int lane = t & 31;

    // ---- stage folded input-proj weights ----
    for (int i = t; i < 768; i += THREADS) s.Wnr[i] = g_Wnr[i];
    if (t < 256)      s.Wr[t] = g_Wr[t];
    else if (t < 320) s.bnr[t - 256] = g_bnr[t - 256];
    else if (t < 384) s.br[t - 320] = g_br[t - 320];
    __syncthreads();

    // ---- x0 = feat @ W_eff + b_eff : warp w -> rows 4w..4w+3 ----
    // row r <-> (elem = blk*EPB + (r>>1), branch = r&1)
    {
        const int e0 = blockIdx.x * EPB + 2 * w;
        float fe[2][16];
#pragma unroll
        for (int e = 0; e < 2; e++) {
            const float4* xp = (const float4*)(xin + (size_t)(e0 + e) * 16);
#pragma unroll
            for (int q = 0; q < 4; q++) {
                float4 v = xp[q];
                fe[e][4 * q + 0] = v.x; fe[e][4 * q + 1] = v.y;
                fe[e][4 * q + 2] = v.z; fe[e][4 * q + 3] = v.w;
            }
        }
        float2 bn = *(const float2*)&s.bnr[2 * lane];
        float2 bb = *(const float2*)&s.br[2 * lane];
        ull a0 = pk2(bn.x, bn.y), a2 = a0;
        ull a1 = pk2(bb.x, bb.y), a3 = a1;
#pragma unroll
        for (int f = 0; f < 12; f++) {
            ull wp = *(const ull*)&s.Wnr[f * 64 + 2 * lane];
            a0 = ffma2(wp, pk2(fe[0][f], fe[0][f]), a0);
            a2 = ffma2(wp, pk2(fe[1][f], fe[1][f]), a2);
        }
#pragma unroll
        for (int f = 0; f < 4; f++) {
            ull wp = *(const ull*)&s.Wr[f * 64 + 2 * lane];
            a1 = ffma2(wp, pk2(fe[0][12 + f], fe[0][12 + f]), a1);
            a3 = ffma2(wp, pk2(fe[1][12 + f], fe[1][12 + f]), a3);
        }
        float v0, v1;
        upk2(a0, v0, v1); *(float2*)&s.xs[(4 * w + 0) * XS_S + 2 * lane] = make_float2(v0, v1);
        upk2(a1, v0, v1); *(float2*)&s.xs[(4 * w + 1) * XS_S + 2 * lane] = make_float2(v0, v1);
        upk2(a2, v0, v1); *(float2*)&s.xs[(4 * w + 2) * XS_S + 2 * lane] = make_float2(v0, v1);
        upk2(a3, v0, v1); *(float2*)&s.xs[(4 * w + 3) * XS_S + 2 * lane] = make_float2(v0, v1);
    }

    // ================= layer loop =================
#pragma unroll 1
    for (int l = 0; l < NL; l++) {
        __syncthreads();   // prior reads done; xs writes visible
        {
            const float4* srcI = (const float4*)(ipw_g + l * 16384);
            float4* dI = (float4*)s.ipw;
            for (int i = t; i < 4096; i += THREADS) dI[i] = srcI[i];
            const float4* srcO = (const float4*)(opw_g + l * 8192);
            float4* dO = (float4*)s.opw;
            for (int i = t; i < 2048; i += THREADS) dO[i] = srcO[i];
            for (int i = t; i < 4608; i += THREADS) {   // xpw[l][d][j]
                int d = i / 36, j = i - d * 36;
                float v = xpw_g[l * 4608 + i];
                if (j < 4) s.xpj[j * 132 + d] = v;
                else       s.xpwT[j * XPW_S + d] = v;
            }
            s.dtw[t] = dtw_g[l * 512 + t];
            if (t < 128)      s.cw3[t] = cw_g[(l * 128 + t) * 4 + 3];
            else if (t < 256) s.cb[t - 128] = cb_g[l * 128 + (t - 128)];
            else if (t < 384) s.dtb[t - 256] = dtb_g[l * 128 + (t - 256)];
            else              s.dskip[t - 384] = dskip_g[l * 128 + (t - 384)];
            if (t < 64)       s.lng[t] = lng_g[l * 64 + t];
            else if (t < 128) s.lnb[t - 64] = lnb_g[l * 64 + (t - 64)];
        }
        __syncthreads();

        // ---- xz gemv, warp-pair split: pair g=w>>1 owns rows 8g..8g+7;
        //      even warp -> xc cols 0..127, odd warp -> z cols 128..255.
        //      lane owns 4 cols (4*lane..4*lane+3) for 8 jobs.
        {
            const int rb = 8 * (w >> 1);
            const int h = w & 1;
            const float* wbase = &s.ipw[h * 128 + 4 * lane];
            ull acc[8][2];
#pragma unroll
            for (int j = 0; j < 8; j++) { acc[j][0] = 0ULL; acc[j][1] = 0ULL; }
#pragma unroll 2
            for (int k0 = 0; k0 < 64; k0 += 4) {
                float4 xv[8];
#pragma unroll
                for (int j = 0; j < 8; j++)
                    xv[j] = *(const float4*)&s.xs[(rb + j) * XS_S + k0];
#pragma unroll
                for (int kk = 0; kk < 4; kk++) {
                    ulonglong2 wv = *(const ulonglong2*)(wbase + (k0 + kk) * 256);
#pragma unroll
                    for (int j = 0; j < 8; j++) {
                        float xf = fcomp(xv[j], kk);
                        ull xp = pk2(xf, xf);
                        acc[j][0] = ffma2(wv.x, xp, acc[j][0]);
                        acc[j][1] = ffma2(wv.y, xp, acc[j][1]);
                    }
                }
            }
            if (h == 0) {     // xc: conv tap + silu
                float4 cwv = *(const float4*)&s.cw3[4 * lane];
                float4 cbv = *(const float4*)&s.cb[4 * lane];
#pragma unroll
                for (int j = 0; j < 8; j++) {
                    float a0, a1, a2, a3;
                    upk2(acc[j][0], a0, a1); upk2(acc[j][1], a2, a3);
                    float4 o;
                    o.x = siluf(fmaf(a0, cwv.x, cbv.x));
                    o.y = siluf(fmaf(a1, cwv.y, cbv.y));
                    o.z = siluf(fmaf(a2, cwv.z, cbv.z));
                    o.w = siluf(fmaf(a3, cwv.w, cbv.w));
                    *(float4*)&s.xc[(rb + j) * XC_S + 4 * lane] = o;
                }
            } else {          // z: silu
#pragma unroll
                for (int j = 0; j < 8; j++) {
                    float a0, a1, a2, a3;
                    upk2(acc[j][0], a0, a1); upk2(acc[j][1], a2, a3);
                    float4 o;
                    o.x = siluf(a0); o.y = siluf(a1); o.z = siluf(a2); o.w = siluf(a3);
                    *(float4*)&s.sz[(rb + j) * XC_S + 4 * lane] = o;
                }
            }
        }
        __syncthreads();

        // ---- stage B: warp w owns rows 4w..4w+3 end-to-end (R2 dataflow) ----
        {
            const int rb4 = 4 * w;
            // lane-local xc chunk (cols 4*lane..4*lane+3) per job
            float xcv[4][4];
#pragma unroll
            for (int j = 0; j < 4; j++) {
                float4 v = *(const float4*)&s.xc[(rb4 + j) * XC_S + 4 * lane];
                xcv[j][0] = v.x; xcv[j][1] = v.y; xcv[j][2] = v.z; xcv[j][3] = v.w;
            }
            // dt pre-projection rows 0..3 via butterfly
            float pr[4][4];
#pragma unroll
            for (int r = 0; r < 4; r++) {
                float4 wv = *(const float4*)&s.xpj[r * 132 + 4 * lane];
#pragma unroll
                for (int j = 0; j < 4; j++) {
                    float p = xcv[j][0] * wv.x + xcv[j][1] * wv.y
                            + xcv[j][2] * wv.z + xcv[j][3] * wv.w;
                    pr[r][j] = warp_sum(p);
                }
            }
            // BC: lane computes xpwT row 4+lane over 128 dims, 4 jobs
            const float* wrow = &s.xpwT[(4 + lane) * XPW_S];
            ull a01 = 0ULL, a23 = 0ULL;
#pragma unroll 4
            for (int d0 = 0; d0 < 128; d0 += 4) {
                float4 c0 = *(const float4*)&s.xc[(rb4 + 0) * XC_S + d0];
                float4 c1 = *(const float4*)&s.xc[(rb4 + 1) * XC_S + d0];
                float4 c2 = *(const float4*)&s.xc[(rb4 + 2) * XC_S + d0];
                float4 c3 = *(const float4*)&s.xc[(rb4 + 3) * XC_S + d0];
                float w0 = wrow[d0], w1 = wrow[d0 + 1], w2 = wrow[d0 + 2], w3 = wrow[d0 + 3];
                a01 = ffma2(pk2(c0.x, c1.x), pk2(w0, w0), a01);
                a23 = ffma2(pk2(c2.x, c3.x), pk2(w0, w0), a23);
                a01 = ffma2(pk2(c0.y, c1.y), pk2(w1, w1), a01);
                a23 = ffma2(pk2(c2.y, c3.y), pk2(w1, w1), a23);
                a01 = ffma2(pk2(c0.z, c1.z), pk2(w2, w2), a01);
                a23 = ffma2(pk2(c2.z, c3.z), pk2(w2, w2), a23);
                a01 = ffma2(pk2(c0.w, c1.w), pk2(w3, w3), a01);
                a23 = ffma2(pk2(c2.w, c3.w), pk2(w3, w3), a23);
            }
            float bc[4];
            upk2(a01, bc[0], bc[1]); upk2(a23, bc[2], bc[3]);
#pragma unroll
            for (int j = 0; j < 4; j++) {
                float other = __shfl_xor_sync(0xffffffffu, bc[j], 16);
                bc[j] = half_sum(bc[j] * other);
            }
            // dts = softplus(pr @ dtw + dtb) on lane's 4 cols
            float dts[4][4];
            {
                float4 dtbv = *(const float4*)&s.dtb[4 * lane];
#pragma unroll
                for (int j = 0; j < 4; j++) {
                    dts[j][0] = dtbv.x; dts[j][1] = dtbv.y;
                    dts[j][2] = dtbv.z; dts[j][3] = dtbv.w;
                }
#pragma unroll
                for (int r = 0; r < 4; r++) {
                    float4 dwv = *(const float4*)&s.dtw[r * 128 + 4 * lane];
#pragma unroll
                    for (int j = 0; j < 4; j++) {
                        dts[j][0] = fmaf(pr[r][j], dwv.x, dts[j][0]);
                        dts[j][1] = fmaf(pr[r][j], dwv.y, dts[j][1]);
                        dts[j][2] = fmaf(pr[r][j], dwv.z, dts[j][2]);
                        dts[j][3] = fmaf(pr[r][j], dwv.w, dts[j][3]);
                    }
                }
#pragma unroll
                for (int j = 0; j < 4; j++) {
                    dts[j][0] = softplusf(dts[j][0]); dts[j][1] = softplusf(dts[j][1]);
                    dts[j][2] = softplusf(dts[j][2]); dts[j][3] = softplusf(dts[j][3]);
                }
            }
            // y = xc*(dts*BC + dskip)*silu(z)  -> back into s.xc
            {
                float4 dskv = *(const float4*)&s.dskip[4 * lane];
#pragma unroll
                for (int j = 0; j < 4; j++) {
                    float4 szv = *(const float4*)&s.sz[(rb4 + j) * XC_S + 4 * lane];
                    float4 yv;
                    yv.x = xcv[j][0] * fmaf(dts[j][0], bc[j], dskv.x) * szv.x;
                    yv.y = xcv[j][1] * fmaf(dts[j][1], bc[j], dskv.y) * szv.y;
                    yv.z = xcv[j][2] * fmaf(dts[j][2], bc[j], dskv.z) * szv.z;
                    yv.w = xcv[j][3] * fmaf(dts[j][3], bc[j], dskv.w) * szv.w;
                    *(float4*)&s.xc[(rb4 + j) * XC_S + 4 * lane] = yv;
                }
            }
            __syncwarp();

            // out-proj gemv: 128 -> 64, lane owns out cols {2lane, 2lane+1}
            ull aco[4] = {0ULL, 0ULL, 0ULL, 0ULL};
            const float* y0p = &s.xc[(rb4 + 0) * XC_S];
            const float* y1p = &s.xc[(rb4 + 1) * XC_S];
            const float* y2p = &s.xc[(rb4 + 2) * XC_S];
            const float* y3p = &s.xc[(rb4 + 3) * XC_S];
#pragma unroll 4
            for (int d0 = 0; d0 < 128; d0 += 4) {
                float4 y0 = *(const float4*)(y0p + d0);
                float4 y1 = *(const float4*)(y1p + d0);
                float4 y2 = *(const float4*)(y2p + d0);
                float4 y3 = *(const float4*)(y3p + d0);
#pragma unroll
                for (int q = 0; q < 4; q++) {
                    ull wp = *(const ull*)&s.opw[(d0 + q) * 64 + 2 * lane];
                    float f0 = fcomp(y0, q), f1 = fcomp(y1, q);
                    float f2 = fcomp(y2, q), f3 = fcomp(y3, q);
                    aco[0] = ffma2(wp, pk2(f0, f0), aco[0]);
                    aco[1] = ffma2(wp, pk2(f1, f1), aco[1]);
                    aco[2] = ffma2(wp, pk2(f2, f2), aco[2]);
                    aco[3] = ffma2(wp, pk2(f3, f3), aco[3]);
                }
            }

            // layernorm(64) + residual -> s.xs
            {
                float2 gv = *(const float2*)&s.lng[2 * lane];
                float2 bv = *(const float2*)&s.lnb[2 * lane];
#pragma unroll
                for (int j = 0; j < 4; j++) {
                    float o0, o1;
                    upk2(aco[j], o0, o1);
                    float m  = warp_sum(o0 + o1) * (1.0f / 64.0f);
                    float m2 = warp_sum(o0 * o0 + o1 * o1) * (1.0f / 64.0f);
                    float rs = rsqrtf(m2 - m * m + EPSV);
                    float2 xv = *(const float2*)&s.xs[(rb4 + j) * XS_S + 2 * lane];
                    xv.x += (o0 - m) * rs * gv.x + bv.x;
                    xv.y += (o1 - m) * rs * gv.y + bv.y;
                    *(float2*)&s.xs[(rb4 + j) * XS_S + 2 * lane] = xv;
                }
            }
        }
    }

    // ================= head =================
    __syncthreads();
    {
        float* hs = s.xc;   // reuse as hw1[128][33]
        for (int i = t; i < 4096; i += THREADS) {
            int k = i >> 5, c = i & 31;
            hs[k * 33 + c] = hw1[i];
        }
        if (t < 32) { s.cw3[t] = hb1[t]; s.cb[t] = hw2[t]; }
        __syncthreads();

        float b2v = hb2[0];
#pragma unroll
        for (int j = 0; j < 2; j++) {
            int ra = 4 * w + 2 * j;              // nr row; r row = ra+1
            float h = s.cw3[lane];
            const float* xa = &s.xs[ra * XS_S];
            const float* xb = &s.xs[(ra + 1) * XS_S];
#pragma unroll 8
            for (int k = 0; k < 64; k++) h = fmaf(xa[k], hs[k * 33 + lane], h);
#pragma unroll 8
            for (int k = 0; k < 64; k++) h = fmaf(xb[k], hs[(64 + k) * 33 + lane], h);
            h = fmaxf(h, 0.0f);
            float v = warp_sum(h * s.cb[lane]);
            if (lane == 0) out[blockIdx.x * EPB + 2 * w + j] = v + b2v;
        }
    }
}

extern "C" void kernel_launch(void* const* d_in, const int* in_sizes, int n_in,
                              void* d_out, int out_size) {
    const float* x        = (const float*)d_in[0];
    const float* w_nr     = (const float*)d_in[1];
    const float* b_nr     = (const float*)d_in[2];
    const float* w_r      = (const float*)d_in[3];
    const float* b_r      = (const float*)d_in[4];
    const float* w_in_nr  = (const float*)d_in[5];
    const float* b_in_nr  = (const float*)d_in[6];
    const float* w_in_r   = (const float*)d_in[7];
    const float* b_in_r   = (const float*)d_in[8];
    const float* ipw      = (const float*)d_in[9];
    const float* cw       = (const float*)d_in[10];
    const float* cb       = (const float*)d_in[11];
    const float* xpw      = (const float*)d_in[12];
    const float* dtw      = (const float*)d_in[13];
    const float* dtb      = (const float*)d_in[14];
    /* alog d_in[15] dead at L=1 (scan h0=0) */
    const float* dskip    = (const float*)d_in[16];
    const float* opw      = (const float*)d_in[17];
    const float* lng      = (const float*)d_in[18];
    const float* lnb      = (const float*)d_in[19];
    const float* hw1      = (const float*)d_in[20];
    const float* hb1      = (const float*)d_in[21];
    const float* hw2      = (const float*)d_in[22];
    const float* hb2      = (const float*)d_in[23];

    size_t smem = sizeof(Smem);
    cudaFuncSetAttribute((const void*)mamba_main,
                         cudaFuncAttributeMaxDynamicSharedMemorySize, (int)smem);

    prep_kernel<<<144, 256>>>(w_nr, b_nr, w_r, b_r, w_in_nr, b_in_nr, w_in_r, b_in_r);
    mamba_main<<<NBLK, THREADS, smem>>>(x, ipw, cw, cb, xpw, dtw, dtb, dskip, opw,
                                        lng, lnb, hw1, hb1, hw2, hb2, (float*)d_out);
}

// round 6
// speedup vs baseline: 1.6366x; 1.3029x over previous
#include <cuda_runtime.h>

#define NL 4
#define BATCH 16384
#define THREADS 512
#define EPB 32
#define NBLK (BATCH / EPB)
#define XS_S 68          // xs row stride (floats)
#define XC_S 132         // xc/sz row stride (floats)
#define XPW_S 129
#define IPW_S 264        // packed ipw kpair-row stride (u32 words)
#define OPW_S 72         // packed opw kpair-row stride (u32 words)
#define EPSV 1e-5f

typedef unsigned long long ull;
typedef unsigned int u32;

__device__ __forceinline__ ull pk2(float lo, float hi) {
    ull r; asm("mov.b64 %0,{%1,%2};" : "=l"(r) : "f"(lo), "f"(hi)); return r;
}
__device__ __forceinline__ void upk2(ull v, float& lo, float& hi) {
    asm("mov.b64 {%0,%1},%2;" : "=f"(lo), "=f"(hi) : "l"(v));
}
__device__ __forceinline__ ull ffma2(ull a, ull b, ull c) {
    ull d; asm("fma.rn.f32x2 %0,%1,%2,%3;" : "=l"(d) : "l"(a), "l"(b), "l"(c)); return d;
}
__device__ __forceinline__ float warp_sum(float v) {
    v += __shfl_xor_sync(0xffffffffu, v, 16);
    v += __shfl_xor_sync(0xffffffffu, v, 8);
    v += __shfl_xor_sync(0xffffffffu, v, 4);
    v += __shfl_xor_sync(0xffffffffu, v, 2);
    v += __shfl_xor_sync(0xffffffffu, v, 1);
    return v;
}
__device__ __forceinline__ float half_sum(float v) {
    v += __shfl_xor_sync(0xffffffffu, v, 8);
    v += __shfl_xor_sync(0xffffffffu, v, 4);
    v += __shfl_xor_sync(0xffffffffu, v, 2);
    v += __shfl_xor_sync(0xffffffffu, v, 1);
    return v;
}
__device__ __forceinline__ void group_bar(int q) {   // 4-warp barrier, ids 1..4
    asm volatile("bar.sync %0, 128;" :: "r"(q + 1) : "memory");
}
__device__ __forceinline__ float siluf(float v) {
    return __fdividef(v, 1.0f + __expf(-v));
}
__device__ __forceinline__ float softplusf(float v) {
    return fmaxf(v, 0.0f) + __logf(1.0f + __expf(-fabsf(v)));
}
__device__ __forceinline__ float fcomp(const float4& v, int k) {
    return k == 0 ? v.x : k == 1 ? v.y : k == 2 ? v.z : v.w;
}
// split two fp32 (p.x = even/low, p.y = odd/high) into packed bf16x2 hi + lo
__device__ __forceinline__ void bfsplit(float2 p, u32& h, u32& l) {
    asm("cvt.rn.satfinite.bf16x2.f32 %0,%1,%2;" : "=r"(h) : "f"(p.y), "f"(p.x));
    float h0 = __uint_as_float(h << 16);
    float h1 = __uint_as_float(h & 0xffff0000u);
    asm("cvt.rn.satfinite.bf16x2.f32 %0,%1,%2;" : "=r"(l) : "f"(p.y - h1), "f"(p.x - h0));
}
__device__ __forceinline__ void mma_bf16(float* c, const u32* a, u32 b0, u32 b1) {
    asm("mma.sync.aligned.m16n8k16.row.col.f32.bf16.bf16.f32 "
        "{%0,%1,%2,%3},{%4,%5,%6,%7},{%8,%9},{%0,%1,%2,%3};"
        : "+f"(c[0]), "+f"(c[1]), "+f"(c[2]), "+f"(c[3])
        : "r"(a[0]), "r"(a[1]), "r"(a[2]), "r"(a[3]), "r"(b0), "r"(b1));
}

// ------------- folded input-projection weights -------------
__device__ float g_Wnr[12 * 64];
__device__ float g_bnr[64];
__device__ float g_Wr[4 * 64];
__device__ float g_br[64];

__global__ void __launch_bounds__(256)
prep_kernel(const float* __restrict__ w_nr, const float* __restrict__ b_nr,
            const float* __restrict__ w_r,  const float* __restrict__ b_r,
            const float* __restrict__ w_in_nr, const float* __restrict__ b_in_nr,
            const float* __restrict__ w_in_r,  const float* __restrict__ b_in_r) {
    int W = blockIdx.x * 8 + (threadIdx.x >> 5);   // 0..1151
    int lane = threadIdx.x & 31;
    const float* vec; const float* mat; int o;
    if (W < 768)        { vec = w_nr + (W >> 6) * 1000;        mat = w_in_nr; o = W & 63; }
    else if (W < 832)   { vec = b_nr;                          mat = w_in_nr; o = W - 768; }
    else if (W < 1088)  { vec = w_r + ((W - 832) >> 6) * 1000; mat = w_in_r;  o = (W - 832) & 63; }
    else                { vec = b_r;                           mat = w_in_r;  o = W - 1088; }
    float a = 0.0f;
    for (int c = lane; c < 1000; c += 32)
        a = fmaf(vec[c], mat[c * 64 + o], a);
    a = warp_sum(a);
    if (lane == 0) {
        if (W < 768)       g_Wnr[W] = a;
        else if (W < 832)  g_bnr[W - 768] = a + b_in_nr[W - 768];
        else if (W < 1088) g_Wr[W - 832] = a;
        else               g_br[W - 1088] = a + b_in_r[W - 1088];
    }
}

// ---------------- shared memory (~214 KB; 1 block/SM) ----------------
struct __align__(16) Smem {
    u32 ipwh[32 * IPW_S];     // xz weights bf16-hi, kpair-packed
    u32 ipwl[32 * IPW_S];     // bf16-lo
    u32 opwh[64 * OPW_S];
    u32 opwl[64 * OPW_S];
    float xpwT[36 * XPW_S];   // B/C rows 4..35, stride 129
    float xpj[4 * 132];       // dt-proj rows 0..3
    float dtw[4 * 128];
    float cw3[128];
    float cb[128];
    float dtb[128];
    float dskip[128];
    float lng[64];
    float lnb[64];
    float Wnr[12 * 64];
    float Wr[4 * 64];
    float bnr[64];
    float br[64];
    float xs[64 * XS_S];      // residual stream
    float xc[64 * XC_S];      // xc -> y in place; head reuses as hw1[128][33]
    float sz[64 * XC_S];      // silu(z) cols 0..127, then O cols 0..63
};

__global__ void __launch_bounds__(THREADS, 1)
mamba_main(const float* __restrict__ xin,
           const float* __restrict__ ipw_g, const float* __restrict__ cw_g,
           const float* __restrict__ cb_g,  const float* __restrict__ xpw_g,
           const float* __restrict__ dtw_g, const float* __restrict__ dtb_g,
           const float* __restrict__ dskip_g, const float* __restrict__ opw_g,
           const float* __restrict__ lng_g, const float* __restrict__ lnb_g,
           const float* __restrict__ hw1, const float* __restrict__ hb1,
           const float* __restrict__ hw2, const float* __restrict__ hb2,
           float* __restrict__ out) {
    extern __shared__ __align__(16) char smem_raw[];
    Smem& s = *reinterpret_cast<Smem*>(smem_raw);

    const int t = threadIdx.x;
    const int w = t >> 5;
    const int lane = t & 31;
    const int q = w & 3;          // m-tile (group id)
    const int nc = w >> 2;        // n-chunk
    const int g = lane >> 2;      // mma group row
    const int cc = lane & 3;      // mma thread-in-group
    const int rb4 = 16 * q + 4 * nc;   // stage B/D row base

    // ---- stage folded input-proj weights ----
    for (int i = t; i < 768; i += THREADS) s.Wnr[i] = g_Wnr[i];
    if (t < 256)      s.Wr[t] = g_Wr[t];
    else if (t < 320) s.bnr[t - 256] = g_bnr[t - 256];
    else if (t < 384) s.br[t - 320] = g_br[t - 320];
    __syncthreads();

    // ---- x0 = feat @ W_eff + b_eff : warp w -> rows 4w..4w+3 ----
    {
        const int e0 = blockIdx.x * EPB + 2 * w;
        float fe[2][16];
#pragma unroll
        for (int e = 0; e < 2; e++) {
            const float4* xp = (const float4*)(xin + (size_t)(e0 + e) * 16);
#pragma unroll
            for (int qq = 0; qq < 4; qq++) {
                float4 v = xp[qq];
                fe[e][4 * qq + 0] = v.x; fe[e][4 * qq + 1] = v.y;
                fe[e][4 * qq + 2] = v.z; fe[e][4 * qq + 3] = v.w;
            }
        }
        float2 bn = *(const float2*)&s.bnr[2 * lane];
        float2 bb = *(const float2*)&s.br[2 * lane];
        ull a0 = pk2(bn.x, bn.y), a2 = a0;
        ull a1 = pk2(bb.x, bb.y), a3 = a1;
#pragma unroll
        for (int f = 0; f < 12; f++) {
            ull wp = *(const ull*)&s.Wnr[f * 64 + 2 * lane];
            a0 = ffma2(wp, pk2(fe[0][f], fe[0][f]), a0);
            a2 = ffma2(wp, pk2(fe[1][f], fe[1][f]), a2);
        }
#pragma unroll
        for (int f = 0; f < 4; f++) {
            ull wp = *(const ull*)&s.Wr[f * 64 + 2 * lane];
            a1 = ffma2(wp, pk2(fe[0][12 + f], fe[0][12 + f]), a1);
            a3 = ffma2(wp, pk2(fe[1][12 + f], fe[1][12 + f]), a3);
        }
        float v0, v1;
        upk2(a0, v0, v1); *(float2*)&s.xs[(4 * w + 0) * XS_S + 2 * lane] = make_float2(v0, v1);
        upk2(a1, v0, v1); *(float2*)&s.xs[(4 * w + 1) * XS_S + 2 * lane] = make_float2(v0, v1);
        upk2(a2, v0, v1); *(float2*)&s.xs[(4 * w + 2) * XS_S + 2 * lane] = make_float2(v0, v1);
        upk2(a3, v0, v1); *(float2*)&s.xs[(4 * w + 3) * XS_S + 2 * lane] = make_float2(v0, v1);
    }

    // ================= layer loop =================
#pragma unroll 1
    for (int l = 0; l < NL; l++) {
        __syncthreads();   // everyone done with prev weights + xs writes visible
        {
            // ipw [64k][256n] fp32 -> bf16 hi/lo, packed along k-pairs
            for (int i = t; i < 32 * 256; i += THREADS) {
                int kp = i >> 8, n = i & 255;
                const float* src = ipw_g + l * 16384 + (2 * kp) * 256 + n;
                float2 p = make_float2(src[0], src[256]);
                u32 h, lo; bfsplit(p, h, lo);
                s.ipwh[kp * IPW_S + n] = h;
                s.ipwl[kp * IPW_S + n] = lo;
            }
            // opw [128k][64n]
            for (int i = t; i < 64 * 64; i += THREADS) {
                int kp = i >> 6, n = i & 63;
                const float* src = opw_g + l * 8192 + (2 * kp) * 64 + n;
                float2 p = make_float2(src[0], src[64]);
                u32 h, lo; bfsplit(p, h, lo);
                s.opwh[kp * OPW_S + n] = h;
                s.opwl[kp * OPW_S + n] = lo;
            }
            for (int i = t; i < 4608; i += THREADS) {   // xpw[l][d][j]
                int d = i / 36, j = i - d * 36;
                float v = xpw_g[l * 4608 + i];
                if (j < 4) s.xpj[j * 132 + d] = v;
                else       s.xpwT[j * XPW_S + d] = v;
            }
            s.dtw[t] = dtw_g[l * 512 + t];
            if (t < 128)      s.cw3[t] = cw_g[(l * 128 + t) * 4 + 3];
            else if (t < 256) s.cb[t - 128] = cb_g[l * 128 + (t - 128)];
            else if (t < 384) s.dtb[t - 256] = dtb_g[l * 128 + (t - 256)];
            else              s.dskip[t - 384] = dskip_g[l * 128 + (t - 384)];
            if (t < 64)       s.lng[t] = lng_g[l * 64 + t];
            else if (t < 128) s.lnb[t - 64] = lnb_g[l * 64 + (t - 64)];
        }
        __syncthreads();

        // ======== stage A: xz GEMM via bf16x3 mma; warp = m-tile q, n-chunk nc*64 ========
        {
            const float* arow0 = &s.xs[(16 * q + g) * XS_S];
            const float* arow8 = &s.xs[(16 * q + g + 8) * XS_S];
            float acc[8][4];
#pragma unroll
            for (int nt = 0; nt < 8; nt++)
#pragma unroll
                for (int i = 0; i < 4; i++) acc[nt][i] = 0.0f;
#pragma unroll
            for (int ks = 0; ks < 4; ks++) {
                const int k0 = ks * 16 + 2 * cc;
                u32 ah[4], al[4];
                bfsplit(*(const float2*)(arow0 + k0),     ah[0], al[0]);
                bfsplit(*(const float2*)(arow8 + k0),     ah[1], al[1]);
                bfsplit(*(const float2*)(arow0 + k0 + 8), ah[2], al[2]);
                bfsplit(*(const float2*)(arow8 + k0 + 8), ah[3], al[3]);
                const u32* bh = &s.ipwh[(ks * 8 + cc) * IPW_S + nc * 64 + g];
                const u32* bl = &s.ipwl[(ks * 8 + cc) * IPW_S + nc * 64 + g];
#pragma unroll
                for (int nt = 0; nt < 8; nt++) {
                    u32 bh0 = bh[nt * 8], bh1 = bh[4 * IPW_S + nt * 8];
                    u32 bl0 = bl[nt * 8], bl1 = bl[4 * IPW_S + nt * 8];
                    mma_bf16(acc[nt], ah, bh0, bh1);
                    mma_bf16(acc[nt], ah, bl0, bl1);
                    mma_bf16(acc[nt], al, bh0, bh1);
                }
            }
            const int row0 = 16 * q + g, row8 = row0 + 8;
            if (nc < 2) {        // xc half: conv tap + silu
#pragma unroll
                for (int nt = 0; nt < 8; nt++) {
                    int col = nc * 64 + nt * 8 + 2 * cc;
                    float2 cwv = *(const float2*)&s.cw3[col];
                    float2 cbv = *(const float2*)&s.cb[col];
                    *(float2*)&s.xc[row0 * XC_S + col] =
                        make_float2(siluf(fmaf(acc[nt][0], cwv.x, cbv.x)),
                                    siluf(fmaf(acc[nt][1], cwv.y, cbv.y)));
                    *(float2*)&s.xc[row8 * XC_S + col] =
                        make_float2(siluf(fmaf(acc[nt][2], cwv.x, cbv.x)),
                                    siluf(fmaf(acc[nt][3], cwv.y, cbv.y)));
                }
            } else {             // z half: silu
#pragma unroll
                for (int nt = 0; nt < 8; nt++) {
                    int col = (nc - 2) * 64 + nt * 8 + 2 * cc;
                    *(float2*)&s.sz[row0 * XC_S + col] =
                        make_float2(siluf(acc[nt][0]), siluf(acc[nt][1]));
                    *(float2*)&s.sz[row8 * XC_S + col] =
                        make_float2(siluf(acc[nt][2]), siluf(acc[nt][3]));
                }
            }
        }
        group_bar(q);

        // ======== stage B: dt/BC/y for rows rb4..rb4+3 (scalar, per warp) ========
        {
            float xcv[4][4];
#pragma unroll
            for (int j = 0; j < 4; j++) {
                float4 v = *(const float4*)&s.xc[(rb4 + j) * XC_S + 4 * lane];
                xcv[j][0] = v.x; xcv[j][1] = v.y; xcv[j][2] = v.z; xcv[j][3] = v.w;
            }
            float pr[4][4];
#pragma unroll
            for (int r = 0; r < 4; r++) {
                float4 wv = *(const float4*)&s.xpj[r * 132 + 4 * lane];
#pragma unroll
                for (int j = 0; j < 4; j++) {
                    float p = xcv[j][0] * wv.x + xcv[j][1] * wv.y
                            + xcv[j][2] * wv.z + xcv[j][3] * wv.w;
                    pr[r][j] = warp_sum(p);
                }
            }
            const float* wrow = &s.xpwT[(4 + lane) * XPW_S];
            ull a01 = 0ULL, a23 = 0ULL;
#pragma unroll 4
            for (int d0 = 0; d0 < 128; d0 += 4) {
                float4 c0 = *(const float4*)&s.xc[(rb4 + 0) * XC_S + d0];
                float4 c1 = *(const float4*)&s.xc[(rb4 + 1) * XC_S + d0];
                float4 c2 = *(const float4*)&s.xc[(rb4 + 2) * XC_S + d0];
                float4 c3 = *(const float4*)&s.xc[(rb4 + 3) * XC_S + d0];
                float w0 = wrow[d0], w1 = wrow[d0 + 1], w2 = wrow[d0 + 2], w3 = wrow[d0 + 3];
                a01 = ffma2(pk2(c0.x, c1.x), pk2(w0, w0), a01);
                a23 = ffma2(pk2(c2.x, c3.x), pk2(w0, w0), a23);
                a01 = ffma2(pk2(c0.y, c1.y), pk2(w1, w1), a01);
                a23 = ffma2(pk2(c2.y, c3.y), pk2(w1, w1), a23);
                a01 = ffma2(pk2(c0.z, c1.z), pk2(w2, w2), a01);
                a23 = ffma2(pk2(c2.z, c3.z), pk2(w2, w2), a23);
                a01 = ffma2(pk2(c0.w, c1.w), pk2(w3, w3), a01);
                a23 = ffma2(pk2(c2.w, c3.w), pk2(w3, w3), a23);
            }
            float bc[4];
            upk2(a01, bc[0], bc[1]); upk2(a23, bc[2], bc[3]);
#pragma unroll
            for (int j = 0; j < 4; j++) {
                float other = __shfl_xor_sync(0xffffffffu, bc[j], 16);
                bc[j] = half_sum(bc[j] * other);
            }
            float dts[4][4];
            {
                float4 dtbv = *(const float4*)&s.dtb[4 * lane];
#pragma unroll
                for (int j = 0; j < 4; j++) {
                    dts[j][0] = dtbv.x; dts[j][1] = dtbv.y;
                    dts[j][2] = dtbv.z; dts[j][3] = dtbv.w;
                }
#pragma unroll
                for (int r = 0; r < 4; r++) {
                    float4 dwv = *(const float4*)&s.dtw[r * 128 + 4 * lane];
#pragma unroll
                    for (int j = 0; j < 4; j++) {
                        dts[j][0] = fmaf(pr[r][j], dwv.x, dts[j][0]);
                        dts[j][1] = fmaf(pr[r][j], dwv.y, dts[j][1]);
                        dts[j][2] = fmaf(pr[r][j], dwv.z, dts[j][2]);
                        dts[j][3] = fmaf(pr[r][j], dwv.w, dts[j][3]);
                    }
                }
#pragma unroll
                for (int j = 0; j < 4; j++) {
                    dts[j][0] = softplusf(dts[j][0]); dts[j][1] = softplusf(dts[j][1]);
                    dts[j][2] = softplusf(dts[j][2]); dts[j][3] = softplusf(dts[j][3]);
                }
            }
            __syncwarp();   // all lanes done reading xc rows before y overwrite
            {
                float4 dskv = *(const float4*)&s.dskip[4 * lane];
#pragma unroll
                for (int j = 0; j < 4; j++) {
                    float4 szv = *(const float4*)&s.sz[(rb4 + j) * XC_S + 4 * lane];
                    float4 yv;
                    yv.x = xcv[j][0] * fmaf(dts[j][0], bc[j], dskv.x) * szv.x;
                    yv.y = xcv[j][1] * fmaf(dts[j][1], bc[j], dskv.y) * szv.y;
                    yv.z = xcv[j][2] * fmaf(dts[j][2], bc[j], dskv.z) * szv.z;
                    yv.w = xcv[j][3] * fmaf(dts[j][3], bc[j], dskv.w) * szv.w;
                    *(float4*)&s.xc[(rb4 + j) * XC_S + 4 * lane] = yv;
                }
            }
        }
        group_bar(q);

        // ======== stage C: out-proj GEMM via bf16x3 mma; warp = m-tile q, n-chunk nc*16 ========
        {
            const float* arow0 = &s.xc[(16 * q + g) * XC_S];
            const float* arow8 = &s.xc[(16 * q + g + 8) * XC_S];
            float acc[2][4];
#pragma unroll
            for (int nt = 0; nt < 2; nt++)
#pragma unroll
                for (int i = 0; i < 4; i++) acc[nt][i] = 0.0f;
#pragma unroll
            for (int ks = 0; ks < 8; ks++) {
                const int k0 = ks * 16 + 2 * cc;
                u32 ah[4], al[4];
                bfsplit(*(const float2*)(arow0 + k0),     ah[0], al[0]);
                bfsplit(*(const float2*)(arow8 + k0),     ah[1], al[1]);
                bfsplit(*(const float2*)(arow0 + k0 + 8), ah[2], al[2]);
                bfsplit(*(const float2*)(arow8 + k0 + 8), ah[3], al[3]);
                const u32* bh = &s.opwh[(ks * 8 + cc) * OPW_S + nc * 16 + g];
                const u32* bl = &s.opwl[(ks * 8 + cc) * OPW_S + nc * 16 + g];
#pragma unroll
                for (int nt = 0; nt < 2; nt++) {
                    u32 bh0 = bh[nt * 8], bh1 = bh[4 * OPW_S + nt * 8];
                    u32 bl0 = bl[nt * 8], bl1 = bl[4 * OPW_S + nt * 8];
                    mma_bf16(acc[nt], ah, bh0, bh1);
                    mma_bf16(acc[nt], ah, bl0, bl1);
                    mma_bf16(acc[nt], al, bh0, bh1);
                }
            }
            const int row0 = 16 * q + g, row8 = row0 + 8;
#pragma unroll
            for (int nt = 0; nt < 2; nt++) {
                int col = nc * 16 + nt * 8 + 2 * cc;
                *(float2*)&s.sz[row0 * XC_S + col] = make_float2(acc[nt][0], acc[nt][1]);
                *(float2*)&s.sz[row8 * XC_S + col] = make_float2(acc[nt][2], acc[nt][3]);
            }
        }
        group_bar(q);

        // ======== stage D: layernorm(64) + residual, rows rb4..rb4+3 ========
        {
            float2 gv = *(const float2*)&s.lng[2 * lane];
            float2 bv = *(const float2*)&s.lnb[2 * lane];
#pragma unroll
            for (int j = 0; j < 4; j++) {
                float2 ov = *(const float2*)&s.sz[(rb4 + j) * XC_S + 2 * lane];
                float m  = warp_sum(ov.x + ov.y) * (1.0f / 64.0f);
                float m2 = warp_sum(ov.x * ov.x + ov.y * ov.y) * (1.0f / 64.0f);
                float rs = rsqrtf(m2 - m * m + EPSV);
                float2 xv = *(const float2*)&s.xs[(rb4 + j) * XS_S + 2 * lane];
                xv.x += (ov.x - m) * rs * gv.x + bv.x;
                xv.y += (ov.y - m) * rs * gv.y + bv.y;
                *(float2*)&s.xs[(rb4 + j) * XS_S + 2 * lane] = xv;
            }
        }
    }

    // ================= head =================
    __syncthreads();
    {
        float* hs = s.xc;   // reuse as hw1[128][33]
        for (int i = t; i < 4096; i += THREADS) {
            int k = i >> 5, c = i & 31;
            hs[k * 33 + c] = hw1[i];
        }
        if (t < 32) { s.cw3[t] = hb1[t]; s.cb[t] = hw2[t]; }
        __syncthreads();

        float b2v = hb2[0];
#pragma unroll
        for (int j = 0; j < 2; j++) {
            int ra = 4 * w + 2 * j;              // nr row; r row = ra+1
            float h = s.cw3[lane];
            const float* xa = &s.xs[ra * XS_S];
            const float* xb = &s.xs[(ra + 1) * XS_S];
#pragma unroll 8
            for (int k = 0; k < 64; k++) h = fmaf(xa[k], hs[k * 33 + lane], h);
#pragma unroll 8
            for (int k = 0; k < 64; k++) h = fmaf(xb[k], hs[(64 + k) * 33 + lane], h);
            h = fmaxf(h, 0.0f);
            float v = warp_sum(h * s.cb[lane]);
            if (lane == 0) out[blockIdx.x * EPB + 2 * w + j] = v + b2v;
        }
    }
}

extern "C" void kernel_launch(void* const* d_in, const int* in_sizes, int n_in,
                              void* d_out, int out_size) {
    const float* x        = (const float*)d_in[0];
    const float* w_nr     = (const float*)d_in[1];
    const float* b_nr     = (const float*)d_in[2];
    const float* w_r      = (const float*)d_in[3];
    const float* b_r      = (const float*)d_in[4];
    const float* w_in_nr  = (const float*)d_in[5];
    const float* b_in_nr  = (const float*)d_in[6];
    const float* w_in_r   = (const float*)d_in[7];
    const float* b_in_r   = (const float*)d_in[8];
    const float* ipw      = (const float*)d_in[9];
    const float* cw       = (const float*)d_in[10];
    const float* cb       = (const float*)d_in[11];
    const float* xpw      = (const float*)d_in[12];
    const float* dtw      = (const float*)d_in[13];
    const float* dtb      = (const float*)d_in[14];
    /* alog d_in[15] dead at L=1 (scan h0=0) */
    const float* dskip    = (const float*)d_in[16];
    const float* opw      = (const float*)d_in[17];
    const float* lng      = (const float*)d_in[18];
    const float* lnb      = (const float*)d_in[19];
    const float* hw1      = (const float*)d_in[20];
    const float* hb1      = (const float*)d_in[21];
    const float* hw2      = (const float*)d_in[22];
    const float* hb2      = (const float*)d_in[23];

    size_t smem = sizeof(Smem);
    cudaFuncSetAttribute((const void*)mamba_main,
                         cudaFuncAttributeMaxDynamicSharedMemorySize, (int)smem);

    prep_kernel<<<144, 256>>>(w_nr, b_nr, w_r, b_r, w_in_nr, b_in_nr, w_in_r, b_in_r);
    mamba_main<<<NBLK, THREADS, smem>>>(x, ipw, cw, cb, xpw, dtw, dtb, dskip, opw,
                                        lng, lnb, hw1, hb1, hw2, hb2, (float*)d_out);
}

// round 7
// speedup vs baseline: 1.6993x; 1.0383x over previous
#include <cuda_runtime.h>

#define NL 4
#define BATCH 16384
#define THREADS 512
#define EPB 32
#define NBLK (BATCH / EPB)
#define XS_S 68          // xs row stride (floats)
#define XC_S 132         // xc/sz row stride (floats / u32)
#define XH_S 36          // split-xs row stride (u32)
#define XPW_S 129
#define IPW_S 264        // packed ipw kpair-row stride (u32)
#define OPW_S 72         // packed opw kpair-row stride (u32)
#define EPSV 1e-5f

typedef unsigned long long ull;
typedef unsigned int u32;

__device__ __forceinline__ ull pk2(float lo, float hi) {
    ull r; asm("mov.b64 %0,{%1,%2};" : "=l"(r) : "f"(lo), "f"(hi)); return r;
}
__device__ __forceinline__ void upk2(ull v, float& lo, float& hi) {
    asm("mov.b64 {%0,%1},%2;" : "=f"(lo), "=f"(hi) : "l"(v));
}
__device__ __forceinline__ ull ffma2(ull a, ull b, ull c) {
    ull d; asm("fma.rn.f32x2 %0,%1,%2,%3;" : "=l"(d) : "l"(a), "l"(b), "l"(c)); return d;
}
__device__ __forceinline__ float warp_sum(float v) {
    v += __shfl_xor_sync(0xffffffffu, v, 16);
    v += __shfl_xor_sync(0xffffffffu, v, 8);
    v += __shfl_xor_sync(0xffffffffu, v, 4);
    v += __shfl_xor_sync(0xffffffffu, v, 2);
    v += __shfl_xor_sync(0xffffffffu, v, 1);
    return v;
}
__device__ __forceinline__ float half_sum(float v) {
    v += __shfl_xor_sync(0xffffffffu, v, 8);
    v += __shfl_xor_sync(0xffffffffu, v, 4);
    v += __shfl_xor_sync(0xffffffffu, v, 2);
    v += __shfl_xor_sync(0xffffffffu, v, 1);
    return v;
}
__device__ __forceinline__ void group_bar(int q) {
    asm volatile("bar.sync %0, 128;" :: "r"(q + 1) : "memory");
}
__device__ __forceinline__ float siluf(float v) {
    return __fdividef(v, 1.0f + __expf(-v));
}
__device__ __forceinline__ float softplusf(float v) {
    return fmaxf(v, 0.0f) + __logf(1.0f + __expf(-fabsf(v)));
}
// split two fp32 (p.x = even k, p.y = odd k) into packed bf16x2 hi + lo
__device__ __forceinline__ void bfsplit(float2 p, u32& h, u32& l) {
    asm("cvt.rn.satfinite.bf16x2.f32 %0,%1,%2;" : "=r"(h) : "f"(p.y), "f"(p.x));
    float h0 = __uint_as_float(h << 16);
    float h1 = __uint_as_float(h & 0xffff0000u);
    asm("cvt.rn.satfinite.bf16x2.f32 %0,%1,%2;" : "=r"(l) : "f"(p.y - h1), "f"(p.x - h0));
}
__device__ __forceinline__ void mma_bf16(float* c, const u32* a, u32 b0, u32 b1) {
    asm("mma.sync.aligned.m16n8k16.row.col.f32.bf16.bf16.f32 "
        "{%0,%1,%2,%3},{%4,%5,%6,%7},{%8,%9},{%0,%1,%2,%3};"
        : "+f"(c[0]), "+f"(c[1]), "+f"(c[2]), "+f"(c[3])
        : "r"(a[0]), "r"(a[1]), "r"(a[2]), "r"(a[3]), "r"(b0), "r"(b1));
}

// ------------- precomputed device-global weights -------------
__device__ float g_Wnr[12 * 64];
__device__ float g_bnr[64];
__device__ float g_Wr[4 * 64];
__device__ float g_br[64];
__device__ __align__(16) u32 g_ipwh[NL * 8192];
__device__ __align__(16) u32 g_ipwl[NL * 8192];
__device__ __align__(16) u32 g_opwh[NL * 4096];
__device__ __align__(16) u32 g_opwl[NL * 4096];

__global__ void __launch_bounds__(256)
prep_kernel(const float* __restrict__ w_nr, const float* __restrict__ b_nr,
            const float* __restrict__ w_r,  const float* __restrict__ b_r,
            const float* __restrict__ w_in_nr, const float* __restrict__ b_in_nr,
            const float* __restrict__ w_in_r,  const float* __restrict__ b_in_r) {
    int W = blockIdx.x * 8 + (threadIdx.x >> 5);   // 0..1151
    int lane = threadIdx.x & 31;
    const float* vec; const float* mat; int o;
    if (W < 768)        { vec = w_nr + (W >> 6) * 1000;        mat = w_in_nr; o = W & 63; }
    else if (W < 832)   { vec = b_nr;                          mat = w_in_nr; o = W - 768; }
    else if (W < 1088)  { vec = w_r + ((W - 832) >> 6) * 1000; mat = w_in_r;  o = (W - 832) & 63; }
    else                { vec = b_r;                           mat = w_in_r;  o = W - 1088; }
    float a = 0.0f;
    for (int c = lane; c < 1000; c += 32)
        a = fmaf(vec[c], mat[c * 64 + o], a);
    a = warp_sum(a);
    if (lane == 0) {
        if (W < 768)       g_Wnr[W] = a;
        else if (W < 832)  g_bnr[W - 768] = a + b_in_nr[W - 768];
        else if (W < 1088) g_Wr[W - 832] = a;
        else               g_br[W - 1088] = a + b_in_r[W - 1088];
    }
}

// one-time fp32 -> bf16 hi/lo split of ipw & opw, kpair-packed
__global__ void __launch_bounds__(512)
prep_split(const float* __restrict__ ipw_g, const float* __restrict__ opw_g) {
    int idx = blockIdx.x * 512 + threadIdx.x;
    if (idx < NL * 8192) {
        int l = idx >> 13, r = idx & 8191, kp = r >> 8, n = r & 255;
        const float* src = ipw_g + l * 16384 + kp * 512 + n;
        u32 h, lo; bfsplit(make_float2(src[0], src[256]), h, lo);
        g_ipwh[idx] = h; g_ipwl[idx] = lo;
    } else if (idx < NL * 8192 + NL * 4096) {
        int j = idx - NL * 8192;
        int l = j >> 12, r = j & 4095, kp = r >> 6, n = r & 63;
        const float* src = opw_g + l * 8192 + kp * 128 + n;
        u32 h, lo; bfsplit(make_float2(src[0], src[64]), h, lo);
        g_opwh[j] = h; g_opwl[j] = lo;
    }
}

// ---------------- shared memory (231,104 B; 1 block/SM) ----------------
struct __align__(16) Smem {
    u32 ipwh[32 * IPW_S];
    u32 ipwl[32 * IPW_S];
    u32 opwh[64 * OPW_S];
    u32 opwl[64 * OPW_S];
    float xpwT[32 * XPW_S];   // B/C rows (orig rows 4..35)
    float xpj[4 * 132];       // dt-proj rows 0..3
    float dtw[4 * 128];
    float cw3[128];
    float cb[128];
    float dtb[128];
    float dskip[128];
    float lng[64];
    float lnb[64];
    u32 xsh[64 * XH_S];       // split residual (hi), mma-A kpair layout
    u32 xsl[64 * XH_S];       // (lo)
    float xs[64 * XS_S];      // residual stream fp32
    float xc[64 * XC_S];      // xc fp32 -> split y (u32 hi cols 0..63, lo 64..127)
    float sz[64 * XC_S];      // silu(z), then O
};

__global__ void __launch_bounds__(THREADS, 1)
mamba_main(const float* __restrict__ xin,
           const float* __restrict__ cw_g,  const float* __restrict__ cb_g,
           const float* __restrict__ xpw_g, const float* __restrict__ dtw_g,
           const float* __restrict__ dtb_g, const float* __restrict__ dskip_g,
           const float* __restrict__ lng_g, const float* __restrict__ lnb_g,
           const float* __restrict__ hw1, const float* __restrict__ hb1,
           const float* __restrict__ hw2, const float* __restrict__ hb2,
           float* __restrict__ out) {
    extern __shared__ __align__(16) char smem_raw[];
    Smem& s = *reinterpret_cast<Smem*>(smem_raw);

    const int t = threadIdx.x;
    const int w = t >> 5;
    const int lane = t & 31;
    const int q = w & 3;          // m-tile / barrier group
    const int nc = w >> 2;        // n-chunk
    const int g = lane >> 2;      // mma group row
    const int cc = lane & 3;      // mma thread-in-group
    const int rb4 = 16 * q + 4 * nc;

    // ---- stage folded input-proj weights (union'd into xc region) ----
    float* Wnr_s = s.xc;
    float* Wr_s  = s.xc + 768;
    float* bnr_s = s.xc + 1024;
    float* br_s  = s.xc + 1088;
    for (int i = t; i < 768; i += THREADS) Wnr_s[i] = g_Wnr[i];
    if (t < 256)      Wr_s[t] = g_Wr[t];
    else if (t < 320) bnr_s[t - 256] = g_bnr[t - 256];
    else if (t < 384) br_s[t - 320] = g_br[t - 320];
    __syncthreads();

    // ---- x0 = feat @ W_eff + b_eff : warp w -> rows 4w..4w+3; write fp32 + split ----
    {
        const int e0 = blockIdx.x * EPB + 2 * w;
        float fe[2][16];
#pragma unroll
        for (int e = 0; e < 2; e++) {
            const float4* xp = (const float4*)(xin + (size_t)(e0 + e) * 16);
#pragma unroll
            for (int qq = 0; qq < 4; qq++) {
                float4 v = xp[qq];
                fe[e][4 * qq + 0] = v.x; fe[e][4 * qq + 1] = v.y;
                fe[e][4 * qq + 2] = v.z; fe[e][4 * qq + 3] = v.w;
            }
        }
        float2 bn = *(const float2*)&bnr_s[2 * lane];
        float2 bb = *(const float2*)&br_s[2 * lane];
        ull a0 = pk2(bn.x, bn.y), a2 = a0;
        ull a1 = pk2(bb.x, bb.y), a3 = a1;
#pragma unroll
        for (int f = 0; f < 12; f++) {
            ull wp = *(const ull*)&Wnr_s[f * 64 + 2 * lane];
            a0 = ffma2(wp, pk2(fe[0][f], fe[0][f]), a0);
            a2 = ffma2(wp, pk2(fe[1][f], fe[1][f]), a2);
        }
#pragma unroll
        for (int f = 0; f < 4; f++) {
            ull wp = *(const ull*)&Wr_s[f * 64 + 2 * lane];
            a1 = ffma2(wp, pk2(fe[0][12 + f], fe[0][12 + f]), a1);
            a3 = ffma2(wp, pk2(fe[1][12 + f], fe[1][12 + f]), a3);
        }
        ull accs[4] = {a0, a1, a2, a3};
#pragma unroll
        for (int j = 0; j < 4; j++) {
            float v0, v1; upk2(accs[j], v0, v1);
            int row = 4 * w + j;
            *(float2*)&s.xs[row * XS_S + 2 * lane] = make_float2(v0, v1);
            u32 h, lo; bfsplit(make_float2(v0, v1), h, lo);
            s.xsh[row * XH_S + lane] = h;
            s.xsl[row * XH_S + lane] = lo;
        }
    }

    // ================= layer loop =================
#pragma unroll 1
    for (int l = 0; l < NL; l++) {
        __syncthreads();
        {
            // pure uint4 copies of pre-split weights
            const uint4* gih = (const uint4*)(g_ipwh + l * 8192);
            const uint4* gil = (const uint4*)(g_ipwl + l * 8192);
            for (int i = t; i < 2048; i += THREADS) {
                int row = i >> 6, c = (i & 63) << 2;
                *(uint4*)&s.ipwh[row * IPW_S + c] = gih[i];
                *(uint4*)&s.ipwl[row * IPW_S + c] = gil[i];
            }
            const uint4* goh = (const uint4*)(g_opwh + l * 4096);
            const uint4* gol = (const uint4*)(g_opwl + l * 4096);
            for (int i = t; i < 1024; i += THREADS) {
                int row = i >> 4, c = (i & 15) << 2;
                *(uint4*)&s.opwh[row * OPW_S + c] = goh[i];
                *(uint4*)&s.opwl[row * OPW_S + c] = gol[i];
            }
            for (int i = t; i < 4608; i += THREADS) {   // xpw[l][d][j]
                int d = i / 36, j = i - d * 36;
                float v = xpw_g[l * 4608 + i];
                if (j < 4) s.xpj[j * 132 + d] = v;
                else       s.xpwT[(j - 4) * XPW_S + d] = v;
            }
            s.dtw[t] = dtw_g[l * 512 + t];
            if (t < 128)      s.cw3[t] = cw_g[(l * 128 + t) * 4 + 3];
            else if (t < 256) s.cb[t - 128] = cb_g[l * 128 + (t - 128)];
            else if (t < 384) s.dtb[t - 256] = dtb_g[l * 128 + (t - 256)];
            else              s.dskip[t - 384] = dskip_g[l * 128 + (t - 384)];
            if (t < 64)       s.lng[t] = lng_g[l * 64 + t];
            else if (t < 128) s.lnb[t - 64] = lnb_g[l * 64 + (t - 64)];
        }
        __syncthreads();

        // ======== stage A: xz GEMM (bf16x3 mma); A fragments read pre-split ========
        {
            const int row0 = 16 * q + g, row8 = row0 + 8;
            const u32* xh0 = &s.xsh[row0 * XH_S];
            const u32* xh8 = &s.xsh[row8 * XH_S];
            const u32* xl0 = &s.xsl[row0 * XH_S];
            const u32* xl8 = &s.xsl[row8 * XH_S];
            float acc[8][4];
#pragma unroll
            for (int nt = 0; nt < 8; nt++)
#pragma unroll
                for (int i = 0; i < 4; i++) acc[nt][i] = 0.0f;
#pragma unroll
            for (int ks = 0; ks < 4; ks++) {
                const int kp = ks * 8 + cc;
                u32 ah[4], al[4];
                ah[0] = xh0[kp];     ah[1] = xh8[kp];
                ah[2] = xh0[kp + 4]; ah[3] = xh8[kp + 4];
                al[0] = xl0[kp];     al[1] = xl8[kp];
                al[2] = xl0[kp + 4]; al[3] = xl8[kp + 4];
                const u32* bh = &s.ipwh[kp * IPW_S + nc * 64 + g];
                const u32* bl = &s.ipwl[kp * IPW_S + nc * 64 + g];
#pragma unroll
                for (int nt = 0; nt < 8; nt++) {
                    u32 bh0 = bh[nt * 8], bh1 = bh[4 * IPW_S + nt * 8];
                    u32 bl0 = bl[nt * 8], bl1 = bl[4 * IPW_S + nt * 8];
                    mma_bf16(acc[nt], ah, bh0, bh1);
                    mma_bf16(acc[nt], ah, bl0, bl1);
                    mma_bf16(acc[nt], al, bh0, bh1);
                }
            }
            if (nc < 2) {        // xc half: conv tap + silu
#pragma unroll
                for (int nt = 0; nt < 8; nt++) {
                    int col = nc * 64 + nt * 8 + 2 * cc;
                    float2 cwv = *(const float2*)&s.cw3[col];
                    float2 cbv = *(const float2*)&s.cb[col];
                    *(float2*)&s.xc[row0 * XC_S + col] =
                        make_float2(siluf(fmaf(acc[nt][0], cwv.x, cbv.x)),
                                    siluf(fmaf(acc[nt][1], cwv.y, cbv.y)));
                    *(float2*)&s.xc[row8 * XC_S + col] =
                        make_float2(siluf(fmaf(acc[nt][2], cwv.x, cbv.x)),
                                    siluf(fmaf(acc[nt][3], cwv.y, cbv.y)));
                }
            } else {             // z half: silu
#pragma unroll
                for (int nt = 0; nt < 8; nt++) {
                    int col = (nc - 2) * 64 + nt * 8 + 2 * cc;
                    *(float2*)&s.sz[row0 * XC_S + col] =
                        make_float2(siluf(acc[nt][0]), siluf(acc[nt][1]));
                    *(float2*)&s.sz[row8 * XC_S + col] =
                        make_float2(siluf(acc[nt][2]), siluf(acc[nt][3]));
                }
            }
        }
        group_bar(q);

        // ======== stage B: dt/BC/y for rows rb4..rb4+3; y stored pre-split ========
        {
            float xcv[4][4];
#pragma unroll
            for (int j = 0; j < 4; j++) {
                float4 v = *(const float4*)&s.xc[(rb4 + j) * XC_S + 4 * lane];
                xcv[j][0] = v.x; xcv[j][1] = v.y; xcv[j][2] = v.z; xcv[j][3] = v.w;
            }
            float pr[4][4];
#pragma unroll
            for (int r = 0; r < 4; r++) {
                float4 wv = *(const float4*)&s.xpj[r * 132 + 4 * lane];
#pragma unroll
                for (int j = 0; j < 4; j++) {
                    float p = xcv[j][0] * wv.x + xcv[j][1] * wv.y
                            + xcv[j][2] * wv.z + xcv[j][3] * wv.w;
                    pr[r][j] = warp_sum(p);
                }
            }
            const float* wrow = &s.xpwT[lane * XPW_S];
            ull a01 = 0ULL, a23 = 0ULL;
#pragma unroll 4
            for (int d0 = 0; d0 < 128; d0 += 4) {
                float4 c0 = *(const float4*)&s.xc[(rb4 + 0) * XC_S + d0];
                float4 c1 = *(const float4*)&s.xc[(rb4 + 1) * XC_S + d0];
                float4 c2 = *(const float4*)&s.xc[(rb4 + 2) * XC_S + d0];
                float4 c3 = *(const float4*)&s.xc[(rb4 + 3) * XC_S + d0];
                float w0 = wrow[d0], w1 = wrow[d0 + 1], w2 = wrow[d0 + 2], w3 = wrow[d0 + 3];
                a01 = ffma2(pk2(c0.x, c1.x), pk2(w0, w0), a01);
                a23 = ffma2(pk2(c2.x, c3.x), pk2(w0, w0), a23);
                a01 = ffma2(pk2(c0.y, c1.y), pk2(w1, w1), a01);
                a23 = ffma2(pk2(c2.y, c3.y), pk2(w1, w1), a23);
                a01 = ffma2(pk2(c0.z, c1.z), pk2(w2, w2), a01);
                a23 = ffma2(pk2(c2.z, c3.z), pk2(w2, w2), a23);
                a01 = ffma2(pk2(c0.w, c1.w), pk2(w3, w3), a01);
                a23 = ffma2(pk2(c2.w, c3.w), pk2(w3, w3), a23);
            }
            float bc[4];
            upk2(a01, bc[0], bc[1]); upk2(a23, bc[2], bc[3]);
#pragma unroll
            for (int j = 0; j < 4; j++) {
                float other = __shfl_xor_sync(0xffffffffu, bc[j], 16);
                bc[j] = half_sum(bc[j] * other);
            }
            float dts[4][4];
            {
                float4 dtbv = *(const float4*)&s.dtb[4 * lane];
#pragma unroll
                for (int j = 0; j < 4; j++) {
                    dts[j][0] = dtbv.x; dts[j][1] = dtbv.y;
                    dts[j][2] = dtbv.z; dts[j][3] = dtbv.w;
                }
#pragma unroll
                for (int r = 0; r < 4; r++) {
                    float4 dwv = *(const float4*)&s.dtw[r * 128 + 4 * lane];
#pragma unroll
                    for (int j = 0; j < 4; j++) {
                        dts[j][0] = fmaf(pr[r][j], dwv.x, dts[j][0]);
                        dts[j][1] = fmaf(pr[r][j], dwv.y, dts[j][1]);
                        dts[j][2] = fmaf(pr[r][j], dwv.z, dts[j][2]);
                        dts[j][3] = fmaf(pr[r][j], dwv.w, dts[j][3]);
                    }
                }
#pragma unroll
                for (int j = 0; j < 4; j++) {
                    dts[j][0] = softplusf(dts[j][0]); dts[j][1] = softplusf(dts[j][1]);
                    dts[j][2] = softplusf(dts[j][2]); dts[j][3] = softplusf(dts[j][3]);
                }
            }
            __syncwarp();   // all lanes done reading xc rows before split-y overwrite
            {
                float4 dskv = *(const float4*)&s.dskip[4 * lane];
#pragma unroll
                for (int j = 0; j < 4; j++) {
                    float4 szv = *(const float4*)&s.sz[(rb4 + j) * XC_S + 4 * lane];
                    float4 yv;
                    yv.x = xcv[j][0] * fmaf(dts[j][0], bc[j], dskv.x) * szv.x;
                    yv.y = xcv[j][1] * fmaf(dts[j][1], bc[j], dskv.y) * szv.y;
                    yv.z = xcv[j][2] * fmaf(dts[j][2], bc[j], dskv.z) * szv.z;
                    yv.w = xcv[j][3] * fmaf(dts[j][3], bc[j], dskv.w) * szv.w;
                    u32 h0, l0, h1, l1;
                    bfsplit(make_float2(yv.x, yv.y), h0, l0);
                    bfsplit(make_float2(yv.z, yv.w), h1, l1);
                    u32* yr = (u32*)&s.xc[(rb4 + j) * XC_S];
                    *(uint2*)&yr[2 * lane]      = make_uint2(h0, h1);   // hi: cols 0..63
                    *(uint2*)&yr[64 + 2 * lane] = make_uint2(l0, l1);   // lo: cols 64..127
                }
            }
        }
        group_bar(q);

        // ======== stage C: out-proj GEMM (bf16x3 mma); A fragments pre-split ========
        {
            const int row0 = 16 * q + g, row8 = row0 + 8;
            const u32* yv = (const u32*)s.xc;
            const u32* yh0 = yv + row0 * XC_S;
            const u32* yh8 = yv + row8 * XC_S;
            float acc[2][4];
#pragma unroll
            for (int nt = 0; nt < 2; nt++)
#pragma unroll
                for (int i = 0; i < 4; i++) acc[nt][i] = 0.0f;
#pragma unroll
            for (int ks = 0; ks < 8; ks++) {
                const int kp = ks * 8 + cc;
                u32 ah[4], al[4];
                ah[0] = yh0[kp];          ah[1] = yh8[kp];
                ah[2] = yh0[kp + 4];      ah[3] = yh8[kp + 4];
                al[0] = yh0[64 + kp];     al[1] = yh8[64 + kp];
                al[2] = yh0[64 + kp + 4]; al[3] = yh8[64 + kp + 4];
                const u32* bh = &s.opwh[kp * OPW_S + nc * 16 + g];
                const u32* bl = &s.opwl[kp * OPW_S + nc * 16 + g];
#pragma unroll
                for (int nt = 0; nt < 2; nt++) {
                    u32 bh0 = bh[nt * 8], bh1 = bh[4 * OPW_S + nt * 8];
                    u32 bl0 = bl[nt * 8], bl1 = bl[4 * OPW_S + nt * 8];
                    mma_bf16(acc[nt], ah, bh0, bh1);
                    mma_bf16(acc[nt], ah, bl0, bl1);
                    mma_bf16(acc[nt], al, bh0, bh1);
                }
            }
#pragma unroll
            for (int nt = 0; nt < 2; nt++) {
                int col = nc * 16 + nt * 8 + 2 * cc;
                *(float2*)&s.sz[row0 * XC_S + col] = make_float2(acc[nt][0], acc[nt][1]);
                *(float2*)&s.sz[row8 * XC_S + col] = make_float2(acc[nt][2], acc[nt][3]);
            }
        }
        group_bar(q);

        // ======== stage D: layernorm(64) + residual; write fp32 + split ========
        {
            float2 gv = *(const float2*)&s.lng[2 * lane];
            float2 bv = *(const float2*)&s.lnb[2 * lane];
#pragma unroll
            for (int j = 0; j < 4; j++) {
                int row = rb4 + j;
                float2 ov = *(const float2*)&s.sz[row * XC_S + 2 * lane];
                float m  = warp_sum(ov.x + ov.y) * (1.0f / 64.0f);
                float m2 = warp_sum(ov.x * ov.x + ov.y * ov.y) * (1.0f / 64.0f);
                float rs = rsqrtf(m2 - m * m + EPSV);
                float2 xv = *(const float2*)&s.xs[row * XS_S + 2 * lane];
                xv.x += (ov.x - m) * rs * gv.x + bv.x;
                xv.y += (ov.y - m) * rs * gv.y + bv.y;
                *(float2*)&s.xs[row * XS_S + 2 * lane] = xv;
                u32 h, lo; bfsplit(xv, h, lo);
                s.xsh[row * XH_S + lane] = h;
                s.xsl[row * XH_S + lane] = lo;
            }
        }
    }

    // ================= head =================
    __syncthreads();
    {
        float* hs = s.xc;   // reuse as hw1[128][33]
        for (int i = t; i < 4096; i += THREADS) {
            int k = i >> 5, c = i & 31;
            hs[k * 33 + c] = hw1[i];
        }
        if (t < 32) { s.cw3[t] = hb1[t]; s.cb[t] = hw2[t]; }
        __syncthreads();

        float b2v = hb2[0];
#pragma unroll
        for (int j = 0; j < 2; j++) {
            int ra = 4 * w + 2 * j;
            float h = s.cw3[lane];
            const float* xa = &s.xs[ra * XS_S];
            const float* xb = &s.xs[(ra + 1) * XS_S];
#pragma unroll 8
            for (int k = 0; k < 64; k++) h = fmaf(xa[k], hs[k * 33 + lane], h);
#pragma unroll 8
            for (int k = 0; k < 64; k++) h = fmaf(xb[k], hs[(64 + k) * 33 + lane], h);
            h = fmaxf(h, 0.0f);
            float v = warp_sum(h * s.cb[lane]);
            if (lane == 0) out[blockIdx.x * EPB + 2 * w + j] = v + b2v;
        }
    }
}

extern "C" void kernel_launch(void* const* d_in, const int* in_sizes, int n_in,
                              void* d_out, int out_size) {
    const float* x        = (const float*)d_in[0];
    const float* w_nr     = (const float*)d_in[1];
    const float* b_nr     = (const float*)d_in[2];
    const float* w_r      = (const float*)d_in[3];
    const float* b_r      = (const float*)d_in[4];
    const float* w_in_nr  = (const float*)d_in[5];
    const float* b_in_nr  = (const float*)d_in[6];
    const float* w_in_r   = (const float*)d_in[7];
    const float* b_in_r   = (const float*)d_in[8];
    const float* ipw      = (const float*)d_in[9];
    const float* cw       = (const float*)d_in[10];
    const float* cb       = (const float*)d_in[11];
    const float* xpw      = (const float*)d_in[12];
    const float* dtw      = (const float*)d_in[13];
    const float* dtb      = (const float*)d_in[14];
    /* alog d_in[15] dead at L=1 (scan h0=0) */
    const float* dskip    = (const float*)d_in[16];
    const float* opw      = (const float*)d_in[17];
    const float* lng      = (const float*)d_in[18];
    const float* lnb      = (const float*)d_in[19];
    const float* hw1      = (const float*)d_in[20];
    const float* hb1      = (const float*)d_in[21];
    const float* hw2      = (const float*)d_in[22];
    const float* hb2      = (const float*)d_in[23];

    size_t smem = sizeof(Smem);
    cudaFuncSetAttribute((const void*)mamba_main,
                         cudaFuncAttributeMaxDynamicSharedMemorySize, (int)smem);

    prep_kernel<<<144, 256>>>(w_nr, b_nr, w_r, b_r, w_in_nr, b_in_nr, w_in_r, b_in_r);
    prep_split<<<96, 512>>>(ipw, opw);
    mamba_main<<<NBLK, THREADS, smem>>>(x, cw, cb, xpw, dtw, dtb, dskip,
                                        lng, lnb, hw1, hb1, hw2, hb2, (float*)d_out);
}

// round 8
// speedup vs baseline: 1.7056x; 1.0037x over previous
#include <cuda_runtime.h>

#define NL 4
#define BATCH 16384
#define THREADS 512
#define EPB 32
#define NBLK (BATCH / EPB)
#define XS_S 68          // xs row stride (floats)
#define XC_S 132         // xc/sz row stride (floats / u32)
#define XH_S 36          // split-xs row stride (u32)
#define XPW_S 129
#define IPW_S 264        // packed ipw kpair-row stride (u32)
#define OPW_S 72         // packed opw kpair-row stride (u32)
#define EPSV 1e-5f

typedef unsigned long long ull;
typedef unsigned int u32;

__device__ __forceinline__ ull pk2(float lo, float hi) {
    ull r; asm("mov.b64 %0,{%1,%2};" : "=l"(r) : "f"(lo), "f"(hi)); return r;
}
__device__ __forceinline__ void upk2(ull v, float& lo, float& hi) {
    asm("mov.b64 {%0,%1},%2;" : "=f"(lo), "=f"(hi) : "l"(v));
}
__device__ __forceinline__ ull ffma2(ull a, ull b, ull c) {
    ull d; asm("fma.rn.f32x2 %0,%1,%2,%3;" : "=l"(d) : "l"(a), "l"(b), "l"(c)); return d;
}
__device__ __forceinline__ float warp_sum(float v) {
    v += __shfl_xor_sync(0xffffffffu, v, 16);
    v += __shfl_xor_sync(0xffffffffu, v, 8);
    v += __shfl_xor_sync(0xffffffffu, v, 4);
    v += __shfl_xor_sync(0xffffffffu, v, 2);
    v += __shfl_xor_sync(0xffffffffu, v, 1);
    return v;
}
__device__ __forceinline__ float half_sum(float v) {
    v += __shfl_xor_sync(0xffffffffu, v, 8);
    v += __shfl_xor_sync(0xffffffffu, v, 4);
    v += __shfl_xor_sync(0xffffffffu, v, 2);
    v += __shfl_xor_sync(0xffffffffu, v, 1);
    return v;
}
__device__ __forceinline__ void group_bar(int q) {
    asm volatile("bar.sync %0, 128;" :: "r"(q + 1) : "memory");
}
__device__ __forceinline__ float siluf(float v) {
    return __fdividef(v, 1.0f + __expf(-v));
}
__device__ __forceinline__ float softplusf(float v) {
    return fmaxf(v, 0.0f) + __logf(1.0f + __expf(-fabsf(v)));
}
// split two fp32 (p.x = even k, p.y = odd k) into packed bf16x2 hi + lo
__device__ __forceinline__ void bfsplit(float2 p, u32& h, u32& l) {
    asm("cvt.rn.satfinite.bf16x2.f32 %0,%1,%2;" : "=r"(h) : "f"(p.y), "f"(p.x));
    float h0 = __uint_as_float(h << 16);
    float h1 = __uint_as_float(h & 0xffff0000u);
    asm("cvt.rn.satfinite.bf16x2.f32 %0,%1,%2;" : "=r"(l) : "f"(p.y - h1), "f"(p.x - h0));
}
__device__ __forceinline__ void mma_bf16(float* c, const u32* a, u32 b0, u32 b1) {
    asm("mma.sync.aligned.m16n8k16.row.col.f32.bf16.bf16.f32 "
        "{%0,%1,%2,%3},{%4,%5,%6,%7},{%8,%9},{%0,%1,%2,%3};"
        : "+f"(c[0]), "+f"(c[1]), "+f"(c[2]), "+f"(c[3])
        : "r"(a[0]), "r"(a[1]), "r"(a[2]), "r"(a[3]), "r"(b0), "r"(b1));
}

// ---------- per-layer weight blob: byte layout == SMEM layout ----------
struct __align__(16) LayerBlob {
    u32 ipwh[32 * IPW_S];     // 8448
    u32 ipwl[32 * IPW_S];     // 8448
    u32 opwh[64 * OPW_S];     // 4608
    u32 opwl[64 * OPW_S];     // 4608
    float xpwT[32 * XPW_S];   // 4128 (orig xpw rows 4..35, transposed)
    float xpj[4 * 132];       // 528  (dt-proj rows 0..3)
    float dtw[4 * 128];       // 512
    float cw3[128];
    float cb[128];
    float dtb[128];
    float dskip[128];
    float lng[64];
    float lnb[64];
};   // 127,680 B; /16 = 7980

#define BLOB_V4 (sizeof(LayerBlob) / 16)

__device__ LayerBlob g_blob[NL];
__device__ float g_Wnr[12 * 64];
__device__ float g_bnr[64];
__device__ float g_Wr[4 * 64];
__device__ float g_br[64];

// ---- fold kernel: coalesced; block j = output row (0..17), 256 thr = 4 cgrp x 64 o ----
__global__ void __launch_bounds__(256)
prep_fold(const float* __restrict__ w_nr, const float* __restrict__ b_nr,
          const float* __restrict__ w_r,  const float* __restrict__ b_r,
          const float* __restrict__ w_in_nr, const float* __restrict__ b_in_nr,
          const float* __restrict__ w_in_r,  const float* __restrict__ b_in_r) {
    __shared__ float red[4][64];
    const int j = blockIdx.x;          // 0..17
    const int o = threadIdx.x & 63;
    const int cg = threadIdx.x >> 6;
    const float* vec;
    const float* mat;
    if (j < 12)       { vec = w_nr + j * 1000;        mat = w_in_nr; }
    else if (j == 12) { vec = b_nr;                   mat = w_in_nr; }
    else if (j < 17)  { vec = w_r + (j - 13) * 1000;  mat = w_in_r;  }
    else              { vec = b_r;                    mat = w_in_r;  }
    float a0 = 0.f, a1 = 0.f;
    for (int c = cg * 2; c < 1000; c += 8) {          // 125 iters, 2-deep MLP
        a0 = fmaf(vec[c],     mat[c * 64 + o],       a0);
        a1 = fmaf(vec[c + 1], mat[(c + 1) * 64 + o], a1);
    }
    red[cg][o] = a0 + a1;
    __syncthreads();
    if (cg == 0) {
        float a = (red[0][o] + red[1][o]) + (red[2][o] + red[3][o]);
        if (j < 12)       g_Wnr[j * 64 + o] = a;
        else if (j == 12) g_bnr[o] = a + b_in_nr[o];
        else if (j < 17)  g_Wr[(j - 13) * 64 + o] = a;
        else              g_br[o] = a + b_in_r[o];
    }
}

// ---- blob prep: split ipw/opw, transpose xpw, gather the rest ----
#define B0 (NL * 8192)
#define B1 (B0 + NL * 4096)
#define B2 (B1 + NL * 4608)
#define B3 (B2 + NL * 512)
#define B4 (B3 + NL * 128)
#define B5 (B4 + NL * 128)
#define B6 (B5 + NL * 128)
#define B7 (B6 + NL * 128)
#define B8 (B7 + NL * 64)
#define B9 (B8 + NL * 64)

__global__ void __launch_bounds__(512)
prep_blob(const float* __restrict__ ipw, const float* __restrict__ opw,
          const float* __restrict__ xpw, const float* __restrict__ dtw,
          const float* __restrict__ cw,  const float* __restrict__ cb,
          const float* __restrict__ dtb, const float* __restrict__ dskip,
          const float* __restrict__ lng, const float* __restrict__ lnb) {
    int idx = blockIdx.x * 512 + threadIdx.x;
    if (idx < B0) {
        int l = idx >> 13, r = idx & 8191, kp = r >> 8, n = r & 255;
        const float* src = ipw + l * 16384 + kp * 512 + n;
        u32 h, lo; bfsplit(make_float2(src[0], src[256]), h, lo);
        g_blob[l].ipwh[kp * IPW_S + n] = h;
        g_blob[l].ipwl[kp * IPW_S + n] = lo;
    } else if (idx < B1) {
        int j = idx - B0, l = j >> 12, r = j & 4095, kp = r >> 6, n = r & 63;
        const float* src = opw + l * 8192 + kp * 128 + n;
        u32 h, lo; bfsplit(make_float2(src[0], src[64]), h, lo);
        g_blob[l].opwh[kp * OPW_S + n] = h;
        g_blob[l].opwl[kp * OPW_S + n] = lo;
    } else if (idx < B2) {
        int j = idx - B1, l = j / 4608, r = j - l * 4608;
        int d = r / 36, jj = r - d * 36;
        float v = xpw[l * 4608 + r];
        if (jj < 4) g_blob[l].xpj[jj * 132 + d] = v;
        else        g_blob[l].xpwT[(jj - 4) * XPW_S + d] = v;
    } else if (idx < B3) {
        int j = idx - B2, l = j >> 9, r = j & 511;
        g_blob[l].dtw[r] = dtw[l * 512 + r];
    } else if (idx < B4) {
        int j = idx - B3, l = j >> 7, r = j & 127;
        g_blob[l].cw3[r] = cw[(l * 128 + r) * 4 + 3];
    } else if (idx < B5) {
        int j = idx - B4, l = j >> 7, r = j & 127;
        g_blob[l].cb[r] = cb[l * 128 + r];
    } else if (idx < B6) {
        int j = idx - B5, l = j >> 7, r = j & 127;
        g_blob[l].dtb[r] = dtb[l * 128 + r];
    } else if (idx < B7) {
        int j = idx - B6, l = j >> 7, r = j & 127;
        g_blob[l].dskip[r] = dskip[l * 128 + r];
    } else if (idx < B8) {
        int j = idx - B7, l = j >> 6, r = j & 63;
        g_blob[l].lng[r] = lng[l * 64 + r];
    } else if (idx < B9) {
        int j = idx - B8, l = j >> 6, r = j & 63;
        g_blob[l].lnb[r] = lnb[l * 64 + r];
    }
}

// ---------------- shared memory (231,104 B; 1 block/SM) ----------------
struct __align__(16) Smem {
    LayerBlob blob;
    u32 xsh[64 * XH_S];       // split residual (hi), mma-A kpair layout
    u32 xsl[64 * XH_S];       // (lo)
    float xs[64 * XS_S];      // residual stream fp32
    float xc[64 * XC_S];      // xc fp32 -> split y; init Wnr stage; head hw1
    float sz[64 * XC_S];      // silu(z), then O
};

__global__ void __launch_bounds__(THREADS, 1)
mamba_main(const float* __restrict__ xin,
           const float* __restrict__ hw1, const float* __restrict__ hb1,
           const float* __restrict__ hw2, const float* __restrict__ hb2,
           float* __restrict__ out) {
    extern __shared__ __align__(16) char smem_raw[];
    Smem& s = *reinterpret_cast<Smem*>(smem_raw);

    const int t = threadIdx.x;
    const int w = t >> 5;
    const int lane = t & 31;
    const int q = w & 3;          // m-tile / barrier group
    const int nc = w >> 2;        // n-chunk
    const int g = lane >> 2;      // mma group row
    const int cc = lane & 3;      // mma thread-in-group
    const int rb4 = 16 * q + 4 * nc;

    // ---- stage folded input-proj weights (union'd into xc region) ----
    float* Wnr_s = s.xc;
    float* Wr_s  = s.xc + 768;
    float* bnr_s = s.xc + 1024;
    float* br_s  = s.xc + 1088;
    for (int i = t; i < 768; i += THREADS) Wnr_s[i] = g_Wnr[i];
    if (t < 256)      Wr_s[t] = g_Wr[t];
    else if (t < 320) bnr_s[t - 256] = g_bnr[t - 256];
    else if (t < 384) br_s[t - 320] = g_br[t - 320];
    __syncthreads();

    // ---- x0 = feat @ W_eff + b_eff : warp w -> rows 4w..4w+3; write fp32 + split ----
    {
        const int e0 = blockIdx.x * EPB + 2 * w;
        float fe[2][16];
#pragma unroll
        for (int e = 0; e < 2; e++) {
            const float4* xp = (const float4*)(xin + (size_t)(e0 + e) * 16);
#pragma unroll
            for (int qq = 0; qq < 4; qq++) {
                float4 v = xp[qq];
                fe[e][4 * qq + 0] = v.x; fe[e][4 * qq + 1] = v.y;
                fe[e][4 * qq + 2] = v.z; fe[e][4 * qq + 3] = v.w;
            }
        }
        float2 bn = *(const float2*)&bnr_s[2 * lane];
        float2 bb = *(const float2*)&br_s[2 * lane];
        ull a0 = pk2(bn.x, bn.y), a2 = a0;
        ull a1 = pk2(bb.x, bb.y), a3 = a1;
#pragma unroll
        for (int f = 0; f < 12; f++) {
            ull wp = *(const ull*)&Wnr_s[f * 64 + 2 * lane];
            a0 = ffma2(wp, pk2(fe[0][f], fe[0][f]), a0);
            a2 = ffma2(wp, pk2(fe[1][f], fe[1][f]), a2);
        }
#pragma unroll
        for (int f = 0; f < 4; f++) {
            ull wp = *(const ull*)&Wr_s[f * 64 + 2 * lane];
            a1 = ffma2(wp, pk2(fe[0][12 + f], fe[0][12 + f]), a1);
            a3 = ffma2(wp, pk2(fe[1][12 + f], fe[1][12 + f]), a3);
        }
        ull accs[4] = {a0, a1, a2, a3};
#pragma unroll
        for (int j = 0; j < 4; j++) {
            float v0, v1; upk2(accs[j], v0, v1);
            int row = 4 * w + j;
            *(float2*)&s.xs[row * XS_S + 2 * lane] = make_float2(v0, v1);
            u32 h, lo; bfsplit(make_float2(v0, v1), h, lo);
            s.xsh[row * XH_S + lane] = h;
            s.xsl[row * XH_S + lane] = lo;
        }
    }

    // ================= layer loop =================
#pragma unroll 1
    for (int l = 0; l < NL; l++) {
        __syncthreads();
        {   // flat vectorized blob copy (layout-identical)
            const uint4* src = (const uint4*)&g_blob[l];
            uint4* dst = (uint4*)&s.blob;
            for (int i = t; i < BLOB_V4; i += THREADS) dst[i] = src[i];
        }
        __syncthreads();

        // ======== stage A: xz GEMM (bf16x3 mma); A fragments pre-split ========
        {
            const int row0 = 16 * q + g, row8 = row0 + 8;
            const u32* xh0 = &s.xsh[row0 * XH_S];
            const u32* xh8 = &s.xsh[row8 * XH_S];
            const u32* xl0 = &s.xsl[row0 * XH_S];
            const u32* xl8 = &s.xsl[row8 * XH_S];
            float acc[8][4];
#pragma unroll
            for (int nt = 0; nt < 8; nt++)
#pragma unroll
                for (int i = 0; i < 4; i++) acc[nt][i] = 0.0f;
#pragma unroll
            for (int ks = 0; ks < 4; ks++) {
                const int kp = ks * 8 + cc;
                u32 ah[4], al[4];
                ah[0] = xh0[kp];     ah[1] = xh8[kp];
                ah[2] = xh0[kp + 4]; ah[3] = xh8[kp + 4];
                al[0] = xl0[kp];     al[1] = xl8[kp];
                al[2] = xl0[kp + 4]; al[3] = xl8[kp + 4];
                const u32* bh = &s.blob.ipwh[kp * IPW_S + nc * 64 + g];
                const u32* bl = &s.blob.ipwl[kp * IPW_S + nc * 64 + g];
#pragma unroll
                for (int nt = 0; nt < 8; nt++) {
                    u32 bh0 = bh[nt * 8], bh1 = bh[4 * IPW_S + nt * 8];
                    u32 bl0 = bl[nt * 8], bl1 = bl[4 * IPW_S + nt * 8];
                    mma_bf16(acc[nt], ah, bh0, bh1);
                    mma_bf16(acc[nt], ah, bl0, bl1);
                    mma_bf16(acc[nt], al, bh0, bh1);
                }
            }
            if (nc < 2) {        // xc half: conv tap + silu
#pragma unroll
                for (int nt = 0; nt < 8; nt++) {
                    int col = nc * 64 + nt * 8 + 2 * cc;
                    float2 cwv = *(const float2*)&s.blob.cw3[col];
                    float2 cbv = *(const float2*)&s.blob.cb[col];
                    *(float2*)&s.xc[row0 * XC_S + col] =
                        make_float2(siluf(fmaf(acc[nt][0], cwv.x, cbv.x)),
                                    siluf(fmaf(acc[nt][1], cwv.y, cbv.y)));
                    *(float2*)&s.xc[row8 * XC_S + col] =
                        make_float2(siluf(fmaf(acc[nt][2], cwv.x, cbv.x)),
                                    siluf(fmaf(acc[nt][3], cwv.y, cbv.y)));
                }
            } else {             // z half: silu
#pragma unroll
                for (int nt = 0; nt < 8; nt++) {
                    int col = (nc - 2) * 64 + nt * 8 + 2 * cc;
                    *(float2*)&s.sz[row0 * XC_S + col] =
                        make_float2(siluf(acc[nt][0]), siluf(acc[nt][1]));
                    *(float2*)&s.sz[row8 * XC_S + col] =
                        make_float2(siluf(acc[nt][2]), siluf(acc[nt][3]));
                }
            }
        }
        group_bar(q);

        // ======== stage B: dt/BC/y for rows rb4..rb4+3; y stored pre-split ========
        {
            float xcv[4][4];
#pragma unroll
            for (int j = 0; j < 4; j++) {
                float4 v = *(const float4*)&s.xc[(rb4 + j) * XC_S + 4 * lane];
                xcv[j][0] = v.x; xcv[j][1] = v.y; xcv[j][2] = v.z; xcv[j][3] = v.w;
            }
            float pr[4][4];
#pragma unroll
            for (int r = 0; r < 4; r++) {
                float4 wv = *(const float4*)&s.blob.xpj[r * 132 + 4 * lane];
#pragma unroll
                for (int j = 0; j < 4; j++) {
                    float p = xcv[j][0] * wv.x + xcv[j][1] * wv.y
                            + xcv[j][2] * wv.z + xcv[j][3] * wv.w;
                    pr[r][j] = warp_sum(p);
                }
            }
            const float* wrow = &s.blob.xpwT[lane * XPW_S];
            ull a01 = 0ULL, a23 = 0ULL;
#pragma unroll 4
            for (int d0 = 0; d0 < 128; d0 += 4) {
                float4 c0 = *(const float4*)&s.xc[(rb4 + 0) * XC_S + d0];
                float4 c1 = *(const float4*)&s.xc[(rb4 + 1) * XC_S + d0];
                float4 c2 = *(const float4*)&s.xc[(rb4 + 2) * XC_S + d0];
                float4 c3 = *(const float4*)&s.xc[(rb4 + 3) * XC_S + d0];
                float w0 = wrow[d0], w1 = wrow[d0 + 1], w2 = wrow[d0 + 2], w3 = wrow[d0 + 3];
                a01 = ffma2(pk2(c0.x, c1.x), pk2(w0, w0), a01);
                a23 = ffma2(pk2(c2.x, c3.x), pk2(w0, w0), a23);
                a01 = ffma2(pk2(c0.y, c1.y), pk2(w1, w1), a01);
                a23 = ffma2(pk2(c2.y, c3.y), pk2(w1, w1), a23);
                a01 = ffma2(pk2(c0.z, c1.z), pk2(w2, w2), a01);
                a23 = ffma2(pk2(c2.z, c3.z), pk2(w2, w2), a23);
                a01 = ffma2(pk2(c0.w, c1.w), pk2(w3, w3), a01);
                a23 = ffma2(pk2(c2.w, c3.w), pk2(w3, w3), a23);
            }
            float bc[4];
            upk2(a01, bc[0], bc[1]); upk2(a23, bc[2], bc[3]);
#pragma unroll
            for (int j = 0; j < 4; j++) {
                float other = __shfl_xor_sync(0xffffffffu, bc[j], 16);
                bc[j] = half_sum(bc[j] * other);
            }
            float dts[4][4];
            {
                float4 dtbv = *(const float4*)&s.blob.dtb[4 * lane];
#pragma unroll
                for (int j = 0; j < 4; j++) {
                    dts[j][0] = dtbv.x; dts[j][1] = dtbv.y;
                    dts[j][2] = dtbv.z; dts[j][3] = dtbv.w;
                }
#pragma unroll
                for (int r = 0; r < 4; r++) {
                    float4 dwv = *(const float4*)&s.blob.dtw[r * 128 + 4 * lane];
#pragma unroll
                    for (int j = 0; j < 4; j++) {
                        dts[j][0] = fmaf(pr[r][j], dwv.x, dts[j][0]);
                        dts[j][1] = fmaf(pr[r][j], dwv.y, dts[j][1]);
                        dts[j][2] = fmaf(pr[r][j], dwv.z, dts[j][2]);
                        dts[j][3] = fmaf(pr[r][j], dwv.w, dts[j][3]);
                    }
                }
#pragma unroll
                for (int j = 0; j < 4; j++) {
                    dts[j][0] = softplusf(dts[j][0]); dts[j][1] = softplusf(dts[j][1]);
                    dts[j][2] = softplusf(dts[j][2]); dts[j][3] = softplusf(dts[j][3]);
                }
            }
            __syncwarp();   // all lanes done reading xc rows before split-y overwrite
            {
                float4 dskv = *(const float4*)&s.blob.dskip[4 * lane];
#pragma unroll
                for (int j = 0; j < 4; j++) {
                    float4 szv = *(const float4*)&s.sz[(rb4 + j) * XC_S + 4 * lane];
                    float4 yv;
                    yv.x = xcv[j][0] * fmaf(dts[j][0], bc[j], dskv.x) * szv.x;
                    yv.y = xcv[j][1] * fmaf(dts[j][1], bc[j], dskv.y) * szv.y;
                    yv.z = xcv[j][2] * fmaf(dts[j][2], bc[j], dskv.z) * szv.z;
                    yv.w = xcv[j][3] * fmaf(dts[j][3], bc[j], dskv.w) * szv.w;
                    u32 h0, l0, h1, l1;
                    bfsplit(make_float2(yv.x, yv.y), h0, l0);
                    bfsplit(make_float2(yv.z, yv.w), h1, l1);
                    u32* yr = (u32*)&s.xc[(rb4 + j) * XC_S];
                    *(uint2*)&yr[2 * lane]      = make_uint2(h0, h1);   // hi: cols 0..63
                    *(uint2*)&yr[64 + 2 * lane] = make_uint2(l0, l1);   // lo: cols 64..127
                }
            }
        }
        group_bar(q);

        // ======== stage C: out-proj GEMM (bf16x3 mma); A fragments pre-split ========
        {
            const int row0 = 16 * q + g, row8 = row0 + 8;
            const u32* yv = (const u32*)s.xc;
            const u32* yh0 = yv + row0 * XC_S;
            const u32* yh8 = yv + row8 * XC_S;
            float acc[2][4];
#pragma unroll
            for (int nt = 0; nt < 2; nt++)
#pragma unroll
                for (int i = 0; i < 4; i++) acc[nt][i] = 0.0f;
#pragma unroll
            for (int ks = 0; ks < 8; ks++) {
                const int kp = ks * 8 + cc;
                u32 ah[4], al[4];
                ah[0] = yh0[kp];          ah[1] = yh8[kp];
                ah[2] = yh0[kp + 4];      ah[3] = yh8[kp + 4];
                al[0] = yh0[64 + kp];     al[1] = yh8[64 + kp];
                al[2] = yh0[64 + kp + 4]; al[3] = yh8[64 + kp + 4];
                const u32* bh = &s.blob.opwh[kp * OPW_S + nc * 16 + g];
                const u32* bl = &s.blob.opwl[kp * OPW_S + nc * 16 + g];
#pragma unroll
                for (int nt = 0; nt < 2; nt++) {
                    u32 bh0 = bh[nt * 8], bh1 = bh[4 * OPW_S + nt * 8];
                    u32 bl0 = bl[nt * 8], bl1 = bl[4 * OPW_S + nt * 8];
                    mma_bf16(acc[nt], ah, bh0, bh1);
                    mma_bf16(acc[nt], ah, bl0, bl1);
                    mma_bf16(acc[nt], al, bh0, bh1);
                }
            }
#pragma unroll
            for (int nt = 0; nt < 2; nt++) {
                int col = nc * 16 + nt * 8 + 2 * cc;
                *(float2*)&s.sz[row0 * XC_S + col] = make_float2(acc[nt][0], acc[nt][1]);
                *(float2*)&s.sz[row8 * XC_S + col] = make_float2(acc[nt][2], acc[nt][3]);
            }
        }
        group_bar(q);

        // ======== stage D: layernorm(64) + residual; write fp32 + split ========
        {
            float2 gv = *(const float2*)&s.blob.lng[2 * lane];
            float2 bv = *(const float2*)&s.blob.lnb[2 * lane];
#pragma unroll
            for (int j = 0; j < 4; j++) {
                int row = rb4 + j;
                float2 ov = *(const float2*)&s.sz[row * XC_S + 2 * lane];
                float m  = warp_sum(ov.x + ov.y) * (1.0f / 64.0f);
                float m2 = warp_sum(ov.x * ov.x + ov.y * ov.y) * (1.0f / 64.0f);
                float rs = rsqrtf(m2 - m * m + EPSV);
                float2 xv = *(const float2*)&s.xs[row * XS_S + 2 * lane];
                xv.x += (ov.x - m) * rs * gv.x + bv.x;
                xv.y += (ov.y - m) * rs * gv.y + bv.y;
                *(float2*)&s.xs[row * XS_S + 2 * lane] = xv;
                u32 h, lo; bfsplit(xv, h, lo);
                s.xsh[row * XH_S + lane] = h;
                s.xsl[row * XH_S + lane] = lo;
            }
        }
    }

    // ================= head =================
    __syncthreads();
    {
        float* hs = s.xc;   // reuse as hw1[128][33]
        for (int i = t; i < 4096; i += THREADS) {
            int k = i >> 5, c = i & 31;
            hs[k * 33 + c] = hw1[i];
        }
        float* hb1s = s.sz;
        float* hw2s = s.sz + 64;
        if (t < 32) { hb1s[t] = hb1[t]; hw2s[t] = hw2[t]; }
        __syncthreads();

        float b2v = hb2[0];
#pragma unroll
        for (int j = 0; j < 2; j++) {
            int ra = 4 * w + 2 * j;
            float h = hb1s[lane];
            const float* xa = &s.xs[ra * XS_S];
            const float* xb = &s.xs[(ra + 1) * XS_S];
#pragma unroll 8
            for (int k = 0; k < 64; k++) h = fmaf(xa[k], hs[k * 33 + lane], h);
#pragma unroll 8
            for (int k = 0; k < 64; k++) h = fmaf(xb[k], hs[(64 + k) * 33 + lane], h);
            h = fmaxf(h, 0.0f);
            float v = warp_sum(h * hw2s[lane]);
            if (lane == 0) out[blockIdx.x * EPB + 2 * w + j] = v + b2v;
        }
    }
}

extern "C" void kernel_launch(void* const* d_in, const int* in_sizes, int n_in,
                              void* d_out, int out_size) {
    const float* x        = (const float*)d_in[0];
    const float* w_nr     = (const float*)d_in[1];
    const float* b_nr     = (const float*)d_in[2];
    const float* w_r      = (const float*)d_in[3];
    const float* b_r      = (const float*)d_in[4];
    const float* w_in_nr  = (const float*)d_in[5];
    const float* b_in_nr  = (const float*)d_in[6];
    const float* w_in_r   = (const float*)d_in[7];
    const float* b_in_r   = (const float*)d_in[8];
    const float* ipw      = (const float*)d_in[9];
    const float* cw       = (const float*)d_in[10];
    const float* cb       = (const float*)d_in[11];
    const float* xpw      = (const float*)d_in[12];
    const float* dtw      = (const float*)d_in[13];
    const float* dtb      = (const float*)d_in[14];
    /* alog d_in[15] dead at L=1 (scan h0=0) */
    const float* dskip    = (const float*)d_in[16];
    const float* opw      = (const float*)d_in[17];
    const float* lng      = (const float*)d_in[18];
    const float* lnb      = (const float*)d_in[19];
    const float* hw1      = (const float*)d_in[20];
    const float* hb1      = (const float*)d_in[21];
    const float* hw2      = (const float*)d_in[22];
    const float* hb2      = (const float*)d_in[23];

    size_t smem = sizeof(Smem);
    cudaFuncSetAttribute((const void*)mamba_main,
                         cudaFuncAttributeMaxDynamicSharedMemorySize, (int)smem);

    prep_fold<<<18, 256>>>(w_nr, b_nr, w_r, b_r, w_in_nr, b_in_nr, w_in_r, b_in_r);
    prep_blob<<<(B9 + 511) / 512, 512>>>(ipw, opw, xpw, dtw, cw, cb, dtb, dskip, lng, lnb);
    mamba_main<<<NBLK, THREADS, smem>>>(x, hw1, hb1, hw2, hb2, (float*)d_out);
}

// round 9
// speedup vs baseline: 1.8304x; 1.0732x over previous
#include <cuda_runtime.h>

#define NL 4
#define BATCH 16384
#define THREADS 512
#define EPB 32
#define NBLK (BATCH / EPB)
#define XS_S 68          // xs row stride (floats)
#define XC_S 132         // xc/sz row stride (floats / u32)
#define XH_S 36          // split-xs row stride (u32)
#define XPW_S 129
#define IPW_S 264        // packed ipw kpair-row stride (u32)
#define OPW_S 72         // packed opw kpair-row stride (u32)
#define EPSV 1e-5f

typedef unsigned long long ull;
typedef unsigned int u32;

__device__ __forceinline__ ull pk2(float lo, float hi) {
    ull r; asm("mov.b64 %0,{%1,%2};" : "=l"(r) : "f"(lo), "f"(hi)); return r;
}
__device__ __forceinline__ void upk2(ull v, float& lo, float& hi) {
    asm("mov.b64 {%0,%1},%2;" : "=f"(lo), "=f"(hi) : "l"(v));
}
__device__ __forceinline__ ull ffma2(ull a, ull b, ull c) {
    ull d; asm("fma.rn.f32x2 %0,%1,%2,%3;" : "=l"(d) : "l"(a), "l"(b), "l"(c)); return d;
}
__device__ __forceinline__ float warp_sum(float v) {
    v += __shfl_xor_sync(0xffffffffu, v, 16);
    v += __shfl_xor_sync(0xffffffffu, v, 8);
    v += __shfl_xor_sync(0xffffffffu, v, 4);
    v += __shfl_xor_sync(0xffffffffu, v, 2);
    v += __shfl_xor_sync(0xffffffffu, v, 1);
    return v;
}
__device__ __forceinline__ float half_sum(float v) {
    v += __shfl_xor_sync(0xffffffffu, v, 8);
    v += __shfl_xor_sync(0xffffffffu, v, 4);
    v += __shfl_xor_sync(0xffffffffu, v, 2);
    v += __shfl_xor_sync(0xffffffffu, v, 1);
    return v;
}
__device__ __forceinline__ void group_bar(int q) {
    asm volatile("bar.sync %0, 128;" :: "r"(q + 1) : "memory");
}
__device__ __forceinline__ float siluf(float v) {
    return __fdividef(v, 1.0f + __expf(-v));
}
__device__ __forceinline__ float softplusf(float v) {
    return fmaxf(v, 0.0f) + __logf(1.0f + __expf(-fabsf(v)));
}
// split two fp32 (p.x = even k, p.y = odd k) into packed bf16x2 hi + lo
__device__ __forceinline__ void bfsplit(float2 p, u32& h, u32& l) {
    asm("cvt.rn.satfinite.bf16x2.f32 %0,%1,%2;" : "=r"(h) : "f"(p.y), "f"(p.x));
    float h0 = __uint_as_float(h << 16);
    float h1 = __uint_as_float(h & 0xffff0000u);
    asm("cvt.rn.satfinite.bf16x2.f32 %0,%1,%2;" : "=r"(l) : "f"(p.y - h1), "f"(p.x - h0));
}
__device__ __forceinline__ void mma_bf16(float* c, const u32* a, u32 b0, u32 b1) {
    asm("mma.sync.aligned.m16n8k16.row.col.f32.bf16.bf16.f32 "
        "{%0,%1,%2,%3},{%4,%5,%6,%7},{%8,%9},{%0,%1,%2,%3};"
        : "+f"(c[0]), "+f"(c[1]), "+f"(c[2]), "+f"(c[3])
        : "r"(a[0]), "r"(a[1]), "r"(a[2]), "r"(a[3]), "r"(b0), "r"(b1));
}

// ---------- per-layer weight blob: byte layout == SMEM layout ----------
struct __align__(16) LayerBlob {
    u32 ipwh[32 * IPW_S];     // 8448
    u32 ipwl[32 * IPW_S];     // 8448
    u32 opwh[64 * OPW_S];     // 4608
    u32 opwl[64 * OPW_S];     // 4608
    float xpwT[32 * XPW_S];   // 4128 (orig xpw rows 4..35, transposed)
    float xpj[4 * 132];       // 528  (dt-proj rows 0..3)
    float dtw[4 * 128];       // 512
    float cw3[128];
    float cb[128];
    float dtb[128];
    float dskip[128];
    float lng[64];
    float lnb[64];
};   // 127,680 B; /16 = 7980

#define BLOB_V4 (sizeof(LayerBlob) / 16)

__device__ LayerBlob g_blob[NL];
__device__ float g_fold_part[18 * 8 * 64];
__device__ float g_Wnr[12 * 64];
__device__ float g_bnr[64];
__device__ float g_Wr[4 * 64];
__device__ float g_br[64];

// ---- fold kernel: 144 blocks = 18 outputs x 8 c-chunks; partial sums only ----
__global__ void __launch_bounds__(256)
prep_fold(const float* __restrict__ w_nr, const float* __restrict__ b_nr,
          const float* __restrict__ w_r,  const float* __restrict__ b_r,
          const float* __restrict__ w_in_nr, const float* __restrict__ w_in_r) {
    __shared__ float red[4][64];
    const int j = blockIdx.x >> 3;         // 0..17
    const int chunk = blockIdx.x & 7;      // 0..7
    const int o = threadIdx.x & 63;
    const int cg = threadIdx.x >> 6;
    const float* vec;
    const float* mat;
    if (j < 12)       { vec = w_nr + j * 1000;        mat = w_in_nr; }
    else if (j == 12) { vec = b_nr;                   mat = w_in_nr; }
    else if (j < 17)  { vec = w_r + (j - 13) * 1000;  mat = w_in_r;  }
    else              { vec = b_r;                    mat = w_in_r;  }
    const int cbase = chunk * 125;
    const int cend = cbase + 125;
    float a0 = 0.f, a1 = 0.f;
    for (int c = cbase + cg * 2; c < cend; c += 8) {
        a0 = fmaf(vec[c], mat[c * 64 + o], a0);
        if (c + 1 < cend)
            a1 = fmaf(vec[c + 1], mat[(c + 1) * 64 + o], a1);
    }
    red[cg][o] = a0 + a1;
    __syncthreads();
    if (cg == 0)
        g_fold_part[(j * 8 + chunk) * 64 + o] =
            (red[0][o] + red[1][o]) + (red[2][o] + red[3][o]);
}

// ---- blob prep: split ipw/opw, transpose xpw, gather rest, reduce fold partials ----
#define B0 (NL * 8192)
#define B1 (B0 + NL * 4096)
#define B2 (B1 + NL * 4608)
#define B3 (B2 + NL * 512)
#define B4 (B3 + NL * 128)
#define B5 (B4 + NL * 128)
#define B6 (B5 + NL * 128)
#define B7 (B6 + NL * 128)
#define B8 (B7 + NL * 64)
#define B9 (B8 + NL * 64)
#define B10 (B9 + 1152)

__global__ void __launch_bounds__(512)
prep_blob(const float* __restrict__ ipw, const float* __restrict__ opw,
          const float* __restrict__ xpw, const float* __restrict__ dtw,
          const float* __restrict__ cw,  const float* __restrict__ cb,
          const float* __restrict__ dtb, const float* __restrict__ dskip,
          const float* __restrict__ lng, const float* __restrict__ lnb,
          const float* __restrict__ b_in_nr, const float* __restrict__ b_in_r) {
    int idx = blockIdx.x * 512 + threadIdx.x;
    if (idx < B0) {
        int l = idx >> 13, r = idx & 8191, kp = r >> 8, n = r & 255;
        const float* src = ipw + l * 16384 + kp * 512 + n;
        u32 h, lo; bfsplit(make_float2(src[0], src[256]), h, lo);
        g_blob[l].ipwh[kp * IPW_S + n] = h;
        g_blob[l].ipwl[kp * IPW_S + n] = lo;
    } else if (idx < B1) {
        int j = idx - B0, l = j >> 12, r = j & 4095, kp = r >> 6, n = r & 63;
        const float* src = opw + l * 8192 + kp * 128 + n;
        u32 h, lo; bfsplit(make_float2(src[0], src[64]), h, lo);
        g_blob[l].opwh[kp * OPW_S + n] = h;
        g_blob[l].opwl[kp * OPW_S + n] = lo;
    } else if (idx < B2) {
        int j = idx - B1, l = j / 4608, r = j - l * 4608;
        int d = r / 36, jj = r - d * 36;
        float v = xpw[l * 4608 + r];
        if (jj < 4) g_blob[l].xpj[jj * 132 + d] = v;
        else        g_blob[l].xpwT[(jj - 4) * XPW_S + d] = v;
    } else if (idx < B3) {
        int j = idx - B2, l = j >> 9, r = j & 511;
        g_blob[l].dtw[r] = dtw[l * 512 + r];
    } else if (idx < B4) {
        int j = idx - B3, l = j >> 7, r = j & 127;
        g_blob[l].cw3[r] = cw[(l * 128 + r) * 4 + 3];
    } else if (idx < B5) {
        int j = idx - B4, l = j >> 7, r = j & 127;
        g_blob[l].cb[r] = cb[l * 128 + r];
    } else if (idx < B6) {
        int j = idx - B5, l = j >> 7, r = j & 127;
        g_blob[l].dtb[r] = dtb[l * 128 + r];
    } else if (idx < B7) {
        int j = idx - B6, l = j >> 7, r = j & 127;
        g_blob[l].dskip[r] = dskip[l * 128 + r];
    } else if (idx < B8) {
        int j = idx - B7, l = j >> 6, r = j & 63;
        g_blob[l].lng[r] = lng[l * 64 + r];
    } else if (idx < B9) {
        int j = idx - B8, l = j >> 6, r = j & 63;
        g_blob[l].lnb[r] = lnb[l * 64 + r];
    } else if (idx < B10) {
        int W = idx - B9;            // 0..1151
        int j = W >> 6, o = W & 63;
        const float* p = g_fold_part + j * 8 * 64 + o;
        float a = 0.0f;
#pragma unroll
        for (int k = 0; k < 8; k++) a += p[k * 64];
        if (j < 12)       g_Wnr[j * 64 + o] = a;
        else if (j == 12) g_bnr[o] = a + b_in_nr[o];
        else if (j < 17)  g_Wr[(j - 13) * 64 + o] = a;
        else              g_br[o] = a + b_in_r[o];
    }
}

// ---------------- shared memory (231,104 B; 1 block/SM) ----------------
struct __align__(16) Smem {
    LayerBlob blob;
    u32 xsh[64 * XH_S];       // split residual (hi), mma-A kpair layout
    u32 xsl[64 * XH_S];       // (lo)
    float xs[64 * XS_S];      // residual stream fp32
    float xc[64 * XC_S];      // xc fp32 -> split y; init Wnr stage; head hw1
    float sz[64 * XC_S];      // silu(z), then O
};

__global__ void __launch_bounds__(THREADS, 1)
mamba_main(const float* __restrict__ xin,
           const float* __restrict__ hw1, const float* __restrict__ hb1,
           const float* __restrict__ hw2, const float* __restrict__ hb2,
           float* __restrict__ out) {
    extern __shared__ __align__(16) char smem_raw[];
    Smem& s = *reinterpret_cast<Smem*>(smem_raw);

    const int t = threadIdx.x;
    const int w = t >> 5;
    const int lane = t & 31;
    const int q = w & 3;          // m-tile / barrier group
    const int nc = w >> 2;        // n-chunk
    const int g = lane >> 2;      // mma group row
    const int cc = lane & 3;      // mma thread-in-group
    const int rb4 = 16 * q + 4 * nc;

    // ---- stage folded input-proj weights (union'd into xc region) ----
    float* Wnr_s = s.xc;
    float* Wr_s  = s.xc + 768;
    float* bnr_s = s.xc + 1024;
    float* br_s  = s.xc + 1088;
    for (int i = t; i < 768; i += THREADS) Wnr_s[i] = g_Wnr[i];
    if (t < 256)      Wr_s[t] = g_Wr[t];
    else if (t < 320) bnr_s[t - 256] = g_bnr[t - 256];
    else if (t < 384) br_s[t - 320] = g_br[t - 320];
    __syncthreads();

    // ---- x0 = feat @ W_eff + b_eff : warp w -> rows 4w..4w+3; write fp32 + split ----
    {
        const int e0 = blockIdx.x * EPB + 2 * w;
        float fe[2][16];
#pragma unroll
        for (int e = 0; e < 2; e++) {
            const float4* xp = (const float4*)(xin + (size_t)(e0 + e) * 16);
#pragma unroll
            for (int qq = 0; qq < 4; qq++) {
                float4 v = xp[qq];
                fe[e][4 * qq + 0] = v.x; fe[e][4 * qq + 1] = v.y;
                fe[e][4 * qq + 2] = v.z; fe[e][4 * qq + 3] = v.w;
            }
        }
        float2 bn = *(const float2*)&bnr_s[2 * lane];
        float2 bb = *(const float2*)&br_s[2 * lane];
        ull a0 = pk2(bn.x, bn.y), a2 = a0;
        ull a1 = pk2(bb.x, bb.y), a3 = a1;
#pragma unroll
        for (int f = 0; f < 12; f++) {
            ull wp = *(const ull*)&Wnr_s[f * 64 + 2 * lane];
            a0 = ffma2(wp, pk2(fe[0][f], fe[0][f]), a0);
            a2 = ffma2(wp, pk2(fe[1][f], fe[1][f]), a2);
        }
#pragma unroll
        for (int f = 0; f < 4; f++) {
            ull wp = *(const ull*)&Wr_s[f * 64 + 2 * lane];
            a1 = ffma2(wp, pk2(fe[0][12 + f], fe[0][12 + f]), a1);
            a3 = ffma2(wp, pk2(fe[1][12 + f], fe[1][12 + f]), a3);
        }
        ull accs[4] = {a0, a1, a2, a3};
#pragma unroll
        for (int j = 0; j < 4; j++) {
            float v0, v1; upk2(accs[j], v0, v1);
            int row = 4 * w + j;
            *(float2*)&s.xs[row * XS_S + 2 * lane] = make_float2(v0, v1);
            u32 h, lo; bfsplit(make_float2(v0, v1), h, lo);
            s.xsh[row * XH_S + lane] = h;
            s.xsl[row * XH_S + lane] = lo;
        }
    }

    // ================= layer loop =================
#pragma unroll 1
    for (int l = 0; l < NL; l++) {
        __syncthreads();
        {   // flat vectorized blob copy (layout-identical)
            const uint4* src = (const uint4*)&g_blob[l];
            uint4* dst = (uint4*)&s.blob;
            for (int i = t; i < BLOB_V4; i += THREADS) dst[i] = src[i];
        }
        __syncthreads();

        // ======== stage A: xz GEMM (bf16x3 mma); A fragments pre-split ========
        {
            const int row0 = 16 * q + g, row8 = row0 + 8;
            const u32* xh0 = &s.xsh[row0 * XH_S];
            const u32* xh8 = &s.xsh[row8 * XH_S];
            const u32* xl0 = &s.xsl[row0 * XH_S];
            const u32* xl8 = &s.xsl[row8 * XH_S];
            float acc[8][4];
#pragma unroll
            for (int nt = 0; nt < 8; nt++)
#pragma unroll
                for (int i = 0; i < 4; i++) acc[nt][i] = 0.0f;
#pragma unroll
            for (int ks = 0; ks < 4; ks++) {
                const int kp = ks * 8 + cc;
                u32 ah[4], al[4];
                ah[0] = xh0[kp];     ah[1] = xh8[kp];
                ah[2] = xh0[kp + 4]; ah[3] = xh8[kp + 4];
                al[0] = xl0[kp];     al[1] = xl8[kp];
                al[2] = xl0[kp + 4]; al[3] = xl8[kp + 4];
                const u32* bh = &s.blob.ipwh[kp * IPW_S + nc * 64 + g];
                const u32* bl = &s.blob.ipwl[kp * IPW_S + nc * 64 + g];
#pragma unroll
                for (int nt = 0; nt < 8; nt++) {
                    u32 bh0 = bh[nt * 8], bh1 = bh[4 * IPW_S + nt * 8];
                    u32 bl0 = bl[nt * 8], bl1 = bl[4 * IPW_S + nt * 8];
                    mma_bf16(acc[nt], ah, bh0, bh1);
                    mma_bf16(acc[nt], ah, bl0, bl1);
                    mma_bf16(acc[nt], al, bh0, bh1);
                }
            }
            if (nc < 2) {        // xc half: conv tap + silu
#pragma unroll
                for (int nt = 0; nt < 8; nt++) {
                    int col = nc * 64 + nt * 8 + 2 * cc;
                    float2 cwv = *(const float2*)&s.blob.cw3[col];
                    float2 cbv = *(const float2*)&s.blob.cb[col];
                    *(float2*)&s.xc[row0 * XC_S + col] =
                        make_float2(siluf(fmaf(acc[nt][0], cwv.x, cbv.x)),
                                    siluf(fmaf(acc[nt][1], cwv.y, cbv.y)));
                    *(float2*)&s.xc[row8 * XC_S + col] =
                        make_float2(siluf(fmaf(acc[nt][2], cwv.x, cbv.x)),
                                    siluf(fmaf(acc[nt][3], cwv.y, cbv.y)));
                }
            } else {             // z half: silu
#pragma unroll
                for (int nt = 0; nt < 8; nt++) {
                    int col = (nc - 2) * 64 + nt * 8 + 2 * cc;
                    *(float2*)&s.sz[row0 * XC_S + col] =
                        make_float2(siluf(acc[nt][0]), siluf(acc[nt][1]));
                    *(float2*)&s.sz[row8 * XC_S + col] =
                        make_float2(siluf(acc[nt][2]), siluf(acc[nt][3]));
                }
            }
        }
        group_bar(q);

        // ======== stage B: dt/BC/y for rows rb4..rb4+3; y stored pre-split ========
        {
            float xcv[4][4];
#pragma unroll
            for (int j = 0; j < 4; j++) {
                float4 v = *(const float4*)&s.xc[(rb4 + j) * XC_S + 4 * lane];
                xcv[j][0] = v.x; xcv[j][1] = v.y; xcv[j][2] = v.z; xcv[j][3] = v.w;
            }
            float pr[4][4];
#pragma unroll
            for (int r = 0; r < 4; r++) {
                float4 wv = *(const float4*)&s.blob.xpj[r * 132 + 4 * lane];
#pragma unroll
                for (int j = 0; j < 4; j++) {
                    float p = xcv[j][0] * wv.x + xcv[j][1] * wv.y
                            + xcv[j][2] * wv.z + xcv[j][3] * wv.w;
                    pr[r][j] = warp_sum(p);
                }
            }
            const float* wrow = &s.blob.xpwT[lane * XPW_S];
            ull a01 = 0ULL, a23 = 0ULL;
#pragma unroll 4
            for (int d0 = 0; d0 < 128; d0 += 4) {
                float4 c0 = *(const float4*)&s.xc[(rb4 + 0) * XC_S + d0];
                float4 c1 = *(const float4*)&s.xc[(rb4 + 1) * XC_S + d0];
                float4 c2 = *(const float4*)&s.xc[(rb4 + 2) * XC_S + d0];
                float4 c3 = *(const float4*)&s.xc[(rb4 + 3) * XC_S + d0];
                float w0 = wrow[d0], w1 = wrow[d0 + 1], w2 = wrow[d0 + 2], w3 = wrow[d0 + 3];
                a01 = ffma2(pk2(c0.x, c1.x), pk2(w0, w0), a01);
                a23 = ffma2(pk2(c2.x, c3.x), pk2(w0, w0), a23);
                a01 = ffma2(pk2(c0.y, c1.y), pk2(w1, w1), a01);
                a23 = ffma2(pk2(c2.y, c3.y), pk2(w1, w1), a23);
                a01 = ffma2(pk2(c0.z, c1.z), pk2(w2, w2), a01);
                a23 = ffma2(pk2(c2.z, c3.z), pk2(w2, w2), a23);
                a01 = ffma2(pk2(c0.w, c1.w), pk2(w3, w3), a01);
                a23 = ffma2(pk2(c2.w, c3.w), pk2(w3, w3), a23);
            }
            float bc[4];
            upk2(a01, bc[0], bc[1]); upk2(a23, bc[2], bc[3]);
#pragma unroll
            for (int j = 0; j < 4; j++) {
                float other = __shfl_xor_sync(0xffffffffu, bc[j], 16);
                bc[j] = half_sum(bc[j] * other);
            }
            float dts[4][4];
            {
                float4 dtbv = *(const float4*)&s.blob.dtb[4 * lane];
#pragma unroll
                for (int j = 0; j < 4; j++) {
                    dts[j][0] = dtbv.x; dts[j][1] = dtbv.y;
                    dts[j][2] = dtbv.z; dts[j][3] = dtbv.w;
                }
#pragma unroll
                for (int r = 0; r < 4; r++) {
                    float4 dwv = *(const float4*)&s.blob.dtw[r * 128 + 4 * lane];
#pragma unroll
                    for (int j = 0; j < 4; j++) {
                        dts[j][0] = fmaf(pr[r][j], dwv.x, dts[j][0]);
                        dts[j][1] = fmaf(pr[r][j], dwv.y, dts[j][1]);
                        dts[j][2] = fmaf(pr[r][j], dwv.z, dts[j][2]);
                        dts[j][3] = fmaf(pr[r][j], dwv.w, dts[j][3]);
                    }
                }
#pragma unroll
                for (int j = 0; j < 4; j++) {
                    dts[j][0] = softplusf(dts[j][0]); dts[j][1] = softplusf(dts[j][1]);
                    dts[j][2] = softplusf(dts[j][2]); dts[j][3] = softplusf(dts[j][3]);
                }
            }
            __syncwarp();   // all lanes done reading xc rows before split-y overwrite
            {
                float4 dskv = *(const float4*)&s.blob.dskip[4 * lane];
#pragma unroll
                for (int j = 0; j < 4; j++) {
                    float4 szv = *(const float4*)&s.sz[(rb4 + j) * XC_S + 4 * lane];
                    float4 yv;
                    yv.x = xcv[j][0] * fmaf(dts[j][0], bc[j], dskv.x) * szv.x;
                    yv.y = xcv[j][1] * fmaf(dts[j][1], bc[j], dskv.y) * szv.y;
                    yv.z = xcv[j][2] * fmaf(dts[j][2], bc[j], dskv.z) * szv.z;
                    yv.w = xcv[j][3] * fmaf(dts[j][3], bc[j], dskv.w) * szv.w;
                    u32 h0, l0, h1, l1;
                    bfsplit(make_float2(yv.x, yv.y), h0, l0);
                    bfsplit(make_float2(yv.z, yv.w), h1, l1);
                    u32* yr = (u32*)&s.xc[(rb4 + j) * XC_S];
                    *(uint2*)&yr[2 * lane]      = make_uint2(h0, h1);   // hi: cols 0..63
                    *(uint2*)&yr[64 + 2 * lane] = make_uint2(l0, l1);   // lo: cols 64..127
                }
            }
        }
        group_bar(q);

        // ======== stage C: out-proj GEMM (bf16x3 mma); A fragments pre-split ========
        {
            const int row0 = 16 * q + g, row8 = row0 + 8;
            const u32* yv = (const u32*)s.xc;
            const u32* yh0 = yv + row0 * XC_S;
            const u32* yh8 = yv + row8 * XC_S;
            float acc[2][4];
#pragma unroll
            for (int nt = 0; nt < 2; nt++)
#pragma unroll
                for (int i = 0; i < 4; i++) acc[nt][i] = 0.0f;
#pragma unroll
            for (int ks = 0; ks < 8; ks++) {
                const int kp = ks * 8 + cc;
                u32 ah[4], al[4];
                ah[0] = yh0[kp];          ah[1] = yh8[kp];
                ah[2] = yh0[kp + 4];      ah[3] = yh8[kp + 4];
                al[0] = yh0[64 + kp];     al[1] = yh8[64 + kp];
                al[2] = yh0[64 + kp + 4]; al[3] = yh8[64 + kp + 4];
                const u32* bh = &s.blob.opwh[kp * OPW_S + nc * 16 + g];
                const u32* bl = &s.blob.opwl[kp * OPW_S + nc * 16 + g];
#pragma unroll
                for (int nt = 0; nt < 2; nt++) {
                    u32 bh0 = bh[nt * 8], bh1 = bh[4 * OPW_S + nt * 8];
                    u32 bl0 = bl[nt * 8], bl1 = bl[4 * OPW_S + nt * 8];
                    mma_bf16(acc[nt], ah, bh0, bh1);
                    mma_bf16(acc[nt], ah, bl0, bl1);
                    mma_bf16(acc[nt], al, bh0, bh1);
                }
            }
#pragma unroll
            for (int nt = 0; nt < 2; nt++) {
                int col = nc * 16 + nt * 8 + 2 * cc;
                *(float2*)&s.sz[row0 * XC_S + col] = make_float2(acc[nt][0], acc[nt][1]);
                *(float2*)&s.sz[row8 * XC_S + col] = make_float2(acc[nt][2], acc[nt][3]);
            }
        }
        group_bar(q);

        // ======== stage D: layernorm(64) + residual; write fp32 + split ========
        {
            float2 gv = *(const float2*)&s.blob.lng[2 * lane];
            float2 bv = *(const float2*)&s.blob.lnb[2 * lane];
#pragma unroll
            for (int j = 0; j < 4; j++) {
                int row = rb4 + j;
                float2 ov = *(const float2*)&s.sz[row * XC_S + 2 * lane];
                float m  = warp_sum(ov.x + ov.y) * (1.0f / 64.0f);
                float m2 = warp_sum(ov.x * ov.x + ov.y * ov.y) * (1.0f / 64.0f);
                float rs = rsqrtf(m2 - m * m + EPSV);
                float2 xv = *(const float2*)&s.xs[row * XS_S + 2 * lane];
                xv.x += (ov.x - m) * rs * gv.x + bv.x;
                xv.y += (ov.y - m) * rs * gv.y + bv.y;
                *(float2*)&s.xs[row * XS_S + 2 * lane] = xv;
                u32 h, lo; bfsplit(xv, h, lo);
                s.xsh[row * XH_S + lane] = h;
                s.xsl[row * XH_S + lane] = lo;
            }
        }
    }

    // ================= head =================
    __syncthreads();
    {
        float* hs = s.xc;   // reuse as hw1[128][33]
        for (int i = t; i < 4096; i += THREADS) {
            int k = i >> 5, c = i & 31;
            hs[k * 33 + c] = hw1[i];
        }
        float* hb1s = s.sz;
        float* hw2s = s.sz + 64;
        if (t < 32) { hb1s[t] = hb1[t]; hw2s[t] = hw2[t]; }
        __syncthreads();

        float b2v = hb2[0];
#pragma unroll
        for (int j = 0; j < 2; j++) {
            int ra = 4 * w + 2 * j;
            float h = hb1s[lane];
            const float* xa = &s.xs[ra * XS_S];
            const float* xb = &s.xs[(ra + 1) * XS_S];
#pragma unroll 8
            for (int k = 0; k < 64; k++) h = fmaf(xa[k], hs[k * 33 + lane], h);
#pragma unroll 8
            for (int k = 0; k < 64; k++) h = fmaf(xb[k], hs[(64 + k) * 33 + lane], h);
            h = fmaxf(h, 0.0f);
            float v = warp_sum(h * hw2s[lane]);
            if (lane == 0) out[blockIdx.x * EPB + 2 * w + j] = v + b2v;
        }
    }
}

extern "C" void kernel_launch(void* const* d_in, const int* in_sizes, int n_in,
                              void* d_out, int out_size) {
    const float* x        = (const float*)d_in[0];
    const float* w_nr     = (const float*)d_in[1];
    const float* b_nr     = (const float*)d_in[2];
    const float* w_r      = (const float*)d_in[3];
    const float* b_r      = (const float*)d_in[4];
    const float* w_in_nr  = (const float*)d_in[5];
    const float* b_in_nr  = (const float*)d_in[6];
    const float* w_in_r   = (const float*)d_in[7];
    const float* b_in_r   = (const float*)d_in[8];
    const float* ipw      = (const float*)d_in[9];
    const float* cw       = (const float*)d_in[10];
    const float* cb       = (const float*)d_in[11];
    const float* xpw      = (const float*)d_in[12];
    const float* dtw      = (const float*)d_in[13];
    const float* dtb      = (const float*)d_in[14];
    /* alog d_in[15] dead at L=1 (scan h0=0) */
    const float* dskip    = (const float*)d_in[16];
    const float* opw      = (const float*)d_in[17];
    const float* lng      = (const float*)d_in[18];
    const float* lnb      = (const float*)d_in[19];
    const float* hw1      = (const float*)d_in[20];
    const float* hb1      = (const float*)d_in[21];
    const float* hw2      = (const float*)d_in[22];
    const float* hb2      = (const float*)d_in[23];

    size_t smem = sizeof(Smem);
    cudaFuncSetAttribute((const void*)mamba_main,
                         cudaFuncAttributeMaxDynamicSharedMemorySize, (int)smem);

    prep_fold<<<144, 256>>>(w_nr, b_nr, w_r, b_r, w_in_nr, w_in_r);
    prep_blob<<<(B10 + 511) / 512, 512>>>(ipw, opw, xpw, dtw, cw, cb, dtb, dskip,
                                          lng, lnb, b_in_nr, b_in_r);
    mamba_main<<<NBLK, THREADS, smem>>>(x, hw1, hb1, hw2, hb2, (float*)d_out);
}

// round 10
// speedup vs baseline: 2.3066x; 1.2602x over previous
#include <cuda_runtime.h>

#define NL 4
#define BATCH 16384
#define THREADS 512
#define EPB 32
#define NBLK (BATCH / EPB)
#define XS_S 68          // xs row stride (floats)
#define XC_S 132         // xc/sz row stride (floats / u32)
#define XH_S 36          // split-xs row stride (u32)
#define IPW_S 264        // packed ipw kpair-row stride (u32)
#define OPW_S 72         // packed opw kpair-row stride (u32)
#define XPJ_S 36         // packed proj-weight kpair-row stride (u32)
#define PROJ_S 72        // proj scratch row stride (floats)
#define EPSV 1e-5f

typedef unsigned long long ull;
typedef unsigned int u32;

__device__ __forceinline__ ull pk2(float lo, float hi) {
    ull r; asm("mov.b64 %0,{%1,%2};" : "=l"(r) : "f"(lo), "f"(hi)); return r;
}
__device__ __forceinline__ void upk2(ull v, float& lo, float& hi) {
    asm("mov.b64 {%0,%1},%2;" : "=f"(lo), "=f"(hi) : "l"(v));
}
__device__ __forceinline__ ull ffma2(ull a, ull b, ull c) {
    ull d; asm("fma.rn.f32x2 %0,%1,%2,%3;" : "=l"(d) : "l"(a), "l"(b), "l"(c)); return d;
}
__device__ __forceinline__ float warp_sum(float v) {
    v += __shfl_xor_sync(0xffffffffu, v, 16);
    v += __shfl_xor_sync(0xffffffffu, v, 8);
    v += __shfl_xor_sync(0xffffffffu, v, 4);
    v += __shfl_xor_sync(0xffffffffu, v, 2);
    v += __shfl_xor_sync(0xffffffffu, v, 1);
    return v;
}
__device__ __forceinline__ float half_sum(float v) {
    v += __shfl_xor_sync(0xffffffffu, v, 8);
    v += __shfl_xor_sync(0xffffffffu, v, 4);
    v += __shfl_xor_sync(0xffffffffu, v, 2);
    v += __shfl_xor_sync(0xffffffffu, v, 1);
    return v;
}
__device__ __forceinline__ void group_bar(int q) {
    asm volatile("bar.sync %0, 128;" :: "r"(q + 1) : "memory");
}
__device__ __forceinline__ float siluf(float v) {
    return __fdividef(v, 1.0f + __expf(-v));
}
__device__ __forceinline__ float softplusf(float v) {
    return fmaxf(v, 0.0f) + __logf(1.0f + __expf(-fabsf(v)));
}
__device__ __forceinline__ float fget(float4 v, int r) {
    return r == 0 ? v.x : r == 1 ? v.y : r == 2 ? v.z : v.w;
}
// split two fp32 (p.x = even k, p.y = odd k) into packed bf16x2 hi + lo
__device__ __forceinline__ void bfsplit(float2 p, u32& h, u32& l) {
    asm("cvt.rn.satfinite.bf16x2.f32 %0,%1,%2;" : "=r"(h) : "f"(p.y), "f"(p.x));
    float h0 = __uint_as_float(h << 16);
    float h1 = __uint_as_float(h & 0xffff0000u);
    asm("cvt.rn.satfinite.bf16x2.f32 %0,%1,%2;" : "=r"(l) : "f"(p.y - h1), "f"(p.x - h0));
}
__device__ __forceinline__ void mma_bf16(float* c, const u32* a, u32 b0, u32 b1) {
    asm("mma.sync.aligned.m16n8k16.row.col.f32.bf16.bf16.f32 "
        "{%0,%1,%2,%3},{%4,%5,%6,%7},{%8,%9},{%0,%1,%2,%3};"
        : "+f"(c[0]), "+f"(c[1]), "+f"(c[2]), "+f"(c[3])
        : "r"(a[0]), "r"(a[1]), "r"(a[2]), "r"(a[3]), "r"(b0), "r"(b1));
}

// ---------- per-layer weight blob: byte layout == SMEM layout ----------
struct __align__(16) LayerBlob {
    u32 ipwh[32 * IPW_S];        // 8448
    u32 ipwl[32 * IPW_S];        // 8448
    u32 opwh[64 * OPW_S];        // 4608
    u32 opwl[64 * OPW_S];        // 4608
    u32 xpjwh[64 * XPJ_S + 16];  // 2320 (pad: nt=4 tile B-frag over-read)
    u32 xpjwl[64 * XPJ_S + 16];  // 2320
    float dtw[4 * 128];          // 512
    float cw3[128];
    float cb[128];
    float dtb[128];
    float dskip[128];
    float lng[64];
    float lnb[64];
};   // 127,616 B

#define BLOB_V4 (sizeof(LayerBlob) / 16)

__device__ LayerBlob g_blob[NL];
__device__ float g_fold_part[18 * 8 * 64];
__device__ float g_Wnr[12 * 64];
__device__ float g_bnr[64];
__device__ float g_Wr[4 * 64];
__device__ float g_br[64];

// ---- fold kernel: 144 blocks = 18 outputs x 8 c-chunks; partial sums only ----
__global__ void __launch_bounds__(256)
prep_fold(const float* __restrict__ w_nr, const float* __restrict__ b_nr,
          const float* __restrict__ w_r,  const float* __restrict__ b_r,
          const float* __restrict__ w_in_nr, const float* __restrict__ w_in_r) {
    __shared__ float red[4][64];
    const int j = blockIdx.x >> 3;
    const int chunk = blockIdx.x & 7;
    const int o = threadIdx.x & 63;
    const int cg = threadIdx.x >> 6;
    const float* vec;
    const float* mat;
    if (j < 12)       { vec = w_nr + j * 1000;        mat = w_in_nr; }
    else if (j == 12) { vec = b_nr;                   mat = w_in_nr; }
    else if (j < 17)  { vec = w_r + (j - 13) * 1000;  mat = w_in_r;  }
    else              { vec = b_r;                    mat = w_in_r;  }
    const int cbase = chunk * 125;
    const int cend = cbase + 125;
    float a0 = 0.f, a1 = 0.f;
    for (int c = cbase + cg * 2; c < cend; c += 8) {
        a0 = fmaf(vec[c], mat[c * 64 + o], a0);
        if (c + 1 < cend)
            a1 = fmaf(vec[c + 1], mat[(c + 1) * 64 + o], a1);
    }
    red[cg][o] = a0 + a1;
    __syncthreads();
    if (cg == 0)
        g_fold_part[(j * 8 + chunk) * 64 + o] =
            (red[0][o] + red[1][o]) + (red[2][o] + red[3][o]);
}

// ---- blob prep ----
#define B0 (NL * 8192)
#define B1 (B0 + NL * 4096)
#define B2 (B1 + NL * 2304)
#define B3 (B2 + NL * 512)
#define B4 (B3 + NL * 128)
#define B5 (B4 + NL * 128)
#define B6 (B5 + NL * 128)
#define B7 (B6 + NL * 128)
#define B8 (B7 + NL * 64)
#define B9 (B8 + NL * 64)
#define B10 (B9 + 1152)

__global__ void __launch_bounds__(512)
prep_blob(const float* __restrict__ ipw, const float* __restrict__ opw,
          const float* __restrict__ xpw, const float* __restrict__ dtw,
          const float* __restrict__ cw,  const float* __restrict__ cb,
          const float* __restrict__ dtb, const float* __restrict__ dskip,
          const float* __restrict__ lng, const float* __restrict__ lnb,
          const float* __restrict__ b_in_nr, const float* __restrict__ b_in_r) {
    int idx = blockIdx.x * 512 + threadIdx.x;
    if (idx < B0) {
        int l = idx >> 13, r = idx & 8191, kp = r >> 8, n = r & 255;
        const float* src = ipw + l * 16384 + kp * 512 + n;
        u32 h, lo; bfsplit(make_float2(src[0], src[256]), h, lo);
        g_blob[l].ipwh[kp * IPW_S + n] = h;
        g_blob[l].ipwl[kp * IPW_S + n] = lo;
    } else if (idx < B1) {
        int j = idx - B0, l = j >> 12, r = j & 4095, kp = r >> 6, n = r & 63;
        const float* src = opw + l * 8192 + kp * 128 + n;
        u32 h, lo; bfsplit(make_float2(src[0], src[64]), h, lo);
        g_blob[l].opwh[kp * OPW_S + n] = h;
        g_blob[l].opwl[kp * OPW_S + n] = lo;
    } else if (idx < B2) {
        int j = idx - B1, l = j / 2304, r = j - l * 2304;
        int kp = r / 36, n = r - kp * 36;
        const float* src = xpw + l * 4608 + (2 * kp) * 36 + n;
        u32 h, lo; bfsplit(make_float2(src[0], src[36]), h, lo);
        g_blob[l].xpjwh[kp * XPJ_S + n] = h;
        g_blob[l].xpjwl[kp * XPJ_S + n] = lo;
    } else if (idx < B3) {
        int j = idx - B2, l = j >> 9, r = j & 511;
        g_blob[l].dtw[r] = dtw[l * 512 + r];
    } else if (idx < B4) {
        int j = idx - B3, l = j >> 7, r = j & 127;
        g_blob[l].cw3[r] = cw[(l * 128 + r) * 4 + 3];
    } else if (idx < B5) {
        int j = idx - B4, l = j >> 7, r = j & 127;
        g_blob[l].cb[r] = cb[l * 128 + r];
    } else if (idx < B6) {
        int j = idx - B5, l = j >> 7, r = j & 127;
        g_blob[l].dtb[r] = dtb[l * 128 + r];
    } else if (idx < B7) {
        int j = idx - B6, l = j >> 7, r = j & 127;
        g_blob[l].dskip[r] = dskip[l * 128 + r];
    } else if (idx < B8) {
        int j = idx - B7, l = j >> 6, r = j & 63;
        g_blob[l].lng[r] = lng[l * 64 + r];
    } else if (idx < B9) {
        int j = idx - B8, l = j >> 6, r = j & 63;
        g_blob[l].lnb[r] = lnb[l * 64 + r];
    } else if (idx < B10) {
        int W = idx - B9;
        int j = W >> 6, o = W & 63;
        const float* p = g_fold_part + j * 8 * 64 + o;
        float a = 0.0f;
#pragma unroll
        for (int k = 0; k < 8; k++) a += p[k * 64];
        if (j < 12)       g_Wnr[j * 64 + o] = a;
        else if (j == 12) g_bnr[o] = a + b_in_nr[o];
        else if (j < 17)  g_Wr[(j - 13) * 64 + o] = a;
        else              g_br[o] = a + b_in_r[o];
    }
}

// ---------------- shared memory (231,040 B; 1 block/SM) ----------------
struct __align__(16) Smem {
    LayerBlob blob;
    u32 xsh[64 * XH_S];       // split residual hi; dead between stage A & D -> proj scratch
    u32 xsl[64 * XH_S];       // split residual lo; proj[64][72] overlays xsh+xsl
    float xs[64 * XS_S];      // residual fp32
    float xc[64 * XC_S];      // split xc -> split y (u32; hi cols 0..63, lo 64..127)
    float sz[64 * XC_S];      // silu(z), then O
};

__global__ void __launch_bounds__(THREADS, 1)
mamba_main(const float* __restrict__ xin,
           const float* __restrict__ hw1, const float* __restrict__ hb1,
           const float* __restrict__ hw2, const float* __restrict__ hb2,
           float* __restrict__ out) {
    extern __shared__ __align__(16) char smem_raw[];
    Smem& s = *reinterpret_cast<Smem*>(smem_raw);

    const int t = threadIdx.x;
    const int w = t >> 5;
    const int lane = t & 31;
    const int q = w & 3;          // m-tile / barrier group
    const int nc = w >> 2;        // n-chunk
    const int g = lane >> 2;      // mma group row
    const int cc = lane & 3;      // mma thread-in-group
    const int rb4 = 16 * q + 4 * nc;
    float* proj = (float*)s.xsh;  // proj[64][PROJ_S] overlays xsh+xsl (4608 floats)

    // ---- stage folded input-proj weights (union'd into xc region) ----
    float* Wnr_s = s.xc;
    float* Wr_s  = s.xc + 768;
    float* bnr_s = s.xc + 1024;
    float* br_s  = s.xc + 1088;
    for (int i = t; i < 768; i += THREADS) Wnr_s[i] = g_Wnr[i];
    if (t < 256)      Wr_s[t] = g_Wr[t];
    else if (t < 320) bnr_s[t - 256] = g_bnr[t - 256];
    else if (t < 384) br_s[t - 320] = g_br[t - 320];
    __syncthreads();

    // ---- x0 = feat @ W_eff + b_eff : warp w -> rows 4w..4w+3; write fp32 + split ----
    {
        const int e0 = blockIdx.x * EPB + 2 * w;
        float fe[2][16];
#pragma unroll
        for (int e = 0; e < 2; e++) {
            const float4* xp = (const float4*)(xin + (size_t)(e0 + e) * 16);
#pragma unroll
            for (int qq = 0; qq < 4; qq++) {
                float4 v = xp[qq];
                fe[e][4 * qq + 0] = v.x; fe[e][4 * qq + 1] = v.y;
                fe[e][4 * qq + 2] = v.z; fe[e][4 * qq + 3] = v.w;
            }
        }
        float2 bn = *(const float2*)&bnr_s[2 * lane];
        float2 bb = *(const float2*)&br_s[2 * lane];
        ull a0 = pk2(bn.x, bn.y), a2 = a0;
        ull a1 = pk2(bb.x, bb.y), a3 = a1;
#pragma unroll
        for (int f = 0; f < 12; f++) {
            ull wp = *(const ull*)&Wnr_s[f * 64 + 2 * lane];
            a0 = ffma2(wp, pk2(fe[0][f], fe[0][f]), a0);
            a2 = ffma2(wp, pk2(fe[1][f], fe[1][f]), a2);
        }
#pragma unroll
        for (int f = 0; f < 4; f++) {
            ull wp = *(const ull*)&Wr_s[f * 64 + 2 * lane];
            a1 = ffma2(wp, pk2(fe[0][12 + f], fe[0][12 + f]), a1);
            a3 = ffma2(wp, pk2(fe[1][12 + f], fe[1][12 + f]), a3);
        }
        ull accs[4] = {a0, a1, a2, a3};
#pragma unroll
        for (int j = 0; j < 4; j++) {
            float v0, v1; upk2(accs[j], v0, v1);
            int row = 4 * w + j;
            *(float2*)&s.xs[row * XS_S + 2 * lane] = make_float2(v0, v1);
            u32 h, lo; bfsplit(make_float2(v0, v1), h, lo);
            s.xsh[row * XH_S + lane] = h;
            s.xsl[row * XH_S + lane] = lo;
        }
    }

    // ================= layer loop =================
#pragma unroll 1
    for (int l = 0; l < NL; l++) {
        __syncthreads();
        {   // flat vectorized blob copy
            const uint4* src = (const uint4*)&g_blob[l];
            uint4* dst = (uint4*)&s.blob;
            for (int i = t; i < BLOB_V4; i += THREADS) dst[i] = src[i];
        }
        __syncthreads();

        // ======== stage A: xz GEMM (bf16x3); xc stored SPLIT, z stored fp32 ========
        {
            const int row0 = 16 * q + g, row8 = row0 + 8;
            const u32* xh0 = &s.xsh[row0 * XH_S];
            const u32* xh8 = &s.xsh[row8 * XH_S];
            const u32* xl0 = &s.xsl[row0 * XH_S];
            const u32* xl8 = &s.xsl[row8 * XH_S];
            float acc[8][4];
#pragma unroll
            for (int nt = 0; nt < 8; nt++)
#pragma unroll
                for (int i = 0; i < 4; i++) acc[nt][i] = 0.0f;
#pragma unroll
            for (int ks = 0; ks < 4; ks++) {
                const int kp = ks * 8 + cc;
                u32 ah[4], al[4];
                ah[0] = xh0[kp];     ah[1] = xh8[kp];
                ah[2] = xh0[kp + 4]; ah[3] = xh8[kp + 4];
                al[0] = xl0[kp];     al[1] = xl8[kp];
                al[2] = xl0[kp + 4]; al[3] = xl8[kp + 4];
                const u32* bh = &s.blob.ipwh[kp * IPW_S + nc * 64 + g];
                const u32* bl = &s.blob.ipwl[kp * IPW_S + nc * 64 + g];
#pragma unroll
                for (int nt = 0; nt < 8; nt++) {
                    u32 bh0 = bh[nt * 8], bh1 = bh[4 * IPW_S + nt * 8];
                    u32 bl0 = bl[nt * 8], bl1 = bl[4 * IPW_S + nt * 8];
                    mma_bf16(acc[nt], ah, bh0, bh1);
                    mma_bf16(acc[nt], ah, bl0, bl1);
                    mma_bf16(acc[nt], al, bh0, bh1);
                }
            }
            if (nc < 2) {        // xc half: conv tap + silu, stored split
                u32* xr0 = (u32*)&s.xc[row0 * XC_S];
                u32* xr8 = (u32*)&s.xc[row8 * XC_S];
#pragma unroll
                for (int nt = 0; nt < 8; nt++) {
                    int col = nc * 64 + nt * 8 + 2 * cc;
                    int p = col >> 1;
                    float2 cwv = *(const float2*)&s.blob.cw3[col];
                    float2 cbv = *(const float2*)&s.blob.cb[col];
                    float2 v0 = make_float2(siluf(fmaf(acc[nt][0], cwv.x, cbv.x)),
                                            siluf(fmaf(acc[nt][1], cwv.y, cbv.y)));
                    float2 v8 = make_float2(siluf(fmaf(acc[nt][2], cwv.x, cbv.x)),
                                            siluf(fmaf(acc[nt][3], cwv.y, cbv.y)));
                    u32 h, lo;
                    bfsplit(v0, h, lo); xr0[p] = h; xr0[64 + p] = lo;
                    bfsplit(v8, h, lo); xr8[p] = h; xr8[64 + p] = lo;
                }
            } else {             // z half: silu, fp32
#pragma unroll
                for (int nt = 0; nt < 8; nt++) {
                    int col = (nc - 2) * 64 + nt * 8 + 2 * cc;
                    *(float2*)&s.sz[row0 * XC_S + col] =
                        make_float2(siluf(acc[nt][0]), siluf(acc[nt][1]));
                    *(float2*)&s.sz[row8 * XC_S + col] =
                        make_float2(siluf(acc[nt][2]), siluf(acc[nt][3]));
                }
            }
        }
        __syncthreads();   // xsh/xsl reads done block-wide before proj overwrites

        // ======== proj GEMM: proj[64][36+] = xc @ xpw via bf16x3 mma ========
        {
            // n-tile assignment per warp: nc0:{0,1} nc1:{2,3} nc2:{4} nc3:{}
            const int ntb = (nc < 2) ? nc * 2 : (nc == 2 ? 4 : 0);
            const int nte = (nc < 2) ? ntb + 2 : (nc == 2 ? 5 : 0);
            if (ntb < nte) {
                const int row0 = 16 * q + g, row8 = row0 + 8;
                const u32* yh0 = (const u32*)&s.xc[row0 * XC_S];
                const u32* yh8 = (const u32*)&s.xc[row8 * XC_S];
                float acc[2][4];
#pragma unroll
                for (int nt = 0; nt < 2; nt++)
#pragma unroll
                    for (int i = 0; i < 4; i++) acc[nt][i] = 0.0f;
#pragma unroll
                for (int ks = 0; ks < 8; ks++) {
                    const int kp = ks * 8 + cc;
                    u32 ah[4], al[4];
                    ah[0] = yh0[kp];          ah[1] = yh8[kp];
                    ah[2] = yh0[kp + 4];      ah[3] = yh8[kp + 4];
                    al[0] = yh0[64 + kp];     al[1] = yh8[64 + kp];
                    al[2] = yh0[64 + kp + 4]; al[3] = yh8[64 + kp + 4];
                    const u32* bh = &s.blob.xpjwh[kp * XPJ_S + g];
                    const u32* bl = &s.blob.xpjwl[kp * XPJ_S + g];
                    for (int nt = ntb; nt < nte; nt++) {
                        int a = nt - ntb;
                        u32 bh0 = bh[nt * 8], bh1 = bh[4 * XPJ_S + nt * 8];
                        u32 bl0 = bl[nt * 8], bl1 = bl[4 * XPJ_S + nt * 8];
                        mma_bf16(acc[a], ah, bh0, bh1);
                        mma_bf16(acc[a], ah, bl0, bl1);
                        mma_bf16(acc[a], al, bh0, bh1);
                    }
                }
                for (int nt = ntb; nt < nte; nt++) {
                    int a = nt - ntb;
                    int col = nt * 8 + 2 * cc;
                    *(float2*)&proj[row0 * PROJ_S + col] = make_float2(acc[a][0], acc[a][1]);
                    *(float2*)&proj[row8 * PROJ_S + col] = make_float2(acc[a][2], acc[a][3]);
                }
            }
        }
        group_bar(q);

        // ======== stage B: dt/BC/y for rows rb4..rb4+3 (scalar, tiny now) ========
        {
            // pr: direct loads, no reduction
            float4 pj[4];
#pragma unroll
            for (int j = 0; j < 4; j++)
                pj[j] = *(const float4*)&proj[(rb4 + j) * PROJ_S];
            // BC: lanes split 2 jobs x 16 s-values
            float bc[4];
            {
                const int j2 = lane >> 4, sidx = lane & 15;
#pragma unroll
                for (int a = 0; a < 2; a++) {
                    const float* pr = &proj[(rb4 + 2 * a + j2) * PROJ_S];
                    float v = pr[4 + sidx] * pr[20 + sidx];
                    v = half_sum(v);
                    bc[2 * a + 0] = __shfl_sync(0xffffffffu, v, 0);
                    bc[2 * a + 1] = __shfl_sync(0xffffffffu, v, 16);
                }
            }
            // dts = softplus(pj @ dtw + dtb)
            float dts[4][4];
            {
                float4 dtbv = *(const float4*)&s.blob.dtb[4 * lane];
#pragma unroll
                for (int j = 0; j < 4; j++) {
                    dts[j][0] = dtbv.x; dts[j][1] = dtbv.y;
                    dts[j][2] = dtbv.z; dts[j][3] = dtbv.w;
                }
#pragma unroll
                for (int r = 0; r < 4; r++) {
                    float4 dwv = *(const float4*)&s.blob.dtw[r * 128 + 4 * lane];
#pragma unroll
                    for (int j = 0; j < 4; j++) {
                        float prj = fget(pj[j], r);
                        dts[j][0] = fmaf(prj, dwv.x, dts[j][0]);
                        dts[j][1] = fmaf(prj, dwv.y, dts[j][1]);
                        dts[j][2] = fmaf(prj, dwv.z, dts[j][2]);
                        dts[j][3] = fmaf(prj, dwv.w, dts[j][3]);
                    }
                }
#pragma unroll
                for (int j = 0; j < 4; j++) {
                    dts[j][0] = softplusf(dts[j][0]); dts[j][1] = softplusf(dts[j][1]);
                    dts[j][2] = softplusf(dts[j][2]); dts[j][3] = softplusf(dts[j][3]);
                }
            }
            // y = xc*(dts*BC + dskip)*silu(z); xc reconstructed from split; y re-split
            {
                float4 dskv = *(const float4*)&s.blob.dskip[4 * lane];
#pragma unroll
                for (int j = 0; j < 4; j++) {
                    u32* xr = (u32*)&s.xc[(rb4 + j) * XC_S];
                    uint2 hh = *(const uint2*)&xr[2 * lane];
                    uint2 ll = *(const uint2*)&xr[64 + 2 * lane];
                    float xc0 = __uint_as_float(hh.x << 16) + __uint_as_float(ll.x << 16);
                    float xc1 = __uint_as_float(hh.x & 0xffff0000u) + __uint_as_float(ll.x & 0xffff0000u);
                    float xc2 = __uint_as_float(hh.y << 16) + __uint_as_float(ll.y << 16);
                    float xc3 = __uint_as_float(hh.y & 0xffff0000u) + __uint_as_float(ll.y & 0xffff0000u);
                    float4 szv = *(const float4*)&s.sz[(rb4 + j) * XC_S + 4 * lane];
                    float4 yv;
                    yv.x = xc0 * fmaf(dts[j][0], bc[j], dskv.x) * szv.x;
                    yv.y = xc1 * fmaf(dts[j][1], bc[j], dskv.y) * szv.y;
                    yv.z = xc2 * fmaf(dts[j][2], bc[j], dskv.z) * szv.z;
                    yv.w = xc3 * fmaf(dts[j][3], bc[j], dskv.w) * szv.w;
                    u32 h0, l0, h1, l1;
                    bfsplit(make_float2(yv.x, yv.y), h0, l0);
                    bfsplit(make_float2(yv.z, yv.w), h1, l1);
                    *(uint2*)&xr[2 * lane]      = make_uint2(h0, h1);
                    *(uint2*)&xr[64 + 2 * lane] = make_uint2(l0, l1);
                }
            }
        }
        group_bar(q);

        // ======== stage C: out-proj GEMM (bf16x3 mma) ========
        {
            const int row0 = 16 * q + g, row8 = row0 + 8;
            const u32* yh0 = (const u32*)&s.xc[row0 * XC_S];
            const u32* yh8 = (const u32*)&s.xc[row8 * XC_S];
            float acc[2][4];
#pragma unroll
            for (int nt = 0; nt < 2; nt++)
#pragma unroll
                for (int i = 0; i < 4; i++) acc[nt][i] = 0.0f;
#pragma unroll
            for (int ks = 0; ks < 8; ks++) {
                const int kp = ks * 8 + cc;
                u32 ah[4], al[4];
                ah[0] = yh0[kp];          ah[1] = yh8[kp];
                ah[2] = yh0[kp + 4];      ah[3] = yh8[kp + 4];
                al[0] = yh0[64 + kp];     al[1] = yh8[64 + kp];
                al[2] = yh0[64 + kp + 4]; al[3] = yh8[64 + kp + 4];
                const u32* bh = &s.blob.opwh[kp * OPW_S + nc * 16 + g];
                const u32* bl = &s.blob.opwl[kp * OPW_S + nc * 16 + g];
#pragma unroll
                for (int nt = 0; nt < 2; nt++) {
                    u32 bh0 = bh[nt * 8], bh1 = bh[4 * OPW_S + nt * 8];
                    u32 bl0 = bl[nt * 8], bl1 = bl[4 * OPW_S + nt * 8];
                    mma_bf16(acc[nt], ah, bh0, bh1);
                    mma_bf16(acc[nt], ah, bl0, bl1);
                    mma_bf16(acc[nt], al, bh0, bh1);
                }
            }
#pragma unroll
            for (int nt = 0; nt < 2; nt++) {
                int col = nc * 16 + nt * 8 + 2 * cc;
                *(float2*)&s.sz[row0 * XC_S + col] = make_float2(acc[nt][0], acc[nt][1]);
                *(float2*)&s.sz[row8 * XC_S + col] = make_float2(acc[nt][2], acc[nt][3]);
            }
        }
        __syncthreads();   // all proj reads done before stage D rewrites xsh/xsl

        // ======== stage D: layernorm(64) + residual; write fp32 + split ========
        {
            float2 gv = *(const float2*)&s.blob.lng[2 * lane];
            float2 bv = *(const float2*)&s.blob.lnb[2 * lane];
#pragma unroll
            for (int j = 0; j < 4; j++) {
                int row = rb4 + j;
                float2 ov = *(const float2*)&s.sz[row * XC_S + 2 * lane];
                float m  = warp_sum(ov.x + ov.y) * (1.0f / 64.0f);
                float m2 = warp_sum(ov.x * ov.x + ov.y * ov.y) * (1.0f / 64.0f);
                float rs = rsqrtf(m2 - m * m + EPSV);
                float2 xv = *(const float2*)&s.xs[row * XS_S + 2 * lane];
                xv.x += (ov.x - m) * rs * gv.x + bv.x;
                xv.y += (ov.y - m) * rs * gv.y + bv.y;
                *(float2*)&s.xs[row * XS_S + 2 * lane] = xv;
                u32 h, lo; bfsplit(xv, h, lo);
                s.xsh[row * XH_S + lane] = h;
                s.xsl[row * XH_S + lane] = lo;
            }
        }
    }

    // ================= head =================
    __syncthreads();
    {
        float* hs = s.xc;   // reuse as hw1[128][33]
        for (int i = t; i < 4096; i += THREADS) {
            int k = i >> 5, c = i & 31;
            hs[k * 33 + c] = hw1[i];
        }
        float* hb1s = s.sz;
        float* hw2s = s.sz + 64;
        if (t < 32) { hb1s[t] = hb1[t]; hw2s[t] = hw2[t]; }
        __syncthreads();

        float b2v = hb2[0];
#pragma unroll
        for (int j = 0; j < 2; j++) {
            int ra = 4 * w + 2 * j;
            float h = hb1s[lane];
            const float* xa = &s.xs[ra * XS_S];
            const float* xb = &s.xs[(ra + 1) * XS_S];
#pragma unroll 8
            for (int k = 0; k < 64; k++) h = fmaf(xa[k], hs[k * 33 + lane], h);
#pragma unroll 8
            for (int k = 0; k < 64; k++) h = fmaf(xb[k], hs[(64 + k) * 33 + lane], h);
            h = fmaxf(h, 0.0f);
            float v = warp_sum(h * hw2s[lane]);
            if (lane == 0) out[blockIdx.x * EPB + 2 * w + j] = v + b2v;
        }
    }
}

extern "C" void kernel_launch(void* const* d_in, const int* in_sizes, int n_in,
                              void* d_out, int out_size) {
    const float* x        = (const float*)d_in[0];
    const float* w_nr     = (const float*)d_in[1];
    const float* b_nr     = (const float*)d_in[2];
    const float* w_r      = (const float*)d_in[3];
    const float* b_r      = (const float*)d_in[4];
    const float* w_in_nr  = (const float*)d_in[5];
    const float* b_in_nr  = (const float*)d_in[6];
    const float* w_in_r   = (const float*)d_in[7];
    const float* b_in_r   = (const float*)d_in[8];
    const float* ipw      = (const float*)d_in[9];
    const float* cw       = (const float*)d_in[10];
    const float* cb       = (const float*)d_in[11];
    const float* xpw      = (const float*)d_in[12];
    const float* dtw      = (const float*)d_in[13];
    const float* dtb      = (const float*)d_in[14];
    /* alog d_in[15] dead at L=1 (scan h0=0) */
    const float* dskip    = (const float*)d_in[16];
    const float* opw      = (const float*)d_in[17];
    const float* lng      = (const float*)d_in[18];
    const float* lnb      = (const float*)d_in[19];
    const float* hw1      = (const float*)d_in[20];
    const float* hb1      = (const float*)d_in[21];
    const float* hw2      = (const float*)d_in[22];
    const float* hb2      = (const float*)d_in[23];

    size_t smem = sizeof(Smem);
    cudaFuncSetAttribute((const void*)mamba_main,
                         cudaFuncAttributeMaxDynamicSharedMemorySize, (int)smem);

    prep_fold<<<144, 256>>>(w_nr, b_nr, w_r, b_r, w_in_nr, w_in_r);
    prep_blob<<<(B10 + 511) / 512, 512>>>(ipw, opw, xpw, dtw, cw, cb, dtb, dskip,
                                          lng, lnb, b_in_nr, b_in_r);
    mamba_main<<<NBLK, THREADS, smem>>>(x, hw1, hb1, hw2, hb2, (float*)d_out);
}

// round 11
// speedup vs baseline: 2.3208x; 1.0062x over previous
#include <cuda_runtime.h>

#define NL 4
#define BATCH 16384
#define THREADS 512
#define EPB 32
#define NBLK (BATCH / EPB)
#define XS_S 68          // xs row stride (floats)
#define XC_S 132         // xc/sz row stride (floats / u32)
#define XH_S 36          // split-xs row stride (u32)
#define IPW_S 264        // packed ipw kpair-row stride (u32)
#define OPW_S 72         // packed opw kpair-row stride (u32)
#define XPJ_S 36         // packed proj-weight kpair-row stride (u32)
#define PROJ_S 72        // proj scratch row stride (floats)
#define NCHUNK 16        // fold c-split
#define EPSV 1e-5f

typedef unsigned long long ull;
typedef unsigned int u32;

__device__ __forceinline__ ull pk2(float lo, float hi) {
    ull r; asm("mov.b64 %0,{%1,%2};" : "=l"(r) : "f"(lo), "f"(hi)); return r;
}
__device__ __forceinline__ void upk2(ull v, float& lo, float& hi) {
    asm("mov.b64 {%0,%1},%2;" : "=f"(lo), "=f"(hi) : "l"(v));
}
__device__ __forceinline__ ull ffma2(ull a, ull b, ull c) {
    ull d; asm("fma.rn.f32x2 %0,%1,%2,%3;" : "=l"(d) : "l"(a), "l"(b), "l"(c)); return d;
}
__device__ __forceinline__ float warp_sum(float v) {
    v += __shfl_xor_sync(0xffffffffu, v, 16);
    v += __shfl_xor_sync(0xffffffffu, v, 8);
    v += __shfl_xor_sync(0xffffffffu, v, 4);
    v += __shfl_xor_sync(0xffffffffu, v, 2);
    v += __shfl_xor_sync(0xffffffffu, v, 1);
    return v;
}
__device__ __forceinline__ float half_sum(float v) {
    v += __shfl_xor_sync(0xffffffffu, v, 8);
    v += __shfl_xor_sync(0xffffffffu, v, 4);
    v += __shfl_xor_sync(0xffffffffu, v, 2);
    v += __shfl_xor_sync(0xffffffffu, v, 1);
    return v;
}
__device__ __forceinline__ void group_bar(int q) {
    asm volatile("bar.sync %0, 128;" :: "r"(q + 1) : "memory");
}
__device__ __forceinline__ float siluf(float v) {
    return __fdividef(v, 1.0f + __expf(-v));
}
__device__ __forceinline__ float softplusf(float v) {
    return fmaxf(v, 0.0f) + __logf(1.0f + __expf(-fabsf(v)));
}
__device__ __forceinline__ float fget(float4 v, int r) {
    return r == 0 ? v.x : r == 1 ? v.y : r == 2 ? v.z : v.w;
}
// split two fp32 (p.x = even k, p.y = odd k) into packed bf16x2 hi + lo
__device__ __forceinline__ void bfsplit(float2 p, u32& h, u32& l) {
    asm("cvt.rn.satfinite.bf16x2.f32 %0,%1,%2;" : "=r"(h) : "f"(p.y), "f"(p.x));
    float h0 = __uint_as_float(h << 16);
    float h1 = __uint_as_float(h & 0xffff0000u);
    asm("cvt.rn.satfinite.bf16x2.f32 %0,%1,%2;" : "=r"(l) : "f"(p.y - h1), "f"(p.x - h0));
}
__device__ __forceinline__ void mma_bf16(float* c, const u32* a, u32 b0, u32 b1) {
    asm("mma.sync.aligned.m16n8k16.row.col.f32.bf16.bf16.f32 "
        "{%0,%1,%2,%3},{%4,%5,%6,%7},{%8,%9},{%0,%1,%2,%3};"
        : "+f"(c[0]), "+f"(c[1]), "+f"(c[2]), "+f"(c[3])
        : "r"(a[0]), "r"(a[1]), "r"(a[2]), "r"(a[3]), "r"(b0), "r"(b1));
}

// ---------- per-layer weight blob: byte layout == SMEM layout ----------
struct __align__(16) LayerBlob {
    u32 ipwh[32 * IPW_S];        // 8448
    u32 ipwl[32 * IPW_S];        // 8448
    u32 opwh[64 * OPW_S];        // 4608
    u32 opwl[64 * OPW_S];        // 4608
    u32 xpjwh[64 * XPJ_S + 16];  // 2320 (pad: nt=4 tile B-frag over-read)
    u32 xpjwl[64 * XPJ_S + 16];  // 2320
    float dtw[4 * 128];          // 512
    float cw3[128];
    float cb[128];
    float dtb[128];
    float dskip[128];
    float lng[64];
    float lnb[64];
};   // 127,616 B

#define BLOB_V4 (sizeof(LayerBlob) / 16)

__device__ LayerBlob g_blob[NL];
__device__ float g_fold_part[18 * NCHUNK * 64];

// ---- merged prep: blocks [0,288) = fold partials; [288, 288+246) = blob ----
#define FOLD_BLKS (18 * NCHUNK)
#define B0 (NL * 8192)
#define B1 (B0 + NL * 4096)
#define B2 (B1 + NL * 2304)
#define B3 (B2 + NL * 512)
#define B4 (B3 + NL * 128)
#define B5 (B4 + NL * 128)
#define B6 (B5 + NL * 128)
#define B7 (B6 + NL * 128)
#define B8 (B7 + NL * 64)
#define B9 (B8 + NL * 64)
#define BLOB_BLKS ((B9 + 255) / 256)

__global__ void __launch_bounds__(256)
prep_all(const float* __restrict__ w_nr, const float* __restrict__ b_nr,
         const float* __restrict__ w_r,  const float* __restrict__ b_r,
         const float* __restrict__ w_in_nr, const float* __restrict__ w_in_r,
         const float* __restrict__ ipw, const float* __restrict__ opw,
         const float* __restrict__ xpw, const float* __restrict__ dtw,
         const float* __restrict__ cw,  const float* __restrict__ cb,
         const float* __restrict__ dtb, const float* __restrict__ dskip,
         const float* __restrict__ lng, const float* __restrict__ lnb) {
    if (blockIdx.x < FOLD_BLKS) {
        // -------- fold partials: block = (j, chunk of 63 c-values) --------
        __shared__ float red[4][64];
        const int j = blockIdx.x / NCHUNK;
        const int chunk = blockIdx.x - j * NCHUNK;
        const int o = threadIdx.x & 63;
        const int cg = threadIdx.x >> 6;
        const float* vec;
        const float* mat;
        if (j < 12)       { vec = w_nr + j * 1000;        mat = w_in_nr; }
        else if (j == 12) { vec = b_nr;                   mat = w_in_nr; }
        else if (j < 17)  { vec = w_r + (j - 13) * 1000;  mat = w_in_r;  }
        else              { vec = b_r;                    mat = w_in_r;  }
        const int cbase = chunk * 63;
        const int cend = (cbase + 63 < 1000) ? cbase + 63 : 1000;
        float a0 = 0.f, a1 = 0.f;
        for (int c = cbase + cg * 2; c < cend; c += 8) {
            a0 = fmaf(vec[c], mat[c * 64 + o], a0);
            if (c + 1 < cend)
                a1 = fmaf(vec[c + 1], mat[(c + 1) * 64 + o], a1);
        }
        red[cg][o] = a0 + a1;
        __syncthreads();
        if (cg == 0)
            g_fold_part[(j * NCHUNK + chunk) * 64 + o] =
                (red[0][o] + red[1][o]) + (red[2][o] + red[3][o]);
        return;
    }
    // -------- blob packing --------
    int idx = (blockIdx.x - FOLD_BLKS) * 256 + threadIdx.x;
    if (idx < B0) {
        int l = idx >> 13, r = idx & 8191, kp = r >> 8, n = r & 255;
        const float* src = ipw + l * 16384 + kp * 512 + n;
        u32 h, lo; bfsplit(make_float2(src[0], src[256]), h, lo);
        g_blob[l].ipwh[kp * IPW_S + n] = h;
        g_blob[l].ipwl[kp * IPW_S + n] = lo;
    } else if (idx < B1) {
        int j = idx - B0, l = j >> 12, r = j & 4095, kp = r >> 6, n = r & 63;
        const float* src = opw + l * 8192 + kp * 128 + n;
        u32 h, lo; bfsplit(make_float2(src[0], src[64]), h, lo);
        g_blob[l].opwh[kp * OPW_S + n] = h;
        g_blob[l].opwl[kp * OPW_S + n] = lo;
    } else if (idx < B2) {
        int j = idx - B1, l = j / 2304, r = j - l * 2304;
        int kp = r / 36, n = r - kp * 36;
        const float* src = xpw + l * 4608 + (2 * kp) * 36 + n;
        u32 h, lo; bfsplit(make_float2(src[0], src[36]), h, lo);
        g_blob[l].xpjwh[kp * XPJ_S + n] = h;
        g_blob[l].xpjwl[kp * XPJ_S + n] = lo;
    } else if (idx < B3) {
        int j = idx - B2, l = j >> 9, r = j & 511;
        g_blob[l].dtw[r] = dtw[l * 512 + r];
    } else if (idx < B4) {
        int j = idx - B3, l = j >> 7, r = j & 127;
        g_blob[l].cw3[r] = cw[(l * 128 + r) * 4 + 3];
    } else if (idx < B5) {
        int j = idx - B4, l = j >> 7, r = j & 127;
        g_blob[l].cb[r] = cb[l * 128 + r];
    } else if (idx < B6) {
        int j = idx - B5, l = j >> 7, r = j & 127;
        g_blob[l].dtb[r] = dtb[l * 128 + r];
    } else if (idx < B7) {
        int j = idx - B6, l = j >> 7, r = j & 127;
        g_blob[l].dskip[r] = dskip[l * 128 + r];
    } else if (idx < B8) {
        int j = idx - B7, l = j >> 6, r = j & 63;
        g_blob[l].lng[r] = lng[l * 64 + r];
    } else if (idx < B9) {
        int j = idx - B8, l = j >> 6, r = j & 63;
        g_blob[l].lnb[r] = lnb[l * 64 + r];
    }
}

// ---------------- shared memory (231,040 B; 1 block/SM) ----------------
struct __align__(16) Smem {
    LayerBlob blob;
    u32 xsh[64 * XH_S];       // split residual hi; dead between stage A & D -> proj scratch
    u32 xsl[64 * XH_S];       // split residual lo; proj[64][72] overlays xsh+xsl
    float xs[64 * XS_S];      // residual fp32
    float xc[64 * XC_S];      // split xc -> split y (u32; hi cols 0..63, lo 64..127)
    float sz[64 * XC_S];      // silu(z), then O
};

__global__ void __launch_bounds__(THREADS, 1)
mamba_main(const float* __restrict__ xin,
           const float* __restrict__ b_in_nr, const float* __restrict__ b_in_r,
           const float* __restrict__ hw1, const float* __restrict__ hb1,
           const float* __restrict__ hw2, const float* __restrict__ hb2,
           float* __restrict__ out) {
    extern __shared__ __align__(16) char smem_raw[];
    Smem& s = *reinterpret_cast<Smem*>(smem_raw);

    const int t = threadIdx.x;
    const int w = t >> 5;
    const int lane = t & 31;
    const int q = w & 3;          // m-tile / barrier group
    const int nc = w >> 2;        // n-chunk
    const int g = lane >> 2;      // mma group row
    const int cc = lane & 3;      // mma thread-in-group
    const int rb4 = 16 * q + 4 * nc;
    float* proj = (float*)s.xsh;  // proj[64][PROJ_S] overlays xsh+xsl (4608 floats)

    // ---- fold-reduce directly into SMEM (union'd into xc region) ----
    float* Wnr_s = s.xc;
    float* Wr_s  = s.xc + 768;
    float* bnr_s = s.xc + 1024;
    float* br_s  = s.xc + 1088;
    for (int i = t; i < 1152; i += THREADS) {
        int j = i >> 6, o = i & 63;
        const float* p = g_fold_part + (j * NCHUNK) * 64 + o;
        float a = 0.0f;
#pragma unroll
        for (int k = 0; k < NCHUNK; k++) a += p[k * 64];
        if (j < 12)       Wnr_s[j * 64 + o] = a;
        else if (j == 12) bnr_s[o] = a + b_in_nr[o];
        else if (j < 17)  Wr_s[(j - 13) * 64 + o] = a;
        else              br_s[o] = a + b_in_r[o];
    }
    __syncthreads();

    // ---- x0 = feat @ W_eff + b_eff : warp w -> rows 4w..4w+3; write fp32 + split ----
    {
        const int e0 = blockIdx.x * EPB + 2 * w;
        float fe[2][16];
#pragma unroll
        for (int e = 0; e < 2; e++) {
            const float4* xp = (const float4*)(xin + (size_t)(e0 + e) * 16);
#pragma unroll
            for (int qq = 0; qq < 4; qq++) {
                float4 v = xp[qq];
                fe[e][4 * qq + 0] = v.x; fe[e][4 * qq + 1] = v.y;
                fe[e][4 * qq + 2] = v.z; fe[e][4 * qq + 3] = v.w;
            }
        }
        float2 bn = *(const float2*)&bnr_s[2 * lane];
        float2 bb = *(const float2*)&br_s[2 * lane];
        ull a0 = pk2(bn.x, bn.y), a2 = a0;
        ull a1 = pk2(bb.x, bb.y), a3 = a1;
#pragma unroll
        for (int f = 0; f < 12; f++) {
            ull wp = *(const ull*)&Wnr_s[f * 64 + 2 * lane];
            a0 = ffma2(wp, pk2(fe[0][f], fe[0][f]), a0);
            a2 = ffma2(wp, pk2(fe[1][f], fe[1][f]), a2);
        }
#pragma unroll
        for (int f = 0; f < 4; f++) {
            ull wp = *(const ull*)&Wr_s[f * 64 + 2 * lane];
            a1 = ffma2(wp, pk2(fe[0][12 + f], fe[0][12 + f]), a1);
            a3 = ffma2(wp, pk2(fe[1][12 + f], fe[1][12 + f]), a3);
        }
        ull accs[4] = {a0, a1, a2, a3};
#pragma unroll
        for (int j = 0; j < 4; j++) {
            float v0, v1; upk2(accs[j], v0, v1);
            int row = 4 * w + j;
            *(float2*)&s.xs[row * XS_S + 2 * lane] = make_float2(v0, v1);
            u32 h, lo; bfsplit(make_float2(v0, v1), h, lo);
            s.xsh[row * XH_S + lane] = h;
            s.xsl[row * XH_S + lane] = lo;
        }
    }

    // ================= layer loop =================
#pragma unroll 1
    for (int l = 0; l < NL; l++) {
        __syncthreads();
        {   // flat vectorized blob copy
            const uint4* src = (const uint4*)&g_blob[l];
            uint4* dst = (uint4*)&s.blob;
            for (int i = t; i < BLOB_V4; i += THREADS) dst[i] = src[i];
        }
        __syncthreads();

        // ======== stage A: xz GEMM (bf16x3); xc stored SPLIT, z stored fp32 ========
        {
            const int row0 = 16 * q + g, row8 = row0 + 8;
            const u32* xh0 = &s.xsh[row0 * XH_S];
            const u32* xh8 = &s.xsh[row8 * XH_S];
            const u32* xl0 = &s.xsl[row0 * XH_S];
            const u32* xl8 = &s.xsl[row8 * XH_S];
            float acc[8][4];
#pragma unroll
            for (int nt = 0; nt < 8; nt++)
#pragma unroll
                for (int i = 0; i < 4; i++) acc[nt][i] = 0.0f;
#pragma unroll
            for (int ks = 0; ks < 4; ks++) {
                const int kp = ks * 8 + cc;
                u32 ah[4], al[4];
                ah[0] = xh0[kp];     ah[1] = xh8[kp];
                ah[2] = xh0[kp + 4]; ah[3] = xh8[kp + 4];
                al[0] = xl0[kp];     al[1] = xl8[kp];
                al[2] = xl0[kp + 4]; al[3] = xl8[kp + 4];
                const u32* bh = &s.blob.ipwh[kp * IPW_S + nc * 64 + g];
                const u32* bl = &s.blob.ipwl[kp * IPW_S + nc * 64 + g];
#pragma unroll
                for (int nt = 0; nt < 8; nt++) {
                    u32 bh0 = bh[nt * 8], bh1 = bh[4 * IPW_S + nt * 8];
                    u32 bl0 = bl[nt * 8], bl1 = bl[4 * IPW_S + nt * 8];
                    mma_bf16(acc[nt], ah, bh0, bh1);
                    mma_bf16(acc[nt], ah, bl0, bl1);
                    mma_bf16(acc[nt], al, bh0, bh1);
                }
            }
            if (nc < 2) {        // xc half: conv tap + silu, stored split
                u32* xr0 = (u32*)&s.xc[row0 * XC_S];
                u32* xr8 = (u32*)&s.xc[row8 * XC_S];
#pragma unroll
                for (int nt = 0; nt < 8; nt++) {
                    int col = nc * 64 + nt * 8 + 2 * cc;
                    int p = col >> 1;
                    float2 cwv = *(const float2*)&s.blob.cw3[col];
                    float2 cbv = *(const float2*)&s.blob.cb[col];
                    float2 v0 = make_float2(siluf(fmaf(acc[nt][0], cwv.x, cbv.x)),
                                            siluf(fmaf(acc[nt][1], cwv.y, cbv.y)));
                    float2 v8 = make_float2(siluf(fmaf(acc[nt][2], cwv.x, cbv.x)),
                                            siluf(fmaf(acc[nt][3], cwv.y, cbv.y)));
                    u32 h, lo;
                    bfsplit(v0, h, lo); xr0[p] = h; xr0[64 + p] = lo;
                    bfsplit(v8, h, lo); xr8[p] = h; xr8[64 + p] = lo;
                }
            } else {             // z half: silu, fp32
#pragma unroll
                for (int nt = 0; nt < 8; nt++) {
                    int col = (nc - 2) * 64 + nt * 8 + 2 * cc;
                    *(float2*)&s.sz[row0 * XC_S + col] =
                        make_float2(siluf(acc[nt][0]), siluf(acc[nt][1]));
                    *(float2*)&s.sz[row8 * XC_S + col] =
                        make_float2(siluf(acc[nt][2]), siluf(acc[nt][3]));
                }
            }
        }
        __syncthreads();   // xsh/xsl reads done block-wide before proj overwrites

        // ======== proj GEMM: proj[64][36+] = xc @ xpw via bf16x3 mma ========
        {
            const int ntb = (nc < 2) ? nc * 2 : (nc == 2 ? 4 : 0);
            const int nte = (nc < 2) ? ntb + 2 : (nc == 2 ? 5 : 0);
            if (ntb < nte) {
                const int row0 = 16 * q + g, row8 = row0 + 8;
                const u32* yh0 = (const u32*)&s.xc[row0 * XC_S];
                const u32* yh8 = (const u32*)&s.xc[row8 * XC_S];
                float acc[2][4];
#pragma unroll
                for (int nt = 0; nt < 2; nt++)
#pragma unroll
                    for (int i = 0; i < 4; i++) acc[nt][i] = 0.0f;
#pragma unroll
                for (int ks = 0; ks < 8; ks++) {
                    const int kp = ks * 8 + cc;
                    u32 ah[4], al[4];
                    ah[0] = yh0[kp];          ah[1] = yh8[kp];
                    ah[2] = yh0[kp + 4];      ah[3] = yh8[kp + 4];
                    al[0] = yh0[64 + kp];     al[1] = yh8[64 + kp];
                    al[2] = yh0[64 + kp + 4]; al[3] = yh8[64 + kp + 4];
                    const u32* bh = &s.blob.xpjwh[kp * XPJ_S + g];
                    const u32* bl = &s.blob.xpjwl[kp * XPJ_S + g];
                    for (int nt = ntb; nt < nte; nt++) {
                        int a = nt - ntb;
                        u32 bh0 = bh[nt * 8], bh1 = bh[4 * XPJ_S + nt * 8];
                        u32 bl0 = bl[nt * 8], bl1 = bl[4 * XPJ_S + nt * 8];
                        mma_bf16(acc[a], ah, bh0, bh1);
                        mma_bf16(acc[a], ah, bl0, bl1);
                        mma_bf16(acc[a], al, bh0, bh1);
                    }
                }
                for (int nt = ntb; nt < nte; nt++) {
                    int a = nt - ntb;
                    int col = nt * 8 + 2 * cc;
                    *(float2*)&proj[row0 * PROJ_S + col] = make_float2(acc[a][0], acc[a][1]);
                    *(float2*)&proj[row8 * PROJ_S + col] = make_float2(acc[a][2], acc[a][3]);
                }
            }
        }
        group_bar(q);

        // ======== stage B: dt/BC/y for rows rb4..rb4+3 ========
        {
            float4 pj[4];
#pragma unroll
            for (int j = 0; j < 4; j++)
                pj[j] = *(const float4*)&proj[(rb4 + j) * PROJ_S];
            float bc[4];
            {
                const int j2 = lane >> 4, sidx = lane & 15;
#pragma unroll
                for (int a = 0; a < 2; a++) {
                    const float* pr = &proj[(rb4 + 2 * a + j2) * PROJ_S];
                    float v = pr[4 + sidx] * pr[20 + sidx];
                    v = half_sum(v);
                    bc[2 * a + 0] = __shfl_sync(0xffffffffu, v, 0);
                    bc[2 * a + 1] = __shfl_sync(0xffffffffu, v, 16);
                }
            }
            float dts[4][4];
            {
                float4 dtbv = *(const float4*)&s.blob.dtb[4 * lane];
#pragma unroll
                for (int j = 0; j < 4; j++) {
                    dts[j][0] = dtbv.x; dts[j][1] = dtbv.y;
                    dts[j][2] = dtbv.z; dts[j][3] = dtbv.w;
                }
#pragma unroll
                for (int r = 0; r < 4; r++) {
                    float4 dwv = *(const float4*)&s.blob.dtw[r * 128 + 4 * lane];
#pragma unroll
                    for (int j = 0; j < 4; j++) {
                        float prj = fget(pj[j], r);
                        dts[j][0] = fmaf(prj, dwv.x, dts[j][0]);
                        dts[j][1] = fmaf(prj, dwv.y, dts[j][1]);
                        dts[j][2] = fmaf(prj, dwv.z, dts[j][2]);
                        dts[j][3] = fmaf(prj, dwv.w, dts[j][3]);
                    }
                }
#pragma unroll
                for (int j = 0; j < 4; j++) {
                    dts[j][0] = softplusf(dts[j][0]); dts[j][1] = softplusf(dts[j][1]);
                    dts[j][2] = softplusf(dts[j][2]); dts[j][3] = softplusf(dts[j][3]);
                }
            }
            {
                float4 dskv = *(const float4*)&s.blob.dskip[4 * lane];
#pragma unroll
                for (int j = 0; j < 4; j++) {
                    u32* xr = (u32*)&s.xc[(rb4 + j) * XC_S];
                    uint2 hh = *(const uint2*)&xr[2 * lane];
                    uint2 ll = *(const uint2*)&xr[64 + 2 * lane];
                    float xc0 = __uint_as_float(hh.x << 16) + __uint_as_float(ll.x << 16);
                    float xc1 = __uint_as_float(hh.x & 0xffff0000u) + __uint_as_float(ll.x & 0xffff0000u);
                    float xc2 = __uint_as_float(hh.y << 16) + __uint_as_float(ll.y << 16);
                    float xc3 = __uint_as_float(hh.y & 0xffff0000u) + __uint_as_float(ll.y & 0xffff0000u);
                    float4 szv = *(const float4*)&s.sz[(rb4 + j) * XC_S + 4 * lane];
                    float4 yv;
                    yv.x = xc0 * fmaf(dts[j][0], bc[j], dskv.x) * szv.x;
                    yv.y = xc1 * fmaf(dts[j][1], bc[j], dskv.y) * szv.y;
                    yv.z = xc2 * fmaf(dts[j][2], bc[j], dskv.z) * szv.z;
                    yv.w = xc3 * fmaf(dts[j][3], bc[j], dskv.w) * szv.w;
                    u32 h0, l0, h1, l1;
                    bfsplit(make_float2(yv.x, yv.y), h0, l0);
                    bfsplit(make_float2(yv.z, yv.w), h1, l1);
                    *(uint2*)&xr[2 * lane]      = make_uint2(h0, h1);
                    *(uint2*)&xr[64 + 2 * lane] = make_uint2(l0, l1);
                }
            }
        }
        group_bar(q);

        // ======== stage C: out-proj GEMM (bf16x3 mma) ========
        {
            const int row0 = 16 * q + g, row8 = row0 + 8;
            const u32* yh0 = (const u32*)&s.xc[row0 * XC_S];
            const u32* yh8 = (const u32*)&s.xc[row8 * XC_S];
            float acc[2][4];
#pragma unroll
            for (int nt = 0; nt < 2; nt++)
#pragma unroll
                for (int i = 0; i < 4; i++) acc[nt][i] = 0.0f;
#pragma unroll
            for (int ks = 0; ks < 8; ks++) {
                const int kp = ks * 8 + cc;
                u32 ah[4], al[4];
                ah[0] = yh0[kp];          ah[1] = yh8[kp];
                ah[2] = yh0[kp + 4];      ah[3] = yh8[kp + 4];
                al[0] = yh0[64 + kp];     al[1] = yh8[64 + kp];
                al[2] = yh0[64 + kp + 4]; al[3] = yh8[64 + kp + 4];
                const u32* bh = &s.blob.opwh[kp * OPW_S + nc * 16 + g];
                const u32* bl = &s.blob.opwl[kp * OPW_S + nc * 16 + g];
#pragma unroll
                for (int nt = 0; nt < 2; nt++) {
                    u32 bh0 = bh[nt * 8], bh1 = bh[4 * OPW_S + nt * 8];
                    u32 bl0 = bl[nt * 8], bl1 = bl[4 * OPW_S + nt * 8];
                    mma_bf16(acc[nt], ah, bh0, bh1);
                    mma_bf16(acc[nt], ah, bl0, bl1);
                    mma_bf16(acc[nt], al, bh0, bh1);
                }
            }
#pragma unroll
            for (int nt = 0; nt < 2; nt++) {
                int col = nc * 16 + nt * 8 + 2 * cc;
                *(float2*)&s.sz[row0 * XC_S + col] = make_float2(acc[nt][0], acc[nt][1]);
                *(float2*)&s.sz[row8 * XC_S + col] = make_float2(acc[nt][2], acc[nt][3]);
            }
        }
        __syncthreads();   // all proj reads done before stage D rewrites xsh/xsl

        // ======== stage D: layernorm(64) + residual; write fp32 + split ========
        {
            float2 gv = *(const float2*)&s.blob.lng[2 * lane];
            float2 bv = *(const float2*)&s.blob.lnb[2 * lane];
#pragma unroll
            for (int j = 0; j < 4; j++) {
                int row = rb4 + j;
                float2 ov = *(const float2*)&s.sz[row * XC_S + 2 * lane];
                float m  = warp_sum(ov.x + ov.y) * (1.0f / 64.0f);
                float m2 = warp_sum(ov.x * ov.x + ov.y * ov.y) * (1.0f / 64.0f);
                float rs = rsqrtf(m2 - m * m + EPSV);
                float2 xv = *(const float2*)&s.xs[row * XS_S + 2 * lane];
                xv.x += (ov.x - m) * rs * gv.x + bv.x;
                xv.y += (ov.y - m) * rs * gv.y + bv.y;
                *(float2*)&s.xs[row * XS_S + 2 * lane] = xv;
                u32 h, lo; bfsplit(xv, h, lo);
                s.xsh[row * XH_S + lane] = h;
                s.xsl[row * XH_S + lane] = lo;
            }
        }
    }

    // ================= head =================
    __syncthreads();
    {
        float* hs = s.xc;   // reuse as hw1[128][33]
        for (int i = t; i < 4096; i += THREADS) {
            int k = i >> 5, c = i & 31;
            hs[k * 33 + c] = hw1[i];
        }
        float* hb1s = s.sz;
        float* hw2s = s.sz + 64;
        if (t < 32) { hb1s[t] = hb1[t]; hw2s[t] = hw2[t]; }
        __syncthreads();

        float b2v = hb2[0];
#pragma unroll
        for (int j = 0; j < 2; j++) {
            int ra = 4 * w + 2 * j;
            float h = hb1s[lane];
            const float* xa = &s.xs[ra * XS_S];
            const float* xb = &s.xs[(ra + 1) * XS_S];
#pragma unroll 8
            for (int k = 0; k < 64; k++) h = fmaf(xa[k], hs[k * 33 + lane], h);
#pragma unroll 8
            for (int k = 0; k < 64; k++) h = fmaf(xb[k], hs[(64 + k) * 33 + lane], h);
            h = fmaxf(h, 0.0f);
            float v = warp_sum(h * hw2s[lane]);
            if (lane == 0) out[blockIdx.x * EPB + 2 * w + j] = v + b2v;
        }
    }
}

extern "C" void kernel_launch(void* const* d_in, const int* in_sizes, int n_in,
                              void* d_out, int out_size) {
    const float* x        = (const float*)d_in[0];
    const float* w_nr     = (const float*)d_in[1];
    const float* b_nr     = (const float*)d_in[2];
    const float* w_r      = (const float*)d_in[3];
    const float* b_r      = (const float*)d_in[4];
    const float* w_in_nr  = (const float*)d_in[5];
    const float* b_in_nr  = (const float*)d_in[6];
    const float* w_in_r   = (const float*)d_in[7];
    const float* b_in_r   = (const float*)d_in[8];
    const float* ipw      = (const float*)d_in[9];
    const float* cw       = (const float*)d_in[10];
    const float* cb       = (const float*)d_in[11];
    const float* xpw      = (const float*)d_in[12];
    const float* dtw      = (const float*)d_in[13];
    const float* dtb      = (const float*)d_in[14];
    /* alog d_in[15] dead at L=1 (scan h0=0) */
    const float* dskip    = (const float*)d_in[16];
    const float* opw      = (const float*)d_in[17];
    const float* lng      = (const float*)d_in[18];
    const float* lnb      = (const float*)d_in[19];
    const float* hw1      = (const float*)d_in[20];
    const float* hb1      = (const float*)d_in[21];
    const float* hw2      = (const float*)d_in[22];
    const float* hb2      = (const float*)d_in[23];

    size_t smem = sizeof(Smem);
    cudaFuncSetAttribute((const void*)mamba_main,
                         cudaFuncAttributeMaxDynamicSharedMemorySize, (int)smem);

    prep_all<<<FOLD_BLKS + BLOB_BLKS, 256>>>(w_nr, b_nr, w_r, b_r, w_in_nr, w_in_r,
                                             ipw, opw, xpw, dtw, cw, cb, dtb, dskip,
                                             lng, lnb);
    mamba_main<<<NBLK, THREADS, smem>>>(x, b_in_nr, b_in_r, hw1, hb1, hw2, hb2,
                                        (float*)d_out);
}

// round 12
// speedup vs baseline: 2.3764x; 1.0239x over previous
#include <cuda_runtime.h>

#define NL 4
#define BATCH 16384
#define THREADS 512
#define EPB 32
#define NBLK (BATCH / EPB)
#define XS_S 68          // xs row stride (floats)
#define XC_S 132         // xc/sz row stride (floats / u32)
#define XH_S 36          // split-xs row stride (u32)
#define PROJ_S 72        // proj scratch row stride (floats)
#define NCHUNK 16        // fold c-split
#define EPSV 1e-5f

typedef unsigned long long ull;
typedef unsigned int u32;

__device__ __forceinline__ ull pk2(float lo, float hi) {
    ull r; asm("mov.b64 %0,{%1,%2};" : "=l"(r) : "f"(lo), "f"(hi)); return r;
}
__device__ __forceinline__ void upk2(ull v, float& lo, float& hi) {
    asm("mov.b64 {%0,%1},%2;" : "=f"(lo), "=f"(hi) : "l"(v));
}
__device__ __forceinline__ ull ffma2(ull a, ull b, ull c) {
    ull d; asm("fma.rn.f32x2 %0,%1,%2,%3;" : "=l"(d) : "l"(a), "l"(b), "l"(c)); return d;
}
__device__ __forceinline__ float warp_sum(float v) {
    v += __shfl_xor_sync(0xffffffffu, v, 16);
    v += __shfl_xor_sync(0xffffffffu, v, 8);
    v += __shfl_xor_sync(0xffffffffu, v, 4);
    v += __shfl_xor_sync(0xffffffffu, v, 2);
    v += __shfl_xor_sync(0xffffffffu, v, 1);
    return v;
}
__device__ __forceinline__ float half_sum(float v) {
    v += __shfl_xor_sync(0xffffffffu, v, 8);
    v += __shfl_xor_sync(0xffffffffu, v, 4);
    v += __shfl_xor_sync(0xffffffffu, v, 2);
    v += __shfl_xor_sync(0xffffffffu, v, 1);
    return v;
}
__device__ __forceinline__ void group_bar(int q) {
    asm volatile("bar.sync %0, 128;" :: "r"(q + 1) : "memory");
}
__device__ __forceinline__ float siluf(float v) {
    return __fdividef(v, 1.0f + __expf(-v));
}
__device__ __forceinline__ float softplusf(float v) {
    return fmaxf(v, 0.0f) + __logf(1.0f + __expf(-fabsf(v)));
}
__device__ __forceinline__ float fget(float4 v, int r) {
    return r == 0 ? v.x : r == 1 ? v.y : r == 2 ? v.z : v.w;
}
__device__ __forceinline__ u32 uget(uint4 v, int r) {
    return r == 0 ? v.x : r == 1 ? v.y : r == 2 ? v.z : v.w;
}
// split two fp32 (p.x = even k, p.y = odd k) into packed bf16x2 hi + lo
__device__ __forceinline__ void bfsplit(float2 p, u32& h, u32& l) {
    asm("cvt.rn.satfinite.bf16x2.f32 %0,%1,%2;" : "=r"(h) : "f"(p.y), "f"(p.x));
    float h0 = __uint_as_float(h << 16);
    float h1 = __uint_as_float(h & 0xffff0000u);
    asm("cvt.rn.satfinite.bf16x2.f32 %0,%1,%2;" : "=r"(l) : "f"(p.y - h1), "f"(p.x - h0));
}
__device__ __forceinline__ void mma_bf16(float* c, const u32* a, u32 b0, u32 b1) {
    asm("mma.sync.aligned.m16n8k16.row.col.f32.bf16.bf16.f32 "
        "{%0,%1,%2,%3},{%4,%5,%6,%7},{%8,%9},{%0,%1,%2,%3};"
        : "+f"(c[0]), "+f"(c[1]), "+f"(c[2]), "+f"(c[3])
        : "r"(a[0]), "r"(a[1]), "r"(a[2]), "r"(a[3]), "r"(b0), "r"(b1));
}

// ---------- per-layer weight blob: FRAGMENT-ORDER packing, layout == SMEM ----------
// ipwP: [ks(4)][nc(4)][lane(32)][16 u32], slot = chunk ^ ((lane>>1)&3), 4 u32/chunk.
//       chunk 0,1 = row kp nt0-3/nt4-7; chunk 2,3 = row kp+4. kp = ks*8 + (lane&3).
// opwP: [ks(8)][nc(4)][lane(32)][4 u32] = {(kp,nt0),(kp,nt1),(kp+4,nt0),(kp+4,nt1)}
// xpjP: [ks(8)][nt(5)][lane(32)][2 u32] = {row kp, row kp+4}
struct __align__(16) LayerBlob {
    u32 ipwPh[4 * 4 * 32 * 16];   // 8192
    u32 ipwPl[4 * 4 * 32 * 16];   // 8192
    u32 opwPh[8 * 4 * 32 * 4];    // 4096
    u32 opwPl[8 * 4 * 32 * 4];    // 4096
    u32 xpjPh[8 * 5 * 32 * 2];    // 2560
    u32 xpjPl[8 * 5 * 32 * 2];    // 2560
    float dtw[4 * 128];
    float cw3[128];
    float cb[128];
    float dtb[128];
    float dskip[128];
    float lng[64];
    float lnb[64];
};   // 123,392 B

#define BLOB_V4 (sizeof(LayerBlob) / 16)

__device__ LayerBlob g_blob[NL];
__device__ float g_fold_part[18 * NCHUNK * 64];

#define FOLD_BLKS (18 * NCHUNK)
#define B0 (NL * 8192)
#define B1 (B0 + NL * 4096)
#define B2 (B1 + NL * 2560)
#define B3 (B2 + NL * 512)
#define B4 (B3 + NL * 128)
#define B5 (B4 + NL * 128)
#define B6 (B5 + NL * 128)
#define B7 (B6 + NL * 128)
#define B8 (B7 + NL * 64)
#define B9 (B8 + NL * 64)
#define BLOB_BLKS ((B9 + 255) / 256)

__global__ void __launch_bounds__(256)
prep_all(const float* __restrict__ w_nr, const float* __restrict__ b_nr,
         const float* __restrict__ w_r,  const float* __restrict__ b_r,
         const float* __restrict__ w_in_nr, const float* __restrict__ w_in_r,
         const float* __restrict__ ipw, const float* __restrict__ opw,
         const float* __restrict__ xpw, const float* __restrict__ dtw,
         const float* __restrict__ cw,  const float* __restrict__ cb,
         const float* __restrict__ dtb, const float* __restrict__ dskip,
         const float* __restrict__ lng, const float* __restrict__ lnb) {
    if (blockIdx.x < FOLD_BLKS) {
        __shared__ float red[4][64];
        const int j = blockIdx.x / NCHUNK;
        const int chunk = blockIdx.x - j * NCHUNK;
        const int o = threadIdx.x & 63;
        const int cg = threadIdx.x >> 6;
        const float* vec;
        const float* mat;
        if (j < 12)       { vec = w_nr + j * 1000;        mat = w_in_nr; }
        else if (j == 12) { vec = b_nr;                   mat = w_in_nr; }
        else if (j < 17)  { vec = w_r + (j - 13) * 1000;  mat = w_in_r;  }
        else              { vec = b_r;                    mat = w_in_r;  }
        const int cbase = chunk * 63;
        const int cend = (cbase + 63 < 1000) ? cbase + 63 : 1000;
        float a0 = 0.f, a1 = 0.f;
        for (int c = cbase + cg * 2; c < cend; c += 8) {
            a0 = fmaf(vec[c], mat[c * 64 + o], a0);
            if (c + 1 < cend)
                a1 = fmaf(vec[c + 1], mat[(c + 1) * 64 + o], a1);
        }
        red[cg][o] = a0 + a1;
        __syncthreads();
        if (cg == 0)
            g_fold_part[(j * NCHUNK + chunk) * 64 + o] =
                (red[0][o] + red[1][o]) + (red[2][o] + red[3][o]);
        return;
    }
    int idx = (blockIdx.x - FOLD_BLKS) * 256 + threadIdx.x;
    if (idx < B0) {
        // ipw fragment-order pack (swizzled)
        int l = idx >> 13, r = idx & 8191;
        int pos = r & 15, lane = (r >> 4) & 31, t2 = r >> 9;
        int nc = t2 & 3, ks = t2 >> 2;
        int sw = (lane >> 1) & 3;
        int c = (pos >> 2) ^ sw;            // logical chunk living in this slot
        int jw = pos & 3;
        int g = lane >> 2, cc = lane & 3;
        int kp = ks * 8 + cc + ((c >= 2) ? 4 : 0);
        int nt = (c & 1) * 4 + jw;
        int n = nc * 64 + nt * 8 + g;
        const float* src = ipw + l * 16384 + kp * 512 + n;
        u32 h, lo; bfsplit(make_float2(src[0], src[256]), h, lo);
        g_blob[l].ipwPh[r] = h;
        g_blob[l].ipwPl[r] = lo;
    } else if (idx < B1) {
        // opw fragment-order pack
        int j2 = idx - B0, l = j2 >> 12, r = j2 & 4095;
        int jw = r & 3, lane = (r >> 2) & 31, t2 = r >> 7;
        int nc = t2 & 3, ks = t2 >> 2;
        int g = lane >> 2, cc = lane & 3;
        int kp = ks * 8 + cc + ((jw >= 2) ? 4 : 0);
        int nt = jw & 1;
        int n = nc * 16 + nt * 8 + g;
        const float* src = opw + l * 8192 + kp * 128 + n;
        u32 h, lo; bfsplit(make_float2(src[0], src[64]), h, lo);
        g_blob[l].opwPh[r] = h;
        g_blob[l].opwPl[r] = lo;
    } else if (idx < B2) {
        // xpjw fragment-order pack
        int j2 = idx - B1, l = j2 / 2560, r = j2 - l * 2560;
        int e = r & 1, lane = (r >> 1) & 31, t2 = r >> 6;   // t2 in 0..39
        int nt = t2 % 5, ks = t2 / 5;
        int g = lane >> 2, cc = lane & 3;
        int kp = ks * 8 + cc + (e ? 4 : 0);
        int n = nt * 8 + g;
        const float* src = xpw + l * 4608 + (2 * kp) * 36 + n;
        u32 h, lo; bfsplit(make_float2(src[0], src[36]), h, lo);
        g_blob[l].xpjPh[r] = h;
        g_blob[l].xpjPl[r] = lo;
    } else if (idx < B3) {
        int j = idx - B2, l = j >> 9, r = j & 511;
        g_blob[l].dtw[r] = dtw[l * 512 + r];
    } else if (idx < B4) {
        int j = idx - B3, l = j >> 7, r = j & 127;
        g_blob[l].cw3[r] = cw[(l * 128 + r) * 4 + 3];
    } else if (idx < B5) {
        int j = idx - B4, l = j >> 7, r = j & 127;
        g_blob[l].cb[r] = cb[l * 128 + r];
    } else if (idx < B6) {
        int j = idx - B5, l = j >> 7, r = j & 127;
        g_blob[l].dtb[r] = dtb[l * 128 + r];
    } else if (idx < B7) {
        int j = idx - B6, l = j >> 7, r = j & 127;
        g_blob[l].dskip[r] = dskip[l * 128 + r];
    } else if (idx < B8) {
        int j = idx - B7, l = j >> 6, r = j & 63;
        g_blob[l].lng[r] = lng[l * 64 + r];
    } else if (idx < B9) {
        int j = idx - B8, l = j >> 6, r = j & 63;
        g_blob[l].lnb[r] = lnb[l * 64 + r];
    }
}

// ---------------- shared memory (226,816 B; 1 block/SM) ----------------
struct __align__(16) Smem {
    LayerBlob blob;
    u32 xsh[64 * XH_S];       // split residual hi; proj scratch between A and D
    u32 xsl[64 * XH_S];
    float xs[64 * XS_S];      // residual fp32
    float xc[64 * XC_S];      // split xc -> split y (u32; hi cols 0..63, lo 64..127)
    float sz[64 * XC_S];      // silu(z), then O
};

__global__ void __launch_bounds__(THREADS, 1)
mamba_main(const float* __restrict__ xin,
           const float* __restrict__ b_in_nr, const float* __restrict__ b_in_r,
           const float* __restrict__ hw1, const float* __restrict__ hb1,
           const float* __restrict__ hw2, const float* __restrict__ hb2,
           float* __restrict__ out) {
    extern __shared__ __align__(16) char smem_raw[];
    Smem& s = *reinterpret_cast<Smem*>(smem_raw);

    const int t = threadIdx.x;
    const int w = t >> 5;
    const int lane = t & 31;
    const int q = w & 3;
    const int nc = w >> 2;
    const int g = lane >> 2;
    const int cc = lane & 3;
    const int sw = (lane >> 1) & 3;
    const int rb4 = 16 * q + 4 * nc;
    float* proj = (float*)s.xsh;

    // ---- fold-reduce into SMEM (union'd into xc region) ----
    float* Wnr_s = s.xc;
    float* Wr_s  = s.xc + 768;
    float* bnr_s = s.xc + 1024;
    float* br_s  = s.xc + 1088;
    for (int i = t; i < 1152; i += THREADS) {
        int j = i >> 6, o = i & 63;
        const float* p = g_fold_part + (j * NCHUNK) * 64 + o;
        float a = 0.0f;
#pragma unroll
        for (int k = 0; k < NCHUNK; k++) a += p[k * 64];
        if (j < 12)       Wnr_s[j * 64 + o] = a;
        else if (j == 12) bnr_s[o] = a + b_in_nr[o];
        else if (j < 17)  Wr_s[(j - 13) * 64 + o] = a;
        else              br_s[o] = a + b_in_r[o];
    }
    __syncthreads();

    // ---- x0 = feat @ W_eff + b_eff ----
    {
        const int e0 = blockIdx.x * EPB + 2 * w;
        float fe[2][16];
#pragma unroll
        for (int e = 0; e < 2; e++) {
            const float4* xp = (const float4*)(xin + (size_t)(e0 + e) * 16);
#pragma unroll
            for (int qq = 0; qq < 4; qq++) {
                float4 v = xp[qq];
                fe[e][4 * qq + 0] = v.x; fe[e][4 * qq + 1] = v.y;
                fe[e][4 * qq + 2] = v.z; fe[e][4 * qq + 3] = v.w;
            }
        }
        float2 bn = *(const float2*)&bnr_s[2 * lane];
        float2 bb = *(const float2*)&br_s[2 * lane];
        ull a0 = pk2(bn.x, bn.y), a2 = a0;
        ull a1 = pk2(bb.x, bb.y), a3 = a1;
#pragma unroll
        for (int f = 0; f < 12; f++) {
            ull wp = *(const ull*)&Wnr_s[f * 64 + 2 * lane];
            a0 = ffma2(wp, pk2(fe[0][f], fe[0][f]), a0);
            a2 = ffma2(wp, pk2(fe[1][f], fe[1][f]), a2);
        }
#pragma unroll
        for (int f = 0; f < 4; f++) {
            ull wp = *(const ull*)&Wr_s[f * 64 + 2 * lane];
            a1 = ffma2(wp, pk2(fe[0][12 + f], fe[0][12 + f]), a1);
            a3 = ffma2(wp, pk2(fe[1][12 + f], fe[1][12 + f]), a3);
        }
        ull accs[4] = {a0, a1, a2, a3};
#pragma unroll
        for (int j = 0; j < 4; j++) {
            float v0, v1; upk2(accs[j], v0, v1);
            int row = 4 * w + j;
            *(float2*)&s.xs[row * XS_S + 2 * lane] = make_float2(v0, v1);
            u32 h, lo; bfsplit(make_float2(v0, v1), h, lo);
            s.xsh[row * XH_S + lane] = h;
            s.xsl[row * XH_S + lane] = lo;
        }
    }

    // ================= layer loop =================
#pragma unroll 1
    for (int l = 0; l < NL; l++) {
        __syncthreads();
        {
            const uint4* src = (const uint4*)&g_blob[l];
            uint4* dst = (uint4*)&s.blob;
            for (int i = t; i < BLOB_V4; i += THREADS) dst[i] = src[i];
        }
        __syncthreads();

        // ======== stage A: xz GEMM; B frags via swizzled LDS.128 ========
        {
            const int row0 = 16 * q + g, row8 = row0 + 8;
            const u32* xh0 = &s.xsh[row0 * XH_S];
            const u32* xh8 = &s.xsh[row8 * XH_S];
            const u32* xl0 = &s.xsl[row0 * XH_S];
            const u32* xl8 = &s.xsl[row8 * XH_S];
            float acc[8][4];
#pragma unroll
            for (int nt = 0; nt < 8; nt++)
#pragma unroll
                for (int i = 0; i < 4; i++) acc[nt][i] = 0.0f;
#pragma unroll
            for (int ks = 0; ks < 4; ks++) {
                const int kp = ks * 8 + cc;
                u32 ah[4], al[4];
                ah[0] = xh0[kp];     ah[1] = xh8[kp];
                ah[2] = xh0[kp + 4]; ah[3] = xh8[kp + 4];
                al[0] = xl0[kp];     al[1] = xl8[kp];
                al[2] = xl0[kp + 4]; al[3] = xl8[kp + 4];
                const u32* bp_h = &s.blob.ipwPh[(((ks * 4 + nc) * 32) + lane) * 16];
                const u32* bp_l = &s.blob.ipwPl[(((ks * 4 + nc) * 32) + lane) * 16];
                uint4 H0 = *(const uint4*)&bp_h[(0 ^ sw) * 4];
                uint4 H1 = *(const uint4*)&bp_h[(1 ^ sw) * 4];
                uint4 H2 = *(const uint4*)&bp_h[(2 ^ sw) * 4];
                uint4 H3 = *(const uint4*)&bp_h[(3 ^ sw) * 4];
#pragma unroll
                for (int nt = 0; nt < 8; nt++) {
                    u32 b0 = nt < 4 ? uget(H0, nt) : uget(H1, nt - 4);
                    u32 b1 = nt < 4 ? uget(H2, nt) : uget(H3, nt - 4);
                    mma_bf16(acc[nt], ah, b0, b1);
                    mma_bf16(acc[nt], al, b0, b1);
                }
                uint4 L0 = *(const uint4*)&bp_l[(0 ^ sw) * 4];
                uint4 L1 = *(const uint4*)&bp_l[(1 ^ sw) * 4];
                uint4 L2 = *(const uint4*)&bp_l[(2 ^ sw) * 4];
                uint4 L3 = *(const uint4*)&bp_l[(3 ^ sw) * 4];
#pragma unroll
                for (int nt = 0; nt < 8; nt++) {
                    u32 b0 = nt < 4 ? uget(L0, nt) : uget(L1, nt - 4);
                    u32 b1 = nt < 4 ? uget(L2, nt) : uget(L3, nt - 4);
                    mma_bf16(acc[nt], ah, b0, b1);
                }
            }
            if (nc < 2) {        // xc half: conv tap + silu, stored split
                u32* xr0 = (u32*)&s.xc[row0 * XC_S];
                u32* xr8 = (u32*)&s.xc[row8 * XC_S];
#pragma unroll
                for (int nt = 0; nt < 8; nt++) {
                    int col = nc * 64 + nt * 8 + 2 * cc;
                    int p = col >> 1;
                    float2 cwv = *(const float2*)&s.blob.cw3[col];
                    float2 cbv = *(const float2*)&s.blob.cb[col];
                    float2 v0 = make_float2(siluf(fmaf(acc[nt][0], cwv.x, cbv.x)),
                                            siluf(fmaf(acc[nt][1], cwv.y, cbv.y)));
                    float2 v8 = make_float2(siluf(fmaf(acc[nt][2], cwv.x, cbv.x)),
                                            siluf(fmaf(acc[nt][3], cwv.y, cbv.y)));
                    u32 h, lo;
                    bfsplit(v0, h, lo); xr0[p] = h; xr0[64 + p] = lo;
                    bfsplit(v8, h, lo); xr8[p] = h; xr8[64 + p] = lo;
                }
            } else {             // z half: silu, fp32
#pragma unroll
                for (int nt = 0; nt < 8; nt++) {
                    int col = (nc - 2) * 64 + nt * 8 + 2 * cc;
                    *(float2*)&s.sz[row0 * XC_S + col] =
                        make_float2(siluf(acc[nt][0]), siluf(acc[nt][1]));
                    *(float2*)&s.sz[row8 * XC_S + col] =
                        make_float2(siluf(acc[nt][2]), siluf(acc[nt][3]));
                }
            }
        }
        __syncthreads();   // xsh/xsl reads done before proj overwrites

        // ======== proj GEMM: n-tiles rebalanced 2/1/1/1; B via LDS.64 ========
        {
            const int ntb = (nc == 0) ? 0 : nc + 1;   // 0,2,3,4
            const int nte = nc + 2;                   // 2,3,4,5
            const int row0 = 16 * q + g, row8 = row0 + 8;
            const u32* yh0 = (const u32*)&s.xc[row0 * XC_S];
            const u32* yh8 = (const u32*)&s.xc[row8 * XC_S];
            float acc[2][4];
#pragma unroll
            for (int nt = 0; nt < 2; nt++)
#pragma unroll
                for (int i = 0; i < 4; i++) acc[nt][i] = 0.0f;
#pragma unroll
            for (int ks = 0; ks < 8; ks++) {
                const int kp = ks * 8 + cc;
                u32 ah[4], al[4];
                ah[0] = yh0[kp];          ah[1] = yh8[kp];
                ah[2] = yh0[kp + 4];      ah[3] = yh8[kp + 4];
                al[0] = yh0[64 + kp];     al[1] = yh8[64 + kp];
                al[2] = yh0[64 + kp + 4]; al[3] = yh8[64 + kp + 4];
                for (int nt = ntb; nt < nte; nt++) {
                    int a = nt - ntb;
                    ull hv = *(const ull*)&s.blob.xpjPh[((ks * 5 + nt) * 32 + lane) * 2];
                    ull lv = *(const ull*)&s.blob.xpjPl[((ks * 5 + nt) * 32 + lane) * 2];
                    u32 bh0 = (u32)hv, bh1 = (u32)(hv >> 32);
                    u32 bl0 = (u32)lv, bl1 = (u32)(lv >> 32);
                    mma_bf16(acc[a], ah, bh0, bh1);
                    mma_bf16(acc[a], ah, bl0, bl1);
                    mma_bf16(acc[a], al, bh0, bh1);
                }
            }
            for (int nt = ntb; nt < nte; nt++) {
                int a = nt - ntb;
                int col = nt * 8 + 2 * cc;
                *(float2*)&proj[row0 * PROJ_S + col] = make_float2(acc[a][0], acc[a][1]);
                *(float2*)&proj[row8 * PROJ_S + col] = make_float2(acc[a][2], acc[a][3]);
            }
        }
        group_bar(q);

        // ======== stage B: dt/BC/y for rows rb4..rb4+3 ========
        {
            float4 pj[4];
#pragma unroll
            for (int j = 0; j < 4; j++)
                pj[j] = *(const float4*)&proj[(rb4 + j) * PROJ_S];
            float bc[4];
            {
                const int j2 = lane >> 4, sidx = lane & 15;
#pragma unroll
                for (int a = 0; a < 2; a++) {
                    const float* pr = &proj[(rb4 + 2 * a + j2) * PROJ_S];
                    float v = pr[4 + sidx] * pr[20 + sidx];
                    v = half_sum(v);
                    bc[2 * a + 0] = __shfl_sync(0xffffffffu, v, 0);
                    bc[2 * a + 1] = __shfl_sync(0xffffffffu, v, 16);
                }
            }
            float dts[4][4];
            {
                float4 dtbv = *(const float4*)&s.blob.dtb[4 * lane];
#pragma unroll
                for (int j = 0; j < 4; j++) {
                    dts[j][0] = dtbv.x; dts[j][1] = dtbv.y;
                    dts[j][2] = dtbv.z; dts[j][3] = dtbv.w;
                }
#pragma unroll
                for (int r = 0; r < 4; r++) {
                    float4 dwv = *(const float4*)&s.blob.dtw[r * 128 + 4 * lane];
#pragma unroll
                    for (int j = 0; j < 4; j++) {
                        float prj = fget(pj[j], r);
                        dts[j][0] = fmaf(prj, dwv.x, dts[j][0]);
                        dts[j][1] = fmaf(prj, dwv.y, dts[j][1]);
                        dts[j][2] = fmaf(prj, dwv.z, dts[j][2]);
                        dts[j][3] = fmaf(prj, dwv.w, dts[j][3]);
                    }
                }
#pragma unroll
                for (int j = 0; j < 4; j++) {
                    dts[j][0] = softplusf(dts[j][0]); dts[j][1] = softplusf(dts[j][1]);
                    dts[j][2] = softplusf(dts[j][2]); dts[j][3] = softplusf(dts[j][3]);
                }
            }
            {
                float4 dskv = *(const float4*)&s.blob.dskip[4 * lane];
#pragma unroll
                for (int j = 0; j < 4; j++) {
                    u32* xr = (u32*)&s.xc[(rb4 + j) * XC_S];
                    uint2 hh = *(const uint2*)&xr[2 * lane];
                    uint2 ll = *(const uint2*)&xr[64 + 2 * lane];
                    float xc0 = __uint_as_float(hh.x << 16) + __uint_as_float(ll.x << 16);
                    float xc1 = __uint_as_float(hh.x & 0xffff0000u) + __uint_as_float(ll.x & 0xffff0000u);
                    float xc2 = __uint_as_float(hh.y << 16) + __uint_as_float(ll.y << 16);
                    float xc3 = __uint_as_float(hh.y & 0xffff0000u) + __uint_as_float(ll.y & 0xffff0000u);
                    float4 szv = *(const float4*)&s.sz[(rb4 + j) * XC_S + 4 * lane];
                    float4 yv;
                    yv.x = xc0 * fmaf(dts[j][0], bc[j], dskv.x) * szv.x;
                    yv.y = xc1 * fmaf(dts[j][1], bc[j], dskv.y) * szv.y;
                    yv.z = xc2 * fmaf(dts[j][2], bc[j], dskv.z) * szv.z;
                    yv.w = xc3 * fmaf(dts[j][3], bc[j], dskv.w) * szv.w;
                    u32 h0, l0, h1, l1;
                    bfsplit(make_float2(yv.x, yv.y), h0, l0);
                    bfsplit(make_float2(yv.z, yv.w), h1, l1);
                    *(uint2*)&xr[2 * lane]      = make_uint2(h0, h1);
                    *(uint2*)&xr[64 + 2 * lane] = make_uint2(l0, l1);
                }
            }
        }
        group_bar(q);

        // ======== stage C: out-proj GEMM; B frags via single LDS.128 ========
        {
            const int row0 = 16 * q + g, row8 = row0 + 8;
            const u32* yh0 = (const u32*)&s.xc[row0 * XC_S];
            const u32* yh8 = (const u32*)&s.xc[row8 * XC_S];
            float acc[2][4];
#pragma unroll
            for (int nt = 0; nt < 2; nt++)
#pragma unroll
                for (int i = 0; i < 4; i++) acc[nt][i] = 0.0f;
#pragma unroll
            for (int ks = 0; ks < 8; ks++) {
                const int kp = ks * 8 + cc;
                u32 ah[4], al[4];
                ah[0] = yh0[kp];          ah[1] = yh8[kp];
                ah[2] = yh0[kp + 4];      ah[3] = yh8[kp + 4];
                al[0] = yh0[64 + kp];     al[1] = yh8[64 + kp];
                al[2] = yh0[64 + kp + 4]; al[3] = yh8[64 + kp + 4];
                uint4 UH = *(const uint4*)&s.blob.opwPh[(((ks * 4 + nc) * 32) + lane) * 4];
                uint4 UL = *(const uint4*)&s.blob.opwPl[(((ks * 4 + nc) * 32) + lane) * 4];
                mma_bf16(acc[0], ah, UH.x, UH.z);
                mma_bf16(acc[0], ah, UL.x, UL.z);
                mma_bf16(acc[0], al, UH.x, UH.z);
                mma_bf16(acc[1], ah, UH.y, UH.w);
                mma_bf16(acc[1], ah, UL.y, UL.w);
                mma_bf16(acc[1], al, UH.y, UH.w);
            }
#pragma unroll
            for (int nt = 0; nt < 2; nt++) {
                int col = nc * 16 + nt * 8 + 2 * cc;
                *(float2*)&s.sz[row0 * XC_S + col] = make_float2(acc[nt][0], acc[nt][1]);
                *(float2*)&s.sz[row8 * XC_S + col] = make_float2(acc[nt][2], acc[nt][3]);
            }
        }
        __syncthreads();   // proj reads done before stage D rewrites xsh/xsl

        // ======== stage D: layernorm(64) + residual; write fp32 + split ========
        {
            float2 gv = *(const float2*)&s.blob.lng[2 * lane];
            float2 bv = *(const float2*)&s.blob.lnb[2 * lane];
#pragma unroll
            for (int j = 0; j < 4; j++) {
                int row = rb4 + j;
                float2 ov = *(const float2*)&s.sz[row * XC_S + 2 * lane];
                float m  = warp_sum(ov.x + ov.y) * (1.0f / 64.0f);
                float m2 = warp_sum(ov.x * ov.x + ov.y * ov.y) * (1.0f / 64.0f);
                float rs = rsqrtf(m2 - m * m + EPSV);
                float2 xv = *(const float2*)&s.xs[row * XS_S + 2 * lane];
                xv.x += (ov.x - m) * rs * gv.x + bv.x;
                xv.y += (ov.y - m) * rs * gv.y + bv.y;
                *(float2*)&s.xs[row * XS_S + 2 * lane] = xv;
                u32 h, lo; bfsplit(xv, h, lo);
                s.xsh[row * XH_S + lane] = h;
                s.xsl[row * XH_S + lane] = lo;
            }
        }
    }

    // ================= head =================
    __syncthreads();
    {
        float* hs = s.xc;   // reuse as hw1[128][33]
        for (int i = t; i < 4096; i += THREADS) {
            int k = i >> 5, c = i & 31;
            hs[k * 33 + c] = hw1[i];
        }
        float* hb1s = s.sz;
        float* hw2s = s.sz + 64;
        if (t < 32) { hb1s[t] = hb1[t]; hw2s[t] = hw2[t]; }
        __syncthreads();

        float b2v = hb2[0];
#pragma unroll
        for (int j = 0; j < 2; j++) {
            int ra = 4 * w + 2 * j;
            float h = hb1s[lane];
            const float* xa = &s.xs[ra * XS_S];
            const float* xb = &s.xs[(ra + 1) * XS_S];
#pragma unroll 8
            for (int k = 0; k < 64; k++) h = fmaf(xa[k], hs[k * 33 + lane], h);
#pragma unroll 8
            for (int k = 0; k < 64; k++) h = fmaf(xb[k], hs[(64 + k) * 33 + lane], h);
            h = fmaxf(h, 0.0f);
            float v = warp_sum(h * hw2s[lane]);
            if (lane == 0) out[blockIdx.x * EPB + 2 * w + j] = v + b2v;
        }
    }
}

extern "C" void kernel_launch(void* const* d_in, const int* in_sizes, int n_in,
                              void* d_out, int out_size) {
    const float* x        = (const float*)d_in[0];
    const float* w_nr     = (const float*)d_in[1];
    const float* b_nr     = (const float*)d_in[2];
    const float* w_r      = (const float*)d_in[3];
    const float* b_r      = (const float*)d_in[4];
    const float* w_in_nr  = (const float*)d_in[5];
    const float* b_in_nr  = (const float*)d_in[6];
    const float* w_in_r   = (const float*)d_in[7];
    const float* b_in_r   = (const float*)d_in[8];
    const float* ipw      = (const float*)d_in[9];
    const float* cw       = (const float*)d_in[10];
    const float* cb       = (const float*)d_in[11];
    const float* xpw      = (const float*)d_in[12];
    const float* dtw      = (const float*)d_in[13];
    const float* dtb      = (const float*)d_in[14];
    /* alog d_in[15] dead at L=1 (scan h0=0) */
    const float* dskip    = (const float*)d_in[16];
    const float* opw      = (const float*)d_in[17];
    const float* lng      = (const float*)d_in[18];
    const float* lnb      = (const float*)d_in[19];
    const float* hw1      = (const float*)d_in[20];
    const float* hb1      = (const float*)d_in[21];
    const float* hw2      = (const float*)d_in[22];
    const float* hb2      = (const float*)d_in[23];

    size_t smem = sizeof(Smem);
    cudaFuncSetAttribute((const void*)mamba_main,
                         cudaFuncAttributeMaxDynamicSharedMemorySize, (int)smem);

    prep_all<<<FOLD_BLKS + BLOB_BLKS, 256>>>(w_nr, b_nr, w_r, b_r, w_in_nr, w_in_r,
                                             ipw, opw, xpw, dtw, cw, cb, dtb, dskip,
                                             lng, lnb);
    mamba_main<<<NBLK, THREADS, smem>>>(x, b_in_nr, b_in_r, hw1, hb1, hw2, hb2,
                                        (float*)d_out);
}